// round 8
// baseline (speedup 1.0000x reference)
#include <cuda_runtime.h>
#include <cuda_bf16.h>
#include <cuda_fp16.h>

#define NN 10000
#define NS 64
#define NV 64
#define HID 128
#define WN 320
#define KS0 192
#define EAD 20
#define TPS 128
#define TPV 192

#define TE 16
#define BT 320

#define INV_SQRT3 0.5773502691896258f
#define INV_SQRT2 0.7071067811865476f
#define VSCALE    0.0625f
#define VUNSCALE  16.0f

// smem offsets (float units)
#define OFF_S0T   0        // half [192][16]  (1536 fu)  ─┐ overlay
#define OFF_H1T   1536     // half [128][16]  (1024 fu)   │ region
#define OFF_R1T   2560     // half [128][16]  (1024 fu)   │ (Vt half [192][48]
#define OFF_VT    0        //                             ┘  = 4608 fu)
#define OFF_SPS   4608     // f32  [128][16]  (2048)
#define OFF_VPS   6656     // f32  [384][16]  (6144)
#define OFF_TPW   12800    // f32  [320][16]  (5120)
#define OFF_OUTS  17920    // half [128][16]  (1024)
#define OFF_EAT   18944    // f32  [20][16]   (320)
#define OFF_IDX   19264    // 32 ints
#define SMEM_FLOATS 19296

typedef unsigned long long u64;

__device__ float g_sp[NN * NS];
__device__ float g_vp[NN * 3 * NV];   // [n][c*64+v]

__device__ __forceinline__ float siluf(float x) { return x / (1.0f + __expf(-x)); }
__device__ __forceinline__ void fma2(u64& d, u64 a, u64 b) {
    asm("fma.rn.f32x2 %0, %1, %2, %0;" : "+l"(d) : "l"(a), "l"(b));
}
__device__ __forceinline__ u64 pk(float x, float y) {
    u64 r; asm("mov.b64 %0, {%1, %2};" : "=l"(r) : "f"(x), "f"(y)); return r;
}
__device__ __forceinline__ float2 up(u64 a) {
    float2 r; asm("mov.b64 {%0, %1}, %2;" : "=f"(r.x), "=f"(r.y) : "l"(a)); return r;
}
// half2 bits -> packed f32x2 operand
__device__ __forceinline__ u64 h2pk(unsigned int h) {
    __half2 hh = *reinterpret_cast<__half2*>(&h);
    float2 f = __half22float2(hh);
    return pk(f.x, f.y);
}
__device__ __forceinline__ unsigned int f2h2(float a, float b) {
    __half2 h = __floats2half2_rn(a, b);
    return *reinterpret_cast<unsigned int*>(&h);
}

// ---------------------------------------------------------------------------
__global__ __launch_bounds__(256) void node_kernel(
    const float* __restrict__ x,
    const float* __restrict__ Wps, const float* __restrict__ bps,
    const float* __restrict__ Wpv,
    const float* __restrict__ gw, const float* __restrict__ gb,
    int N)
{
    __shared__ float sx[4][256];
    const int ln = threadIdx.x >> 6;
    const int v  = threadIdx.x & 63;
    const int n  = blockIdx.x * 4 + ln;

    if (n < N) {
        #pragma unroll
        for (int i = v; i < 256; i += 64) sx[ln][i] = x[n * 256 + i];
    }
    __syncthreads();
    if (n >= N) return;

    const float* xs = sx[ln];
    const float* xv = sx[ln] + 64;

    float sacc = bps[v];
    #pragma unroll 4
    for (int i = 0; i < NS; i++) sacc = fmaf(xs[i], Wps[i * NS + v], sacc);

    float ax = 0.f, ay = 0.f, az = 0.f;
    #pragma unroll 4
    for (int u = 0; u < NV; u++) {
        float w = Wpv[u * NV + v];
        ax = fmaf(xv[u * 3 + 0], w, ax);
        ay = fmaf(xv[u * 3 + 1], w, ay);
        az = fmaf(xv[u * 3 + 2], w, az);
    }
    float nrm = sqrtf(ax * ax + ay * ay + az * az + 1e-12f);
    float g = siluf(nrm * gw[v] + gb[v]);

    g_sp[n * NS + v] = siluf(sacc);
    g_vp[n * 192 + 0 * 64 + v] = ax * g;
    g_vp[n * 192 + 1 * 64 + v] = ay * g;
    g_vp[n * 192 + 2 * 64 + v] = az * g;
}

// ---------------------------------------------------------------------------
__global__ __launch_bounds__(BT, 2) void edge_kernel(
    const float* __restrict__ x,
    const float* __restrict__ edge_attr,
    const float* __restrict__ fij_in,
    const float* __restrict__ Ws1, const float* __restrict__ bs1,
    const float* __restrict__ Ws2, const float* __restrict__ bs2,
    const float* __restrict__ Wr1, const float* __restrict__ br1,
    const float* __restrict__ Wr2, const float* __restrict__ br2,
    const float* __restrict__ gwp, const float* __restrict__ gbp,
    const float* __restrict__ Wpost_s, const float* __restrict__ Wpost_v,
    const int* __restrict__ ei,
    float* __restrict__ out, int E)
{
    extern __shared__ float sm[];
    __half* s0h   = (__half*)(sm + OFF_S0T);   // [192][16]
    __half* h1h   = (__half*)(sm + OFF_H1T);   // [128][16]
    __half* r1h   = (__half*)(sm + OFF_R1T);   // [128][16]
    __half* Vth   = (__half*)(sm + OFF_VT);    // [192][48] after ph3 (scaled by 1/16)
    float*  spsT  = sm + OFF_SPS;
    float*  vpsT  = sm + OFF_VPS;
    float*  tpwT  = sm + OFF_TPW;              // [320][16]
    __half* outsh = (__half*)(sm + OFF_OUTS);  // [128][16]
    float*  eat   = sm + OFF_EAT;
    int*    sidx  = (int*)(sm + OFF_IDX);

    const int tid = threadIdx.x;
    const int e0  = blockIdx.x * TE;

    if (tid < 32) {
        int e = tid & 15;
        sidx[tid] = (tid < 16) ? ei[e0 + e] : ei[E + e0 + e];
    }
    __syncthreads();

    // ---- Phase 1 (tid<256): gather x, g_sp, g_vp; (tid>=256): edge_attr ----
    if (tid < 256) {
        const int e = tid & 15, q = tid >> 4;
        const int s = sidx[e], d = sidx[TE + e];
        const float* xs = x + (size_t)s * 256;
        const float* xd = x + (size_t)d * 256;

        float4 a = *(const float4*)(xs + q * 4);
        float4 b = *(const float4*)(xd + q * 4);
        s0h[(q*4+0)*16+e] = __float2half_rn(a.x);
        s0h[(q*4+1)*16+e] = __float2half_rn(a.y);
        s0h[(q*4+2)*16+e] = __float2half_rn(a.z);
        s0h[(q*4+3)*16+e] = __float2half_rn(a.w);
        s0h[(64+q*4+0)*16+e] = __float2half_rn(b.x);
        s0h[(64+q*4+1)*16+e] = __float2half_rn(b.y);
        s0h[(64+q*4+2)*16+e] = __float2half_rn(b.z);
        s0h[(64+q*4+3)*16+e] = __float2half_rn(b.w);

        float4 v0 = *(const float4*)(xs + 64 + q*12);
        float4 v1 = *(const float4*)(xs + 64 + q*12 + 4);
        float4 v2 = *(const float4*)(xs + 64 + q*12 + 8);
        float4 w0 = *(const float4*)(xd + 64 + q*12);
        float4 w1 = *(const float4*)(xd + 64 + q*12 + 4);
        float4 w2 = *(const float4*)(xd + 64 + q*12 + 8);
        float d0 = v0.x*w0.x + v0.y*w0.y + v0.z*w0.z;
        float d1 = v0.w*w0.w + v1.x*w1.x + v1.y*w1.y;
        float d2 = v1.z*w1.z + v1.w*w1.w + v2.x*w2.x;
        float d3 = v2.y*w2.y + v2.z*w2.z + v2.w*w2.w;
        s0h[(128+q*4+0)*16+e] = __float2half_rn(d0);
        s0h[(128+q*4+1)*16+e] = __float2half_rn(d1);
        s0h[(128+q*4+2)*16+e] = __float2half_rn(d2);
        s0h[(128+q*4+3)*16+e] = __float2half_rn(d3);

        float4 gs = *(const float4*)(g_sp + (size_t)s * 64 + q * 4);
        float4 gd = *(const float4*)(g_sp + (size_t)d * 64 + q * 4);
        spsT[(q*4+0)*16+e] = gs.x; spsT[(q*4+1)*16+e] = gs.y;
        spsT[(q*4+2)*16+e] = gs.z; spsT[(q*4+3)*16+e] = gs.w;
        spsT[(64+q*4+0)*16+e] = gd.x; spsT[(64+q*4+1)*16+e] = gd.y;
        spsT[(64+q*4+2)*16+e] = gd.z; spsT[(64+q*4+3)*16+e] = gd.w;

        {
            float4 p0 = *(const float4*)(g_vp + (size_t)s * 192 + q * 12);
            float4 p1 = *(const float4*)(g_vp + (size_t)s * 192 + q * 12 + 4);
            float4 p2 = *(const float4*)(g_vp + (size_t)s * 192 + q * 12 + 8);
            float pv[12] = {p0.x,p0.y,p0.z,p0.w,p1.x,p1.y,p1.z,p1.w,p2.x,p2.y,p2.z,p2.w};
            #pragma unroll
            for (int r = 0; r < 12; r++) vpsT[(q*12 + r)*16 + e] = pv[r];
        }
        {
            float4 p0 = *(const float4*)(g_vp + (size_t)d * 192 + q * 12);
            float4 p1 = *(const float4*)(g_vp + (size_t)d * 192 + q * 12 + 4);
            float4 p2 = *(const float4*)(g_vp + (size_t)d * 192 + q * 12 + 8);
            float pv[12] = {p0.x,p0.y,p0.z,p0.w,p1.x,p1.y,p1.z,p1.w,p2.x,p2.y,p2.z,p2.w};
            #pragma unroll
            for (int r = 0; r < 12; r++) vpsT[(192 + q*12 + r)*16 + e] = pv[r];
        }
    } else {
        for (int idx = tid - 256; idx < TE * EAD; idx += 64) {
            eat[idx] = edge_attr[(size_t)(e0 + (idx & 15)) * EAD + (idx >> 4)];
        }
    }
    __syncthreads();

    // ---- Phase 2 (tid<256): thread = 2 k x 4 edges, both branches ----
    if (tid < 256) {
        const int kp = tid >> 2;   // k = kp*2, kp*2+1
        const int eq = tid & 3;    // edges eq*4..+3
        // s-branch (192 k-steps)
        {
            float2 bb = *(const float2*)(bs1 + kp*2);
            u64 a0[2] = {pk(bb.x,bb.x), pk(bb.x,bb.x)};
            u64 a1[2] = {pk(bb.y,bb.y), pk(bb.y,bb.y)};
            #pragma unroll 4
            for (int i = 0; i < KS0; i++) {
                float2 w = *(const float2*)(Ws1 + i*HID + kp*2);
                uint2 aa = *(const uint2*)(s0h + i*16 + eq*4);
                u64 x01 = h2pk(aa.x), x23 = h2pk(aa.y);
                u64 w0 = pk(w.x,w.x), w1 = pk(w.y,w.y);
                fma2(a0[0], x01, w0); fma2(a0[1], x23, w0);
                fma2(a1[0], x01, w1); fma2(a1[1], x23, w1);
            }
            float2 q0 = up(a0[0]), q1 = up(a0[1]);
            *(uint2*)(h1h + (kp*2)*16 + eq*4) =
                make_uint2(f2h2(siluf(q0.x), siluf(q0.y)), f2h2(siluf(q1.x), siluf(q1.y)));
            q0 = up(a1[0]); q1 = up(a1[1]);
            *(uint2*)(h1h + (kp*2+1)*16 + eq*4) =
                make_uint2(f2h2(siluf(q0.x), siluf(q0.y)), f2h2(siluf(q1.x), siluf(q1.y)));
        }
        // r-branch (20 k-steps, eat fp32)
        {
            float2 bb = *(const float2*)(br1 + kp*2);
            u64 a0[2] = {pk(bb.x,bb.x), pk(bb.x,bb.x)};
            u64 a1[2] = {pk(bb.y,bb.y), pk(bb.y,bb.y)};
            #pragma unroll 4
            for (int i = 0; i < EAD; i++) {
                float2 w = *(const float2*)(Wr1 + i*HID + kp*2);
                ulonglong2 aa = *(const ulonglong2*)(eat + i*16 + eq*4);
                u64 w0 = pk(w.x,w.x), w1 = pk(w.y,w.y);
                fma2(a0[0], aa.x, w0); fma2(a0[1], aa.y, w0);
                fma2(a1[0], aa.x, w1); fma2(a1[1], aa.y, w1);
            }
            float2 q0 = up(a0[0]), q1 = up(a0[1]);
            *(uint2*)(r1h + (kp*2)*16 + eq*4) =
                make_uint2(f2h2(siluf(q0.x), siluf(q0.y)), f2h2(siluf(q1.x), siluf(q1.y)));
            q0 = up(a1[0]); q1 = up(a1[1]);
            *(uint2*)(r1h + (kp*2+1)*16 + eq*4) =
                make_uint2(f2h2(siluf(q0.x), siluf(q0.y)), f2h2(siluf(q1.x), siluf(q1.y)));
        }
    }
    __syncthreads();

    // ---- Phase 3: thread = 4 kv x 4 edges, both branches (320 threads) ----
    {
        const int kvg = tid >> 2;   // kv = kvg*4..+3
        const int eq  = tid & 3;    // edges eq*4..+3
        u64 att[4][2], arr[4][2];
        #pragma unroll
        for (int kv = 0; kv < 4; kv++) {
            att[kv][0] = att[kv][1] = pk(0.f, 0.f);
            arr[kv][0] = arr[kv][1] = pk(0.f, 0.f);
        }
        #pragma unroll 2
        for (int i = 0; i < HID; i++) {
            float4 wt = *(const float4*)(Ws2 + i*WN + kvg*4);
            float4 wr = *(const float4*)(Wr2 + i*WN + kvg*4);
            uint2 ah = *(const uint2*)(h1h + i*16 + eq*4);
            uint2 ag = *(const uint2*)(r1h + i*16 + eq*4);
            u64 h01 = h2pk(ah.x), h23 = h2pk(ah.y);
            u64 r01 = h2pk(ag.x), r23 = h2pk(ag.y);
            float wts[4] = {wt.x, wt.y, wt.z, wt.w};
            float wrs[4] = {wr.x, wr.y, wr.z, wr.w};
            #pragma unroll
            for (int kv = 0; kv < 4; kv++) {
                u64 w2 = pk(wts[kv], wts[kv]);
                fma2(att[kv][0], h01, w2);
                fma2(att[kv][1], h23, w2);
            }
            #pragma unroll
            for (int kv = 0; kv < 4; kv++) {
                u64 w3 = pk(wrs[kv], wrs[kv]);
                fma2(arr[kv][0], r01, w3);
                fma2(arr[kv][1], r23, w3);
            }
        }
        #pragma unroll
        for (int kv = 0; kv < 4; kv++) {
            float b2 = bs2[kvg*4+kv], c2 = br2[kvg*4+kv];
            #pragma unroll
            for (int p = 0; p < 2; p++) {
                float2 t = up(att[kv][p]), r = up(arr[kv][p]);
                *(u64*)(tpwT + (kvg*4+kv)*16 + eq*4 + p*2) =
                    pk((t.x + b2) * (r.x + c2), (t.y + b2) * (r.y + c2));
            }
        }
    }
    __syncthreads();

    // ---- Phase 4a: out_v gated -> Vth[u][3c x 16e] (half, scaled 1/16) ----
    for (int idx = tid; idx < TE * TPV; idx += BT) {
        int e = idx & 15, u = idx >> 4;
        float vx, vy, vz;
        if (u < 64) {
            float coef = tpwT[(64+u)*16+e] * spsT[u*16+e];
            vx = coef * vpsT[(192 +       u)*16+e];
            vy = coef * vpsT[(192 + 64  + u)*16+e];
            vz = coef * vpsT[(192 + 128 + u)*16+e];
        } else if (u < 128) {
            int uu = u - 64;
            float coef = tpwT[(128+uu)*16+e] * spsT[(64+uu)*16+e];
            vx = coef * vpsT[(      uu)*16+e];
            vy = coef * vpsT[( 64 + uu)*16+e];
            vz = coef * vpsT[(128 + uu)*16+e];
        } else {
            int uu = u - 128;
            float w5 = tpwT[(256+uu)*16+e] * INV_SQRT2;
            float ax = vpsT[uu*16+e],       ay = vpsT[(64+uu)*16+e],  az = vpsT[(128+uu)*16+e];
            float bx = vpsT[(192+uu)*16+e], by = vpsT[(256+uu)*16+e], bz = vpsT[(320+uu)*16+e];
            vx = w5 * (ay*bz - az*by);
            vy = w5 * (az*bx - ax*bz);
            vz = w5 * (ax*by - ay*bx);
        }
        float nrm = sqrtf(vx*vx + vy*vy + vz*vz + 1e-12f);
        float g = siluf(nrm * gwp[u] + gbp[u]) * VSCALE;
        Vth[u*48 +  0 + e] = __float2half_rn(vx * g);
        Vth[u*48 + 16 + e] = __float2half_rn(vy * g);
        Vth[u*48 + 32 + e] = __float2half_rn(vz * g);
    }

    // ---- Phase 4b: out_s -> outsh[j][e] (half) ----
    for (int idx = tid; idx < TE * TPS; idx += BT) {
        int e = idx & 15, j = idx >> 4;
        float val;
        if (j < 64) {
            val = tpwT[j*16+e] * spsT[j*16+e] * spsT[(64+j)*16+e];
        } else {
            int u = j - 64;
            float dt = vpsT[u*16+e]       * vpsT[(192+u)*16+e]
                     + vpsT[(64+u)*16+e]  * vpsT[(256+u)*16+e]
                     + vpsT[(128+u)*16+e] * vpsT[(320+u)*16+e];
            val = tpwT[(192+u)*16+e] * dt * INV_SQRT3;
        }
        outsh[j*16+e] = __float2half_rn(siluf(val));
    }
    __syncthreads();

    // ---- Phase 5: tid<192 -> fij_v (4v x 4cols); tid>=192 -> fij_s (2v x 4e) ----
    if (tid < 192) {
        const int vg = tid & 15;    // v = vg*4..+3
        const int cg = tid >> 4;    // cols cg*4..+3 of 48
        u64 acc[4][2];
        #pragma unroll
        for (int p = 0; p < 4; p++) acc[p][0] = acc[p][1] = pk(0.f, 0.f);
        #pragma unroll 2
        for (int u = 0; u < TPV; u++) {
            float4 w = *(const float4*)(Wpost_v + u*NV + vg*4);
            uint2 vv = *(const uint2*)(Vth + u*48 + cg*4);
            u64 v01 = h2pk(vv.x), v23 = h2pk(vv.y);
            float ws[4] = {w.x, w.y, w.z, w.w};
            #pragma unroll
            for (int p = 0; p < 4; p++) {
                u64 ww = pk(ws[p], ws[p]);
                fma2(acc[p][0], v01, ww);
                fma2(acc[p][1], v23, ww);
            }
        }
        const int c  = cg >> 2;
        const int eb = (cg & 3) * 4;
        #pragma unroll
        for (int p = 0; p < 4; p++) {
            int v = vg*4 + p;
            #pragma unroll
            for (int h = 0; h < 2; h++) {
                float2 q = up(acc[p][h]);
                size_t o0 = (size_t)(e0 + eb + h*2)     * 256 + 64 + (size_t)v*3 + c;
                size_t o1 = (size_t)(e0 + eb + h*2 + 1) * 256 + 64 + (size_t)v*3 + c;
                out[o0] = fij_in[o0] + q.x * VUNSCALE;
                out[o1] = fij_in[o1] + q.y * VUNSCALE;
            }
        }
    } else {
        const int t  = tid - 192;   // 0..127
        const int vp = t >> 2;      // v = vp*2, vp*2+1
        const int eq = t & 3;       // edges eq*4..+3
        u64 a0[2] = {pk(0.f,0.f), pk(0.f,0.f)};
        u64 a1[2] = {pk(0.f,0.f), pk(0.f,0.f)};
        #pragma unroll 4
        for (int j = 0; j < TPS; j++) {
            float2 w = *(const float2*)(Wpost_s + j*NS + vp*2);
            uint2 oo = *(const uint2*)(outsh + j*16 + eq*4);
            u64 o01 = h2pk(oo.x), o23 = h2pk(oo.y);
            u64 w0 = pk(w.x,w.x), w1 = pk(w.y,w.y);
            fma2(a0[0], o01, w0); fma2(a0[1], o23, w0);
            fma2(a1[0], o01, w1); fma2(a1[1], o23, w1);
        }
        #pragma unroll
        for (int vv = 0; vv < 2; vv++) {
            #pragma unroll
            for (int h = 0; h < 2; h++) {
                float2 q = up(vv ? a1[h] : a0[h]);
                size_t o0 = (size_t)(e0 + eq*4 + h*2)     * 256 + vp*2 + vv;
                size_t o1 = (size_t)(e0 + eq*4 + h*2 + 1) * 256 + vp*2 + vv;
                out[o0] = fij_in[o0] + q.x;
                out[o1] = fij_in[o1] + q.y;
            }
        }
    }
}

// ---------------------------------------------------------------------------
extern "C" void kernel_launch(void* const* d_in, const int* in_sizes, int n_in,
                              void* d_out, int out_size)
{
    const float* x         = (const float*)d_in[0];
    const float* edge_attr = (const float*)d_in[1];
    const float* fij_in    = (const float*)d_in[2];
    const float* W_pre_s   = (const float*)d_in[3];
    const float* b_pre_s   = (const float*)d_in[4];
    const float* W_pre_v   = (const float*)d_in[5];
    const float* gw_pre    = (const float*)d_in[6];
    const float* gb_pre    = (const float*)d_in[7];
    const float* Ws1       = (const float*)d_in[8];
    const float* bs1       = (const float*)d_in[9];
    const float* Ws2       = (const float*)d_in[10];
    const float* bs2       = (const float*)d_in[11];
    const float* Wr1       = (const float*)d_in[12];
    const float* br1       = (const float*)d_in[13];
    const float* Wr2       = (const float*)d_in[14];
    const float* br2       = (const float*)d_in[15];
    const float* gw_post   = (const float*)d_in[16];
    const float* gb_post   = (const float*)d_in[17];
    const float* W_post_s  = (const float*)d_in[18];
    const float* W_post_v  = (const float*)d_in[19];
    const int*   ei        = (const int*)d_in[20];

    const int N = in_sizes[0] / 256;
    const int E = in_sizes[2] / 256;

    node_kernel<<<(N + 3) / 4, 256>>>(x, W_pre_s, b_pre_s, W_pre_v, gw_pre, gb_pre, N);

    const size_t shm = (size_t)SMEM_FLOATS * 4;   // 77184 B
    cudaFuncSetAttribute(edge_kernel, cudaFuncAttributeMaxDynamicSharedMemorySize, (int)shm);

    edge_kernel<<<E / TE, BT, shm>>>(
        x, edge_attr, fij_in,
        Ws1, bs1, Ws2, bs2, Wr1, br1, Wr2, br2,
        gw_post, gb_post, W_post_s, W_post_v,
        ei, (float*)d_out, E);
}

// round 9
// speedup vs baseline: 1.1142x; 1.1142x over previous
#include <cuda_runtime.h>
#include <cuda_bf16.h>
#include <cuda_fp16.h>

#define NN 10000
#define NS 64
#define NV 64
#define HID 128
#define WN 320
#define KS0 192
#define EAD 20
#define TPS 128
#define TPV 192

#define TE 16
#define BT 320

#define INV_SQRT3 0.5773502691896258f
#define INV_SQRT2 0.7071067811865476f
#define VSCALE    0.0625f
#define VUNSCALE  16.0f

// smem offsets (float units)
#define OFF_S0T   0        // half [192][16] (1536 fu) ─┐ region A (6656 fu)
#define OFF_H1T   1536     // f32  [128][20] (2560 fu)  │ Vth half [192][48]
#define OFF_R1T   4096     // f32  [128][20] (2560 fu)  │ (4608 fu) overlays
#define OFF_VT    0        //                           ┘
#define OFF_SPS   6656     // f32  [128][16] (2048)
#define OFF_VPS   8704     // f32  [384][16] (6144)
#define OFF_TPW   14848    // half [320][16] (2560)
#define OFF_OUTS  17408    // half [128][16] (1024)
#define OFF_EAT   18432    // f32  [20][16]  (320)
#define OFF_IDX   18752    // 32 ints
#define SMEM_FLOATS 18784  // 75136 B

typedef unsigned long long u64;

__device__ float g_sp[NN * NS];
__device__ float g_vp[NN * 3 * NV];   // [n][c*64+v]

__device__ __forceinline__ float siluf(float x) { return x / (1.0f + __expf(-x)); }
__device__ __forceinline__ void fma2(u64& d, u64 a, u64 b) {
    asm("fma.rn.f32x2 %0, %1, %2, %0;" : "+l"(d) : "l"(a), "l"(b));
}
__device__ __forceinline__ u64 pk(float x, float y) {
    u64 r; asm("mov.b64 %0, {%1, %2};" : "=l"(r) : "f"(x), "f"(y)); return r;
}
__device__ __forceinline__ float2 up(u64 a) {
    float2 r; asm("mov.b64 {%0, %1}, %2;" : "=f"(r.x), "=f"(r.y) : "l"(a)); return r;
}
__device__ __forceinline__ u64 h2pk(unsigned int h) {
    __half2 hh = *reinterpret_cast<__half2*>(&h);
    float2 f = __half22float2(hh);
    return pk(f.x, f.y);
}
__device__ __forceinline__ unsigned int f2h2(float a, float b) {
    __half2 h = __floats2half2_rn(a, b);
    return *reinterpret_cast<unsigned int*>(&h);
}

// ---------------------------------------------------------------------------
__global__ __launch_bounds__(256) void node_kernel(
    const float* __restrict__ x,
    const float* __restrict__ Wps, const float* __restrict__ bps,
    const float* __restrict__ Wpv,
    const float* __restrict__ gw, const float* __restrict__ gb,
    int N)
{
    __shared__ float sx[4][256];
    const int ln = threadIdx.x >> 6;
    const int v  = threadIdx.x & 63;
    const int n  = blockIdx.x * 4 + ln;

    if (n < N) {
        #pragma unroll
        for (int i = v; i < 256; i += 64) sx[ln][i] = x[n * 256 + i];
    }
    __syncthreads();
    if (n >= N) return;

    const float* xs = sx[ln];
    const float* xv = sx[ln] + 64;

    float sacc = bps[v];
    #pragma unroll 4
    for (int i = 0; i < NS; i++) sacc = fmaf(xs[i], Wps[i * NS + v], sacc);

    float ax = 0.f, ay = 0.f, az = 0.f;
    #pragma unroll 4
    for (int u = 0; u < NV; u++) {
        float w = Wpv[u * NV + v];
        ax = fmaf(xv[u * 3 + 0], w, ax);
        ay = fmaf(xv[u * 3 + 1], w, ay);
        az = fmaf(xv[u * 3 + 2], w, az);
    }
    float nrm = sqrtf(ax * ax + ay * ay + az * az + 1e-12f);
    float g = siluf(nrm * gw[v] + gb[v]);

    g_sp[n * NS + v] = siluf(sacc);
    g_vp[n * 192 + 0 * 64 + v] = ax * g;
    g_vp[n * 192 + 1 * 64 + v] = ay * g;
    g_vp[n * 192 + 2 * 64 + v] = az * g;
}

// ---------------------------------------------------------------------------
__global__ __launch_bounds__(BT, 3) void edge_kernel(
    const float* __restrict__ x,
    const float* __restrict__ edge_attr,
    const float* __restrict__ fij_in,
    const float* __restrict__ Ws1, const float* __restrict__ bs1,
    const float* __restrict__ Ws2, const float* __restrict__ bs2,
    const float* __restrict__ Wr1, const float* __restrict__ br1,
    const float* __restrict__ Wr2, const float* __restrict__ br2,
    const float* __restrict__ gwp, const float* __restrict__ gbp,
    const float* __restrict__ Wpost_s, const float* __restrict__ Wpost_v,
    const int* __restrict__ ei,
    float* __restrict__ out, int E)
{
    extern __shared__ float sm[];
    __half* s0h   = (__half*)(sm + OFF_S0T);   // [192][16]
    float*  h1t   = sm + OFF_H1T;              // [128][20]
    float*  r1t   = sm + OFF_R1T;              // [128][20]
    __half* Vth   = (__half*)(sm + OFF_VT);    // [192][48] after ph3 (scaled 1/16)
    float*  spsT  = sm + OFF_SPS;
    float*  vpsT  = sm + OFF_VPS;
    __half* tpwh  = (__half*)(sm + OFF_TPW);   // [320][16]
    __half* outsh = (__half*)(sm + OFF_OUTS);  // [128][16]
    float*  eat   = sm + OFF_EAT;
    int*    sidx  = (int*)(sm + OFF_IDX);

    const int tid = threadIdx.x;
    const int e0  = blockIdx.x * TE;

    if (tid < 32) {
        int e = tid & 15;
        sidx[tid] = (tid < 16) ? ei[e0 + e] : ei[E + e0 + e];
    }
    __syncthreads();

    // ---- Phase 1 (tid<256): gather x, g_sp, g_vp; (tid>=256): edge_attr ----
    if (tid < 256) {
        const int e = tid & 15, q = tid >> 4;
        const int s = sidx[e], d = sidx[TE + e];
        const float* xs = x + (size_t)s * 256;
        const float* xd = x + (size_t)d * 256;

        float4 a = *(const float4*)(xs + q * 4);
        float4 b = *(const float4*)(xd + q * 4);
        s0h[(q*4+0)*16+e] = __float2half_rn(a.x);
        s0h[(q*4+1)*16+e] = __float2half_rn(a.y);
        s0h[(q*4+2)*16+e] = __float2half_rn(a.z);
        s0h[(q*4+3)*16+e] = __float2half_rn(a.w);
        s0h[(64+q*4+0)*16+e] = __float2half_rn(b.x);
        s0h[(64+q*4+1)*16+e] = __float2half_rn(b.y);
        s0h[(64+q*4+2)*16+e] = __float2half_rn(b.z);
        s0h[(64+q*4+3)*16+e] = __float2half_rn(b.w);

        float4 v0 = *(const float4*)(xs + 64 + q*12);
        float4 v1 = *(const float4*)(xs + 64 + q*12 + 4);
        float4 v2 = *(const float4*)(xs + 64 + q*12 + 8);
        float4 w0 = *(const float4*)(xd + 64 + q*12);
        float4 w1 = *(const float4*)(xd + 64 + q*12 + 4);
        float4 w2 = *(const float4*)(xd + 64 + q*12 + 8);
        float d0 = v0.x*w0.x + v0.y*w0.y + v0.z*w0.z;
        float d1 = v0.w*w0.w + v1.x*w1.x + v1.y*w1.y;
        float d2 = v1.z*w1.z + v1.w*w1.w + v2.x*w2.x;
        float d3 = v2.y*w2.y + v2.z*w2.z + v2.w*w2.w;
        s0h[(128+q*4+0)*16+e] = __float2half_rn(d0);
        s0h[(128+q*4+1)*16+e] = __float2half_rn(d1);
        s0h[(128+q*4+2)*16+e] = __float2half_rn(d2);
        s0h[(128+q*4+3)*16+e] = __float2half_rn(d3);

        float4 gs = *(const float4*)(g_sp + (size_t)s * 64 + q * 4);
        float4 gd = *(const float4*)(g_sp + (size_t)d * 64 + q * 4);
        spsT[(q*4+0)*16+e] = gs.x; spsT[(q*4+1)*16+e] = gs.y;
        spsT[(q*4+2)*16+e] = gs.z; spsT[(q*4+3)*16+e] = gs.w;
        spsT[(64+q*4+0)*16+e] = gd.x; spsT[(64+q*4+1)*16+e] = gd.y;
        spsT[(64+q*4+2)*16+e] = gd.z; spsT[(64+q*4+3)*16+e] = gd.w;

        {
            float4 p0 = *(const float4*)(g_vp + (size_t)s * 192 + q * 12);
            float4 p1 = *(const float4*)(g_vp + (size_t)s * 192 + q * 12 + 4);
            float4 p2 = *(const float4*)(g_vp + (size_t)s * 192 + q * 12 + 8);
            float pv[12] = {p0.x,p0.y,p0.z,p0.w,p1.x,p1.y,p1.z,p1.w,p2.x,p2.y,p2.z,p2.w};
            #pragma unroll
            for (int r = 0; r < 12; r++) vpsT[(q*12 + r)*16 + e] = pv[r];
        }
        {
            float4 p0 = *(const float4*)(g_vp + (size_t)d * 192 + q * 12);
            float4 p1 = *(const float4*)(g_vp + (size_t)d * 192 + q * 12 + 4);
            float4 p2 = *(const float4*)(g_vp + (size_t)d * 192 + q * 12 + 8);
            float pv[12] = {p0.x,p0.y,p0.z,p0.w,p1.x,p1.y,p1.z,p1.w,p2.x,p2.y,p2.z,p2.w};
            #pragma unroll
            for (int r = 0; r < 12; r++) vpsT[(192 + q*12 + r)*16 + e] = pv[r];
        }
    } else {
        for (int idx = tid - 256; idx < TE * EAD; idx += 64) {
            eat[idx] = edge_attr[(size_t)(e0 + (idx & 15)) * EAD + (idx >> 4)];
        }
    }
    __syncthreads();

    // ---- Phase 2 (tid<256): thread = 2 k x 4 edges; h1/r1 written fp32 ----
    if (tid < 256) {
        const int kp = tid >> 2;   // k = kp*2, kp*2+1
        const int eq = tid & 3;    // edges eq*4..+3
        // s-branch (192 k-steps, s0 half input)
        {
            float2 bb = *(const float2*)(bs1 + kp*2);
            u64 a0[2] = {pk(bb.x,bb.x), pk(bb.x,bb.x)};
            u64 a1[2] = {pk(bb.y,bb.y), pk(bb.y,bb.y)};
            #pragma unroll 4
            for (int i = 0; i < KS0; i++) {
                float2 w = *(const float2*)(Ws1 + i*HID + kp*2);
                uint2 aa = *(const uint2*)(s0h + i*16 + eq*4);
                u64 x01 = h2pk(aa.x), x23 = h2pk(aa.y);
                u64 w0 = pk(w.x,w.x), w1 = pk(w.y,w.y);
                fma2(a0[0], x01, w0); fma2(a0[1], x23, w0);
                fma2(a1[0], x01, w1); fma2(a1[1], x23, w1);
            }
            float2 q0 = up(a0[0]), q1 = up(a0[1]);
            *(u64*)(h1t + (kp*2)*20 + eq*4)     = pk(siluf(q0.x), siluf(q0.y));
            *(u64*)(h1t + (kp*2)*20 + eq*4 + 2) = pk(siluf(q1.x), siluf(q1.y));
            q0 = up(a1[0]); q1 = up(a1[1]);
            *(u64*)(h1t + (kp*2+1)*20 + eq*4)     = pk(siluf(q0.x), siluf(q0.y));
            *(u64*)(h1t + (kp*2+1)*20 + eq*4 + 2) = pk(siluf(q1.x), siluf(q1.y));
        }
        // r-branch (20 k-steps, eat fp32)
        {
            float2 bb = *(const float2*)(br1 + kp*2);
            u64 a0[2] = {pk(bb.x,bb.x), pk(bb.x,bb.x)};
            u64 a1[2] = {pk(bb.y,bb.y), pk(bb.y,bb.y)};
            #pragma unroll 4
            for (int i = 0; i < EAD; i++) {
                float2 w = *(const float2*)(Wr1 + i*HID + kp*2);
                ulonglong2 aa = *(const ulonglong2*)(eat + i*16 + eq*4);
                u64 w0 = pk(w.x,w.x), w1 = pk(w.y,w.y);
                fma2(a0[0], aa.x, w0); fma2(a0[1], aa.y, w0);
                fma2(a1[0], aa.x, w1); fma2(a1[1], aa.y, w1);
            }
            float2 q0 = up(a0[0]), q1 = up(a0[1]);
            *(u64*)(r1t + (kp*2)*20 + eq*4)     = pk(siluf(q0.x), siluf(q0.y));
            *(u64*)(r1t + (kp*2)*20 + eq*4 + 2) = pk(siluf(q1.x), siluf(q1.y));
            q0 = up(a1[0]); q1 = up(a1[1]);
            *(u64*)(r1t + (kp*2+1)*20 + eq*4)     = pk(siluf(q0.x), siluf(q0.y));
            *(u64*)(r1t + (kp*2+1)*20 + eq*4 + 2) = pk(siluf(q1.x), siluf(q1.y));
        }
    }
    __syncthreads();

    // ---- Phase 3: thread = 4 kv x 4 edges, fp32 h1/r1, no cvt in loop ----
    {
        const int kvg = tid >> 2;   // kv = kvg*4..+3
        const int eq  = tid & 3;    // edges eq*4..+3
        u64 att[4][2], arr[4][2];
        #pragma unroll
        for (int kv = 0; kv < 4; kv++) {
            att[kv][0] = att[kv][1] = pk(0.f, 0.f);
            arr[kv][0] = arr[kv][1] = pk(0.f, 0.f);
        }
        #pragma unroll 2
        for (int i = 0; i < HID; i++) {
            float4 wt = *(const float4*)(Ws2 + i*WN + kvg*4);
            float4 wr = *(const float4*)(Wr2 + i*WN + kvg*4);
            ulonglong2 hh = *(const ulonglong2*)(h1t + i*20 + eq*4);
            ulonglong2 rr = *(const ulonglong2*)(r1t + i*20 + eq*4);
            float wts[4] = {wt.x, wt.y, wt.z, wt.w};
            float wrs[4] = {wr.x, wr.y, wr.z, wr.w};
            #pragma unroll
            for (int kv = 0; kv < 4; kv++) {
                u64 w2 = pk(wts[kv], wts[kv]);
                fma2(att[kv][0], hh.x, w2);
                fma2(att[kv][1], hh.y, w2);
            }
            #pragma unroll
            for (int kv = 0; kv < 4; kv++) {
                u64 w3 = pk(wrs[kv], wrs[kv]);
                fma2(arr[kv][0], rr.x, w3);
                fma2(arr[kv][1], rr.y, w3);
            }
        }
        #pragma unroll
        for (int kv = 0; kv < 4; kv++) {
            float b2 = bs2[kvg*4+kv], c2 = br2[kvg*4+kv];
            float2 t0 = up(att[kv][0]), t1 = up(att[kv][1]);
            float2 r0 = up(arr[kv][0]), r1 = up(arr[kv][1]);
            *(uint2*)(tpwh + (kvg*4+kv)*16 + eq*4) = make_uint2(
                f2h2((t0.x + b2) * (r0.x + c2), (t0.y + b2) * (r0.y + c2)),
                f2h2((t1.x + b2) * (r1.x + c2), (t1.y + b2) * (r1.y + c2)));
        }
    }
    __syncthreads();

    // ---- Phase 4a: out_v gated -> Vth[u][3c x 16e] (half, scaled 1/16) ----
    for (int idx = tid; idx < TE * TPV; idx += BT) {
        int e = idx & 15, u = idx >> 4;
        float vx, vy, vz;
        if (u < 64) {
            float coef = __half2float(tpwh[(64+u)*16+e]) * spsT[u*16+e];
            vx = coef * vpsT[(192 +       u)*16+e];
            vy = coef * vpsT[(192 + 64  + u)*16+e];
            vz = coef * vpsT[(192 + 128 + u)*16+e];
        } else if (u < 128) {
            int uu = u - 64;
            float coef = __half2float(tpwh[(128+uu)*16+e]) * spsT[(64+uu)*16+e];
            vx = coef * vpsT[(      uu)*16+e];
            vy = coef * vpsT[( 64 + uu)*16+e];
            vz = coef * vpsT[(128 + uu)*16+e];
        } else {
            int uu = u - 128;
            float w5 = __half2float(tpwh[(256+uu)*16+e]) * INV_SQRT2;
            float ax = vpsT[uu*16+e],       ay = vpsT[(64+uu)*16+e],  az = vpsT[(128+uu)*16+e];
            float bx = vpsT[(192+uu)*16+e], by = vpsT[(256+uu)*16+e], bz = vpsT[(320+uu)*16+e];
            vx = w5 * (ay*bz - az*by);
            vy = w5 * (az*bx - ax*bz);
            vz = w5 * (ax*by - ay*bx);
        }
        float nrm = sqrtf(vx*vx + vy*vy + vz*vz + 1e-12f);
        float g = siluf(nrm * gwp[u] + gbp[u]) * VSCALE;
        Vth[u*48 +  0 + e] = __float2half_rn(vx * g);
        Vth[u*48 + 16 + e] = __float2half_rn(vy * g);
        Vth[u*48 + 32 + e] = __float2half_rn(vz * g);
    }

    // ---- Phase 4b: out_s -> outsh[j][e] (half) ----
    for (int idx = tid; idx < TE * TPS; idx += BT) {
        int e = idx & 15, j = idx >> 4;
        float val;
        if (j < 64) {
            val = __half2float(tpwh[j*16+e]) * spsT[j*16+e] * spsT[(64+j)*16+e];
        } else {
            int u = j - 64;
            float dt = vpsT[u*16+e]       * vpsT[(192+u)*16+e]
                     + vpsT[(64+u)*16+e]  * vpsT[(256+u)*16+e]
                     + vpsT[(128+u)*16+e] * vpsT[(320+u)*16+e];
            val = __half2float(tpwh[(192+u)*16+e]) * dt * INV_SQRT3;
        }
        outsh[j*16+e] = __float2half_rn(siluf(val));
    }
    __syncthreads();

    // ---- Phase 5: tid<192 -> fij_v (4v x 4cols); tid>=192 -> fij_s (2v x 4e) ----
    if (tid < 192) {
        const int vg = tid & 15;    // v = vg*4..+3
        const int cg = tid >> 4;    // cols cg*4..+3 of 48
        u64 acc[4][2];
        #pragma unroll
        for (int p = 0; p < 4; p++) acc[p][0] = acc[p][1] = pk(0.f, 0.f);
        #pragma unroll 2
        for (int u = 0; u < TPV; u++) {
            float4 w = *(const float4*)(Wpost_v + u*NV + vg*4);
            uint2 vv = *(const uint2*)(Vth + u*48 + cg*4);
            u64 v01 = h2pk(vv.x), v23 = h2pk(vv.y);
            float ws[4] = {w.x, w.y, w.z, w.w};
            #pragma unroll
            for (int p = 0; p < 4; p++) {
                u64 ww = pk(ws[p], ws[p]);
                fma2(acc[p][0], v01, ww);
                fma2(acc[p][1], v23, ww);
            }
        }
        const int c  = cg >> 2;
        const int eb = (cg & 3) * 4;
        #pragma unroll
        for (int p = 0; p < 4; p++) {
            int v = vg*4 + p;
            #pragma unroll
            for (int h = 0; h < 2; h++) {
                float2 q = up(acc[p][h]);
                size_t o0 = (size_t)(e0 + eb + h*2)     * 256 + 64 + (size_t)v*3 + c;
                size_t o1 = (size_t)(e0 + eb + h*2 + 1) * 256 + 64 + (size_t)v*3 + c;
                out[o0] = fij_in[o0] + q.x * VUNSCALE;
                out[o1] = fij_in[o1] + q.y * VUNSCALE;
            }
        }
    } else {
        const int t  = tid - 192;   // 0..127
        const int vp = t >> 2;      // v = vp*2, vp*2+1
        const int eq = t & 3;       // edges eq*4..+3
        u64 a0[2] = {pk(0.f,0.f), pk(0.f,0.f)};
        u64 a1[2] = {pk(0.f,0.f), pk(0.f,0.f)};
        #pragma unroll 4
        for (int j = 0; j < TPS; j++) {
            float2 w = *(const float2*)(Wpost_s + j*NS + vp*2);
            uint2 oo = *(const uint2*)(outsh + j*16 + eq*4);
            u64 o01 = h2pk(oo.x), o23 = h2pk(oo.y);
            u64 w0 = pk(w.x,w.x), w1 = pk(w.y,w.y);
            fma2(a0[0], o01, w0); fma2(a0[1], o23, w0);
            fma2(a1[0], o01, w1); fma2(a1[1], o23, w1);
        }
        #pragma unroll
        for (int vv = 0; vv < 2; vv++) {
            #pragma unroll
            for (int h = 0; h < 2; h++) {
                float2 q = up(vv ? a1[h] : a0[h]);
                size_t o0 = (size_t)(e0 + eq*4 + h*2)     * 256 + vp*2 + vv;
                size_t o1 = (size_t)(e0 + eq*4 + h*2 + 1) * 256 + vp*2 + vv;
                out[o0] = fij_in[o0] + q.x;
                out[o1] = fij_in[o1] + q.y;
            }
        }
    }
}

// ---------------------------------------------------------------------------
extern "C" void kernel_launch(void* const* d_in, const int* in_sizes, int n_in,
                              void* d_out, int out_size)
{
    const float* x         = (const float*)d_in[0];
    const float* edge_attr = (const float*)d_in[1];
    const float* fij_in    = (const float*)d_in[2];
    const float* W_pre_s   = (const float*)d_in[3];
    const float* b_pre_s   = (const float*)d_in[4];
    const float* W_pre_v   = (const float*)d_in[5];
    const float* gw_pre    = (const float*)d_in[6];
    const float* gb_pre    = (const float*)d_in[7];
    const float* Ws1       = (const float*)d_in[8];
    const float* bs1       = (const float*)d_in[9];
    const float* Ws2       = (const float*)d_in[10];
    const float* bs2       = (const float*)d_in[11];
    const float* Wr1       = (const float*)d_in[12];
    const float* br1       = (const float*)d_in[13];
    const float* Wr2       = (const float*)d_in[14];
    const float* br2       = (const float*)d_in[15];
    const float* gw_post   = (const float*)d_in[16];
    const float* gb_post   = (const float*)d_in[17];
    const float* W_post_s  = (const float*)d_in[18];
    const float* W_post_v  = (const float*)d_in[19];
    const int*   ei        = (const int*)d_in[20];

    const int N = in_sizes[0] / 256;
    const int E = in_sizes[2] / 256;

    node_kernel<<<(N + 3) / 4, 256>>>(x, W_pre_s, b_pre_s, W_pre_v, gw_pre, gb_pre, N);

    const size_t shm = (size_t)SMEM_FLOATS * 4;   // 75136 B
    cudaFuncSetAttribute(edge_kernel, cudaFuncAttributeMaxDynamicSharedMemorySize, (int)shm);

    edge_kernel<<<E / TE, BT, shm>>>(
        x, edge_attr, fij_in,
        Ws1, bs1, Ws2, bs2, Wr1, br1, Wr2, br2,
        gw_post, gb_post, W_post_s, W_post_v,
        ei, (float*)d_out, E);
}

// round 11
// speedup vs baseline: 1.2963x; 1.1635x over previous
#include <cuda_runtime.h>
#include <cuda_bf16.h>
#include <cuda_fp16.h>
#include <cstdint>

#define NN 10000
#define NS 64
#define NV 64
#define HID 128
#define WN 320
#define KS0 192
#define EAD 20
#define TPS 128
#define TPV 192

#define TE 16
#define BT 320
#define ROWH 136   // padded halves per h1/r1 row (272 B)

#define INV_SQRT3 0.5773502691896258f
#define INV_SQRT2 0.7071067811865476f
#define VSCALE    0.0625f
#define VUNSCALE  16.0f

// smem offsets (float units)
#define OFF_S0T   0        // half [192][16] (1536 fu) ─┐ region A (4608 fu)
#define OFF_H1    1536     // half [16][136] (1088 fu)  │ Vth half [192][48]
#define OFF_R1    2624     // half [16][136] (1088 fu)  │ overlays
#define OFF_VT    0        //                           ┘
#define OFF_SPS   4608     // f32  [128][16] (2048)
#define OFF_VPS   6656     // f32  [384][16] (6144)
#define OFF_TPW   12800    // half [320][16] (2560)
#define OFF_OUTS  15360    // half [128][16] (1024)
#define OFF_EAT   16384    // f32  [20][16]  (320)
#define OFF_IDX   16704    // 32 ints
#define SMEM_FLOATS 16736  // 66944 B

typedef unsigned long long u64;

__device__ float g_sp[NN * NS];
__device__ float g_vp[NN * 3 * NV];     // [n][c*64+v]
__device__ __half g_Ws2t[WN * HID];     // [n][k] fp16 (transposed)
__device__ __half g_Wr2t[WN * HID];     // [n][k] fp16

__device__ __forceinline__ float siluf(float x) { return x / (1.0f + __expf(-x)); }
__device__ __forceinline__ void fma2(u64& d, u64 a, u64 b) {
    asm("fma.rn.f32x2 %0, %1, %2, %0;" : "+l"(d) : "l"(a), "l"(b));
}
__device__ __forceinline__ u64 pk(float x, float y) {
    u64 r; asm("mov.b64 %0, {%1, %2};" : "=l"(r) : "f"(x), "f"(y)); return r;
}
__device__ __forceinline__ float2 up(u64 a) {
    float2 r; asm("mov.b64 {%0, %1}, %2;" : "=f"(r.x), "=f"(r.y) : "l"(a)); return r;
}
__device__ __forceinline__ u64 h2pk(unsigned int h) {
    __half2 hh = *reinterpret_cast<__half2*>(&h);
    float2 f = __half22float2(hh);
    return pk(f.x, f.y);
}
__device__ __forceinline__ unsigned int f2h2(float a, float b) {
    __half2 h = __floats2half2_rn(a, b);
    return *reinterpret_cast<unsigned int*>(&h);
}

// ---------------------------------------------------------------------------
__global__ __launch_bounds__(256) void node_kernel(
    const float* __restrict__ x,
    const float* __restrict__ Wps, const float* __restrict__ bps,
    const float* __restrict__ Wpv,
    const float* __restrict__ gw, const float* __restrict__ gb,
    int N)
{
    __shared__ float sx[4][256];
    const int ln = threadIdx.x >> 6;
    const int v  = threadIdx.x & 63;
    const int n  = blockIdx.x * 4 + ln;

    if (n < N) {
        #pragma unroll
        for (int i = v; i < 256; i += 64) sx[ln][i] = x[n * 256 + i];
    }
    __syncthreads();
    if (n >= N) return;

    const float* xs = sx[ln];
    const float* xv = sx[ln] + 64;

    float sacc = bps[v];
    #pragma unroll 4
    for (int i = 0; i < NS; i++) sacc = fmaf(xs[i], Wps[i * NS + v], sacc);

    float ax = 0.f, ay = 0.f, az = 0.f;
    #pragma unroll 4
    for (int u = 0; u < NV; u++) {
        float w = Wpv[u * NV + v];
        ax = fmaf(xv[u * 3 + 0], w, ax);
        ay = fmaf(xv[u * 3 + 1], w, ay);
        az = fmaf(xv[u * 3 + 2], w, az);
    }
    float nrm = sqrtf(ax * ax + ay * ay + az * az + 1e-12f);
    float g = siluf(nrm * gw[v] + gb[v]);

    g_sp[n * NS + v] = siluf(sacc);
    g_vp[n * 192 + 0 * 64 + v] = ax * g;
    g_vp[n * 192 + 1 * 64 + v] = ay * g;
    g_vp[n * 192 + 2 * 64 + v] = az * g;
}

// ---------------------------------------------------------------------------
// Weight transpose+fp16 convert: g_Ws2t[n][k] = Ws2[k][n]
__global__ __launch_bounds__(256) void wconv_kernel(
    const float* __restrict__ Ws2, const float* __restrict__ Wr2)
{
    int i = blockIdx.x * 256 + threadIdx.x;
    if (i < WN * HID) {
        int n = i >> 7, k = i & 127;
        g_Ws2t[i] = __float2half_rn(Ws2[k * WN + n]);
        g_Wr2t[i] = __float2half_rn(Wr2[k * WN + n]);
    }
}

// ---------------------------------------------------------------------------
__global__ __launch_bounds__(BT, 3) void edge_kernel(
    const float* __restrict__ x,
    const float* __restrict__ edge_attr,
    const float* __restrict__ fij_in,
    const float* __restrict__ Ws1, const float* __restrict__ bs1,
    const float* __restrict__ bs2,
    const float* __restrict__ Wr1, const float* __restrict__ br1,
    const float* __restrict__ br2,
    const float* __restrict__ gwp, const float* __restrict__ gbp,
    const float* __restrict__ Wpost_s, const float* __restrict__ Wpost_v,
    const int* __restrict__ ei,
    float* __restrict__ out, int E)
{
    extern __shared__ float sm[];
    __half* s0h   = (__half*)(sm + OFF_S0T);   // [192][16]
    __half* h1h   = (__half*)(sm + OFF_H1);    // [16][136]
    __half* r1h   = (__half*)(sm + OFF_R1);    // [16][136]
    __half* Vth   = (__half*)(sm + OFF_VT);    // [192][48] after ph3 (scaled 1/16)
    float*  spsT  = sm + OFF_SPS;
    float*  vpsT  = sm + OFF_VPS;
    __half* tpwh  = (__half*)(sm + OFF_TPW);   // [320][16]
    __half* outsh = (__half*)(sm + OFF_OUTS);  // [128][16]
    float*  eat   = sm + OFF_EAT;
    int*    sidx  = (int*)(sm + OFF_IDX);

    const int tid = threadIdx.x;
    const int e0  = blockIdx.x * TE;
    const unsigned smem_b = (unsigned)__cvta_generic_to_shared(sm);

    if (tid < 32) {
        int e = tid & 15;
        sidx[tid] = (tid < 16) ? ei[e0 + e] : ei[E + e0 + e];
    }
    __syncthreads();

    // ---- Phase 1 (tid<256): gather x, g_sp, g_vp; (tid>=256): edge_attr ----
    if (tid < 256) {
        const int e = tid & 15, q = tid >> 4;
        const int s = sidx[e], d = sidx[TE + e];
        const float* xs = x + (size_t)s * 256;
        const float* xd = x + (size_t)d * 256;

        float4 a = *(const float4*)(xs + q * 4);
        float4 b = *(const float4*)(xd + q * 4);
        s0h[(q*4+0)*16+e] = __float2half_rn(a.x);
        s0h[(q*4+1)*16+e] = __float2half_rn(a.y);
        s0h[(q*4+2)*16+e] = __float2half_rn(a.z);
        s0h[(q*4+3)*16+e] = __float2half_rn(a.w);
        s0h[(64+q*4+0)*16+e] = __float2half_rn(b.x);
        s0h[(64+q*4+1)*16+e] = __float2half_rn(b.y);
        s0h[(64+q*4+2)*16+e] = __float2half_rn(b.z);
        s0h[(64+q*4+3)*16+e] = __float2half_rn(b.w);

        float4 v0 = *(const float4*)(xs + 64 + q*12);
        float4 v1 = *(const float4*)(xs + 64 + q*12 + 4);
        float4 v2 = *(const float4*)(xs + 64 + q*12 + 8);
        float4 w0 = *(const float4*)(xd + 64 + q*12);
        float4 w1 = *(const float4*)(xd + 64 + q*12 + 4);
        float4 w2 = *(const float4*)(xd + 64 + q*12 + 8);
        float d0 = v0.x*w0.x + v0.y*w0.y + v0.z*w0.z;
        float d1 = v0.w*w0.w + v1.x*w1.x + v1.y*w1.y;
        float d2 = v1.z*w1.z + v1.w*w1.w + v2.x*w2.x;
        float d3 = v2.y*w2.y + v2.z*w2.z + v2.w*w2.w;
        s0h[(128+q*4+0)*16+e] = __float2half_rn(d0);
        s0h[(128+q*4+1)*16+e] = __float2half_rn(d1);
        s0h[(128+q*4+2)*16+e] = __float2half_rn(d2);
        s0h[(128+q*4+3)*16+e] = __float2half_rn(d3);

        float4 gs = *(const float4*)(g_sp + (size_t)s * 64 + q * 4);
        float4 gd = *(const float4*)(g_sp + (size_t)d * 64 + q * 4);
        spsT[(q*4+0)*16+e] = gs.x; spsT[(q*4+1)*16+e] = gs.y;
        spsT[(q*4+2)*16+e] = gs.z; spsT[(q*4+3)*16+e] = gs.w;
        spsT[(64+q*4+0)*16+e] = gd.x; spsT[(64+q*4+1)*16+e] = gd.y;
        spsT[(64+q*4+2)*16+e] = gd.z; spsT[(64+q*4+3)*16+e] = gd.w;

        {
            float4 p0 = *(const float4*)(g_vp + (size_t)s * 192 + q * 12);
            float4 p1 = *(const float4*)(g_vp + (size_t)s * 192 + q * 12 + 4);
            float4 p2 = *(const float4*)(g_vp + (size_t)s * 192 + q * 12 + 8);
            float pv[12] = {p0.x,p0.y,p0.z,p0.w,p1.x,p1.y,p1.z,p1.w,p2.x,p2.y,p2.z,p2.w};
            #pragma unroll
            for (int r = 0; r < 12; r++) vpsT[(q*12 + r)*16 + e] = pv[r];
        }
        {
            float4 p0 = *(const float4*)(g_vp + (size_t)d * 192 + q * 12);
            float4 p1 = *(const float4*)(g_vp + (size_t)d * 192 + q * 12 + 4);
            float4 p2 = *(const float4*)(g_vp + (size_t)d * 192 + q * 12 + 8);
            float pv[12] = {p0.x,p0.y,p0.z,p0.w,p1.x,p1.y,p1.z,p1.w,p2.x,p2.y,p2.z,p2.w};
            #pragma unroll
            for (int r = 0; r < 12; r++) vpsT[(192 + q*12 + r)*16 + e] = pv[r];
        }
    } else {
        for (int idx = tid - 256; idx < TE * EAD; idx += 64) {
            eat[idx] = edge_attr[(size_t)(e0 + (idx & 15)) * EAD + (idx >> 4)];
        }
    }
    __syncthreads();

    // ---- Phase 2 (tid<256): thread = 2 k x 4 edges; writes h1/r1 [e][K] half ----
    if (tid < 256) {
        const int kp = tid >> 2;   // k = kp*2, kp*2+1
        const int eq = tid & 3;    // edges eq*4..+3
        // s-branch (192 k-steps, s0 half input)
        {
            float2 bb = *(const float2*)(bs1 + kp*2);
            u64 a0[2] = {pk(bb.x,bb.x), pk(bb.x,bb.x)};
            u64 a1[2] = {pk(bb.y,bb.y), pk(bb.y,bb.y)};
            #pragma unroll 4
            for (int i = 0; i < KS0; i++) {
                float2 w = *(const float2*)(Ws1 + i*HID + kp*2);
                uint2 aa = *(const uint2*)(s0h + i*16 + eq*4);
                u64 x01 = h2pk(aa.x), x23 = h2pk(aa.y);
                u64 w0 = pk(w.x,w.x), w1 = pk(w.y,w.y);
                fma2(a0[0], x01, w0); fma2(a0[1], x23, w0);
                fma2(a1[0], x01, w1); fma2(a1[1], x23, w1);
            }
            float2 q0 = up(a0[0]);   // k,   edges e0,e1
            float2 q1 = up(a1[0]);   // k+1, edges e0,e1
            float2 q2 = up(a0[1]);   // k,   edges e2,e3
            float2 q3 = up(a1[1]);   // k+1, edges e2,e3
            *(unsigned*)(h1h + (eq*4+0)*ROWH + kp*2) = f2h2(siluf(q0.x), siluf(q1.x));
            *(unsigned*)(h1h + (eq*4+1)*ROWH + kp*2) = f2h2(siluf(q0.y), siluf(q1.y));
            *(unsigned*)(h1h + (eq*4+2)*ROWH + kp*2) = f2h2(siluf(q2.x), siluf(q3.x));
            *(unsigned*)(h1h + (eq*4+3)*ROWH + kp*2) = f2h2(siluf(q2.y), siluf(q3.y));
        }
        // r-branch (20 k-steps, eat fp32)
        {
            float2 bb = *(const float2*)(br1 + kp*2);
            u64 a0[2] = {pk(bb.x,bb.x), pk(bb.x,bb.x)};
            u64 a1[2] = {pk(bb.y,bb.y), pk(bb.y,bb.y)};
            #pragma unroll 4
            for (int i = 0; i < EAD; i++) {
                float2 w = *(const float2*)(Wr1 + i*HID + kp*2);
                ulonglong2 aa = *(const ulonglong2*)(eat + i*16 + eq*4);
                u64 w0 = pk(w.x,w.x), w1 = pk(w.y,w.y);
                fma2(a0[0], aa.x, w0); fma2(a0[1], aa.y, w0);
                fma2(a1[0], aa.x, w1); fma2(a1[1], aa.y, w1);
            }
            float2 q0 = up(a0[0]);
            float2 q1 = up(a1[0]);
            float2 q2 = up(a0[1]);
            float2 q3 = up(a1[1]);
            *(unsigned*)(r1h + (eq*4+0)*ROWH + kp*2) = f2h2(siluf(q0.x), siluf(q1.x));
            *(unsigned*)(r1h + (eq*4+1)*ROWH + kp*2) = f2h2(siluf(q0.y), siluf(q1.y));
            *(unsigned*)(r1h + (eq*4+2)*ROWH + kp*2) = f2h2(siluf(q2.x), siluf(q3.x));
            *(unsigned*)(r1h + (eq*4+3)*ROWH + kp*2) = f2h2(siluf(q2.y), siluf(q3.y));
        }
    }
    __syncthreads();

    // ---- Phase 3 (tensor): tp_w via mma.m16n8k16; warp = 4 n-tiles/branch ----
    {
        const int wid = tid >> 5, lane = tid & 31;
        const int g = lane >> 2, t = lane & 3;
        const unsigned aoffs = (unsigned)(lane & 15) * (ROWH * 2) + (unsigned)(lane >> 4) * 16;
        const unsigned h1addr = smem_b + OFF_H1 * 4 + aoffs;
        const unsigned r1addr = smem_b + OFF_R1 * 4 + aoffs;

        uint32_t A[8][4];
        float dt[2][4], dr[2][4];

        #pragma unroll
        for (int pass = 0; pass < 2; pass++) {
            const int ntb = wid * 4 + pass * 2;   // n-tiles ntb, ntb+1
            // --- t-branch: A = h1, B = Ws2t ---
            #pragma unroll
            for (int kt = 0; kt < 8; kt++)
                asm volatile("ldmatrix.sync.aligned.m8n8.x4.shared.b16 {%0,%1,%2,%3}, [%4];"
                    : "=r"(A[kt][0]), "=r"(A[kt][1]), "=r"(A[kt][2]), "=r"(A[kt][3])
                    : "r"(h1addr + kt * 32));
            #pragma unroll
            for (int q = 0; q < 2; q++) {
                dt[q][0] = dt[q][1] = dt[q][2] = dt[q][3] = 0.f;
                const __half* bp = g_Ws2t + ((ntb + q) * 8 + g) * HID + t * 2;
                #pragma unroll
                for (int kt = 0; kt < 8; kt++) {
                    uint32_t b0 = *(const uint32_t*)(bp + kt * 16);
                    uint32_t b1 = *(const uint32_t*)(bp + kt * 16 + 8);
                    asm volatile("mma.sync.aligned.m16n8k16.row.col.f32.f16.f16.f32 "
                        "{%0,%1,%2,%3}, {%4,%5,%6,%7}, {%8,%9}, {%0,%1,%2,%3};"
                        : "+f"(dt[q][0]), "+f"(dt[q][1]), "+f"(dt[q][2]), "+f"(dt[q][3])
                        : "r"(A[kt][0]), "r"(A[kt][1]), "r"(A[kt][2]), "r"(A[kt][3]),
                          "r"(b0), "r"(b1));
                }
            }
            // --- r-branch: A = r1, B = Wr2t ---
            #pragma unroll
            for (int kt = 0; kt < 8; kt++)
                asm volatile("ldmatrix.sync.aligned.m8n8.x4.shared.b16 {%0,%1,%2,%3}, [%4];"
                    : "=r"(A[kt][0]), "=r"(A[kt][1]), "=r"(A[kt][2]), "=r"(A[kt][3])
                    : "r"(r1addr + kt * 32));
            #pragma unroll
            for (int q = 0; q < 2; q++) {
                dr[q][0] = dr[q][1] = dr[q][2] = dr[q][3] = 0.f;
                const __half* bp = g_Wr2t + ((ntb + q) * 8 + g) * HID + t * 2;
                #pragma unroll
                for (int kt = 0; kt < 8; kt++) {
                    uint32_t b0 = *(const uint32_t*)(bp + kt * 16);
                    uint32_t b1 = *(const uint32_t*)(bp + kt * 16 + 8);
                    asm volatile("mma.sync.aligned.m16n8k16.row.col.f32.f16.f16.f32 "
                        "{%0,%1,%2,%3}, {%4,%5,%6,%7}, {%8,%9}, {%0,%1,%2,%3};"
                        : "+f"(dr[q][0]), "+f"(dr[q][1]), "+f"(dr[q][2]), "+f"(dr[q][3])
                        : "r"(A[kt][0]), "r"(A[kt][1]), "r"(A[kt][2]), "r"(A[kt][3]),
                          "r"(b0), "r"(b1));
                }
            }
            // --- combine & store tpw ---
            #pragma unroll
            for (int q = 0; q < 2; q++) {
                int kv0 = (ntb + q) * 8 + t * 2;
                float2 bb = *(const float2*)(bs2 + kv0);
                float2 cc = *(const float2*)(br2 + kv0);
                tpwh[kv0*16 + g]          = __float2half_rn((dt[q][0]+bb.x)*(dr[q][0]+cc.x));
                tpwh[(kv0+1)*16 + g]      = __float2half_rn((dt[q][1]+bb.y)*(dr[q][1]+cc.y));
                tpwh[kv0*16 + g + 8]      = __float2half_rn((dt[q][2]+bb.x)*(dr[q][2]+cc.x));
                tpwh[(kv0+1)*16 + g + 8]  = __float2half_rn((dt[q][3]+bb.y)*(dr[q][3]+cc.y));
            }
        }
    }
    __syncthreads();

    // ---- Phase 4a: out_v gated -> Vth[u][3c x 16e] (half, scaled 1/16) ----
    for (int idx = tid; idx < TE * TPV; idx += BT) {
        int e = idx & 15, u = idx >> 4;
        float vx, vy, vz;
        if (u < 64) {
            float coef = __half2float(tpwh[(64+u)*16+e]) * spsT[u*16+e];
            vx = coef * vpsT[(192 +       u)*16+e];
            vy = coef * vpsT[(192 + 64  + u)*16+e];
            vz = coef * vpsT[(192 + 128 + u)*16+e];
        } else if (u < 128) {
            int uu = u - 64;
            float coef = __half2float(tpwh[(128+uu)*16+e]) * spsT[(64+uu)*16+e];
            vx = coef * vpsT[(      uu)*16+e];
            vy = coef * vpsT[( 64 + uu)*16+e];
            vz = coef * vpsT[(128 + uu)*16+e];
        } else {
            int uu = u - 128;
            float w5 = __half2float(tpwh[(256+uu)*16+e]) * INV_SQRT2;
            float ax = vpsT[uu*16+e],       ay = vpsT[(64+uu)*16+e],  az = vpsT[(128+uu)*16+e];
            float bx = vpsT[(192+uu)*16+e], by = vpsT[(256+uu)*16+e], bz = vpsT[(320+uu)*16+e];
            vx = w5 * (ay*bz - az*by);
            vy = w5 * (az*bx - ax*bz);
            vz = w5 * (ax*by - ay*bx);
        }
        float nrm = sqrtf(vx*vx + vy*vy + vz*vz + 1e-12f);
        float g = siluf(nrm * gwp[u] + gbp[u]) * VSCALE;
        Vth[u*48 +  0 + e] = __float2half_rn(vx * g);
        Vth[u*48 + 16 + e] = __float2half_rn(vy * g);
        Vth[u*48 + 32 + e] = __float2half_rn(vz * g);
    }

    // ---- Phase 4b: out_s -> outsh[j][e] (half) ----
    for (int idx = tid; idx < TE * TPS; idx += BT) {
        int e = idx & 15, j = idx >> 4;
        float val;
        if (j < 64) {
            val = __half2float(tpwh[j*16+e]) * spsT[j*16+e] * spsT[(64+j)*16+e];
        } else {
            int u = j - 64;
            float dt = vpsT[u*16+e]       * vpsT[(192+u)*16+e]
                     + vpsT[(64+u)*16+e]  * vpsT[(256+u)*16+e]
                     + vpsT[(128+u)*16+e] * vpsT[(320+u)*16+e];
            val = __half2float(tpwh[(192+u)*16+e]) * dt * INV_SQRT3;
        }
        outsh[j*16+e] = __float2half_rn(siluf(val));
    }
    __syncthreads();

    // ---- Phase 5: tid<192 -> fij_v (4v x 4cols); tid>=192 -> fij_s (2v x 4e) ----
    if (tid < 192) {
        const int vg = tid & 15;    // v = vg*4..+3
        const int cg = tid >> 4;    // cols cg*4..+3 of 48
        u64 acc[4][2];
        #pragma unroll
        for (int p = 0; p < 4; p++) acc[p][0] = acc[p][1] = pk(0.f, 0.f);
        #pragma unroll 2
        for (int u = 0; u < TPV; u++) {
            float4 w = *(const float4*)(Wpost_v + u*NV + vg*4);
            uint2 vv = *(const uint2*)(Vth + u*48 + cg*4);
            u64 v01 = h2pk(vv.x), v23 = h2pk(vv.y);
            float ws[4] = {w.x, w.y, w.z, w.w};
            #pragma unroll
            for (int p = 0; p < 4; p++) {
                u64 ww = pk(ws[p], ws[p]);
                fma2(acc[p][0], v01, ww);
                fma2(acc[p][1], v23, ww);
            }
        }
        const int c  = cg >> 2;
        const int eb = (cg & 3) * 4;
        #pragma unroll
        for (int p = 0; p < 4; p++) {
            int v = vg*4 + p;
            #pragma unroll
            for (int h = 0; h < 2; h++) {
                float2 q = up(acc[p][h]);
                size_t o0 = (size_t)(e0 + eb + h*2)     * 256 + 64 + (size_t)v*3 + c;
                size_t o1 = (size_t)(e0 + eb + h*2 + 1) * 256 + 64 + (size_t)v*3 + c;
                out[o0] = fij_in[o0] + q.x * VUNSCALE;
                out[o1] = fij_in[o1] + q.y * VUNSCALE;
            }
        }
    } else {
        const int t  = tid - 192;   // 0..127
        const int vp = t >> 2;      // v = vp*2, vp*2+1
        const int eq = t & 3;       // edges eq*4..+3
        u64 a0[2] = {pk(0.f,0.f), pk(0.f,0.f)};
        u64 a1[2] = {pk(0.f,0.f), pk(0.f,0.f)};
        #pragma unroll 4
        for (int j = 0; j < TPS; j++) {
            float2 w = *(const float2*)(Wpost_s + j*NS + vp*2);
            uint2 oo = *(const uint2*)(outsh + j*16 + eq*4);
            u64 o01 = h2pk(oo.x), o23 = h2pk(oo.y);
            u64 w0 = pk(w.x,w.x), w1 = pk(w.y,w.y);
            fma2(a0[0], o01, w0); fma2(a0[1], o23, w0);
            fma2(a1[0], o01, w1); fma2(a1[1], o23, w1);
        }
        #pragma unroll
        for (int vv = 0; vv < 2; vv++) {
            #pragma unroll
            for (int h = 0; h < 2; h++) {
                float2 q = up(vv ? a1[h] : a0[h]);
                size_t o0 = (size_t)(e0 + eq*4 + h*2)     * 256 + vp*2 + vv;
                size_t o1 = (size_t)(e0 + eq*4 + h*2 + 1) * 256 + vp*2 + vv;
                out[o0] = fij_in[o0] + q.x;
                out[o1] = fij_in[o1] + q.y;
            }
        }
    }
}

// ---------------------------------------------------------------------------
extern "C" void kernel_launch(void* const* d_in, const int* in_sizes, int n_in,
                              void* d_out, int out_size)
{
    const float* x         = (const float*)d_in[0];
    const float* edge_attr = (const float*)d_in[1];
    const float* fij_in    = (const float*)d_in[2];
    const float* W_pre_s   = (const float*)d_in[3];
    const float* b_pre_s   = (const float*)d_in[4];
    const float* W_pre_v   = (const float*)d_in[5];
    const float* gw_pre    = (const float*)d_in[6];
    const float* gb_pre    = (const float*)d_in[7];
    const float* Ws1       = (const float*)d_in[8];
    const float* bs1       = (const float*)d_in[9];
    const float* Ws2       = (const float*)d_in[10];
    const float* bs2       = (const float*)d_in[11];
    const float* Wr1       = (const float*)d_in[12];
    const float* br1       = (const float*)d_in[13];
    const float* Wr2       = (const float*)d_in[14];
    const float* br2       = (const float*)d_in[15];
    const float* gw_post   = (const float*)d_in[16];
    const float* gb_post   = (const float*)d_in[17];
    const float* W_post_s  = (const float*)d_in[18];
    const float* W_post_v  = (const float*)d_in[19];
    const int*   ei        = (const int*)d_in[20];

    const int N = in_sizes[0] / 256;
    const int E = in_sizes[2] / 256;

    node_kernel<<<(N + 3) / 4, 256>>>(x, W_pre_s, b_pre_s, W_pre_v, gw_pre, gb_pre, N);
    wconv_kernel<<<(WN * HID + 255) / 256, 256>>>(Ws2, Wr2);

    const size_t shm = (size_t)SMEM_FLOATS * 4;   // 66944 B
    cudaFuncSetAttribute(edge_kernel, cudaFuncAttributeMaxDynamicSharedMemorySize, (int)shm);

    edge_kernel<<<E / TE, BT, shm>>>(
        x, edge_attr, fij_in,
        Ws1, bs1, bs2, Wr1, br1, br2,
        gw_post, gb_post, W_post_s, W_post_v,
        ei, (float*)d_out, E);
}

// round 12
// speedup vs baseline: 1.6606x; 1.2810x over previous
#include <cuda_runtime.h>
#include <cuda_bf16.h>
#include <cuda_fp16.h>
#include <cstdint>

#define NN 10000
#define NS 64
#define NV 64
#define HID 128
#define WN 320
#define KS0 192
#define EAD 20
#define TPS 128
#define TPV 192

#define TE 16
#define BT 320
#define ROWS0 200   // s0 row pitch (halves)
#define ROWH  136   // h1/r1/outs row pitch
#define ROWE  40    // eat row pitch
#define ROWV  200   // Vt2 row pitch

#define INV_SQRT3 0.5773502691896258f
#define INV_SQRT2 0.7071067811865476f
#define VSCALE    0.0625f
#define VUNSCALE  16.0f

// smem offsets (float units)
#define OFF_S0   0      // half [16][200] (1600 fu) ─┐ region A (4800 fu)
#define OFF_H1   1600   // half [16][136] (1088)     │ Vt2 half [48][200]
#define OFF_R1   2688   // half [16][136] (1088)     │ overlays after ph3
#define OFF_EAT2 3776   // half [16][40]  (320)      │
#define OFF_VT   0      //                           ┘
#define OFF_SPS  4800   // f32 [128][16] (2048)
#define OFF_VPS  6848   // f32 [384][16] (6144)
#define OFF_TPW  12992  // half [320][16] (2560)
#define OFF_OUTS 15552  // half [16][136] (1088)
#define OFF_IDX  16640  // 32 ints
#define SMEM_FLOATS 16672   // 66688 B

typedef unsigned long long u64;

__device__ float g_sp[NN * NS];
__device__ float g_vp[NN * 3 * NV];     // [n][c*64+v]
__device__ __half g_Ws1t[HID * KS0];    // [n][k]
__device__ __half g_Wr1t[HID * 32];     // [n][k] zero-padded k>=20
__device__ __half g_Ws2t[WN * HID];     // [n][k]
__device__ __half g_Wr2t[WN * HID];     // [n][k]
__device__ __half g_Wpvt[NV * TPV];     // [v][u]
__device__ __half g_Wpst[NV * TPS];     // [v][j]

__device__ __forceinline__ float siluf(float x) { return x / (1.0f + __expf(-x)); }
__device__ __forceinline__ void fma2(u64& d, u64 a, u64 b) {
    asm("fma.rn.f32x2 %0, %1, %2, %0;" : "+l"(d) : "l"(a), "l"(b));
}
__device__ __forceinline__ u64 pk(float x, float y) {
    u64 r; asm("mov.b64 %0, {%1, %2};" : "=l"(r) : "f"(x), "f"(y)); return r;
}
__device__ __forceinline__ float2 up(u64 a) {
    float2 r; asm("mov.b64 {%0, %1}, %2;" : "=f"(r.x), "=f"(r.y) : "l"(a)); return r;
}
__device__ __forceinline__ u64 h2pk(unsigned int h) {
    __half2 hh = *reinterpret_cast<__half2*>(&h);
    float2 f = __half22float2(hh);
    return pk(f.x, f.y);
}
__device__ __forceinline__ unsigned int f2h2(float a, float b) {
    __half2 h = __floats2half2_rn(a, b);
    return *reinterpret_cast<unsigned int*>(&h);
}
#define LDMX4(r0,r1,r2,r3,addr) \
    asm volatile("ldmatrix.sync.aligned.m8n8.x4.shared.b16 {%0,%1,%2,%3}, [%4];" \
        : "=r"(r0), "=r"(r1), "=r"(r2), "=r"(r3) : "r"(addr))
#define MMA16816(d0,d1,d2,d3,a0,a1,a2,a3,b0,b1) \
    asm volatile("mma.sync.aligned.m16n8k16.row.col.f32.f16.f16.f32 " \
        "{%0,%1,%2,%3}, {%4,%5,%6,%7}, {%8,%9}, {%0,%1,%2,%3};" \
        : "+f"(d0), "+f"(d1), "+f"(d2), "+f"(d3) \
        : "r"(a0), "r"(a1), "r"(a2), "r"(a3), "r"(b0), "r"(b1))

// ---------------------------------------------------------------------------
__global__ __launch_bounds__(256) void node_kernel(
    const float* __restrict__ x,
    const float* __restrict__ Wps, const float* __restrict__ bps,
    const float* __restrict__ Wpv,
    const float* __restrict__ gw, const float* __restrict__ gb,
    int N)
{
    __shared__ float sx[4][256];
    const int ln = threadIdx.x >> 6;
    const int v  = threadIdx.x & 63;
    const int n  = blockIdx.x * 4 + ln;

    if (n < N) {
        #pragma unroll
        for (int i = v; i < 256; i += 64) sx[ln][i] = x[n * 256 + i];
    }
    __syncthreads();
    if (n >= N) return;

    const float* xs = sx[ln];
    const float* xv = sx[ln] + 64;

    float sacc = bps[v];
    #pragma unroll 4
    for (int i = 0; i < NS; i++) sacc = fmaf(xs[i], Wps[i * NS + v], sacc);

    float ax = 0.f, ay = 0.f, az = 0.f;
    #pragma unroll 4
    for (int u = 0; u < NV; u++) {
        float w = Wpv[u * NV + v];
        ax = fmaf(xv[u * 3 + 0], w, ax);
        ay = fmaf(xv[u * 3 + 1], w, ay);
        az = fmaf(xv[u * 3 + 2], w, az);
    }
    float nrm = sqrtf(ax * ax + ay * ay + az * az + 1e-12f);
    float g = siluf(nrm * gw[v] + gb[v]);

    g_sp[n * NS + v] = siluf(sacc);
    g_vp[n * 192 + 0 * 64 + v] = ax * g;
    g_vp[n * 192 + 1 * 64 + v] = ay * g;
    g_vp[n * 192 + 2 * 64 + v] = az * g;
}

// ---------------------------------------------------------------------------
// Weight transpose + fp16 convert for all mma B operands
__global__ __launch_bounds__(256) void wconv_kernel(
    const float* __restrict__ Ws1, const float* __restrict__ Wr1,
    const float* __restrict__ Ws2, const float* __restrict__ Wr2,
    const float* __restrict__ Wpv, const float* __restrict__ Wps)
{
    int i = blockIdx.x * 256 + threadIdx.x;
    if (i < WN * HID) {
        int n = i / HID, k = i % HID;
        g_Ws2t[i] = __float2half_rn(Ws2[k * WN + n]);
        g_Wr2t[i] = __float2half_rn(Wr2[k * WN + n]);
    }
    if (i < HID * KS0) {
        int n = i / KS0, k = i % KS0;
        g_Ws1t[i] = __float2half_rn(Ws1[k * HID + n]);
    }
    if (i < HID * 32) {
        int n = i / 32, k = i % 32;
        g_Wr1t[i] = (k < EAD) ? __float2half_rn(Wr1[k * HID + n]) : __half(0.f);
    }
    if (i < NV * TPV) {
        int v = i / TPV, u = i % TPV;
        g_Wpvt[i] = __float2half_rn(Wpv[u * NV + v]);
    }
    if (i < NV * TPS) {
        int v = i / TPS, j = i % TPS;
        g_Wpst[i] = __float2half_rn(Wps[j * NV + v]);
    }
}

// ---------------------------------------------------------------------------
__global__ __launch_bounds__(BT, 3) void edge_kernel(
    const float* __restrict__ x,
    const float* __restrict__ edge_attr,
    const float* __restrict__ fij_in,
    const float* __restrict__ bs1, const float* __restrict__ bs2,
    const float* __restrict__ br1, const float* __restrict__ br2,
    const float* __restrict__ gwp, const float* __restrict__ gbp,
    const int* __restrict__ ei,
    float* __restrict__ out, int E)
{
    extern __shared__ float sm[];
    __half* s0h   = (__half*)(sm + OFF_S0);    // [16][200]
    __half* h1h   = (__half*)(sm + OFF_H1);    // [16][136]
    __half* r1h   = (__half*)(sm + OFF_R1);    // [16][136]
    __half* eat2  = (__half*)(sm + OFF_EAT2);  // [16][40]
    __half* Vth   = (__half*)(sm + OFF_VT);    // [48][200] after ph3 (scaled 1/16)
    float*  spsT  = sm + OFF_SPS;
    float*  vpsT  = sm + OFF_VPS;
    __half* tpwh  = (__half*)(sm + OFF_TPW);   // [320][16]
    __half* outsh = (__half*)(sm + OFF_OUTS);  // [16][136]
    int*    sidx  = (int*)(sm + OFF_IDX);

    const int tid = threadIdx.x;
    const int e0  = blockIdx.x * TE;
    const unsigned smem_b = (unsigned)__cvta_generic_to_shared(sm);
    const int wid = tid >> 5, lane = tid & 31;
    const int g = lane >> 2, t = lane & 3;
    const unsigned frag_off = (unsigned)(lane & 15) * 0 /*set per use*/;
    (void)frag_off;

    if (tid < 32) {
        int e = tid & 15;
        sidx[tid] = (tid < 16) ? ei[e0 + e] : ei[E + e0 + e];
    }
    __syncthreads();

    // ---- Phase 1 (tid<256): gather x (s0 -> [e][k] fp16), g_sp, g_vp ----
    if (tid < 256) {
        const int e = tid & 15, q = tid >> 4;
        const int s = sidx[e], d = sidx[TE + e];
        const float* xs = x + (size_t)s * 256;
        const float* xd = x + (size_t)d * 256;

        float4 a = *(const float4*)(xs + q * 4);
        float4 b = *(const float4*)(xd + q * 4);
        *(uint2*)(s0h + e*ROWS0 + q*4)      = make_uint2(f2h2(a.x, a.y), f2h2(a.z, a.w));
        *(uint2*)(s0h + e*ROWS0 + 64 + q*4) = make_uint2(f2h2(b.x, b.y), f2h2(b.z, b.w));

        float4 v0 = *(const float4*)(xs + 64 + q*12);
        float4 v1 = *(const float4*)(xs + 64 + q*12 + 4);
        float4 v2 = *(const float4*)(xs + 64 + q*12 + 8);
        float4 w0 = *(const float4*)(xd + 64 + q*12);
        float4 w1 = *(const float4*)(xd + 64 + q*12 + 4);
        float4 w2 = *(const float4*)(xd + 64 + q*12 + 8);
        float d0 = v0.x*w0.x + v0.y*w0.y + v0.z*w0.z;
        float d1 = v0.w*w0.w + v1.x*w1.x + v1.y*w1.y;
        float d2 = v1.z*w1.z + v1.w*w1.w + v2.x*w2.x;
        float d3 = v2.y*w2.y + v2.z*w2.z + v2.w*w2.w;
        *(uint2*)(s0h + e*ROWS0 + 128 + q*4) = make_uint2(f2h2(d0, d1), f2h2(d2, d3));

        float4 gs = *(const float4*)(g_sp + (size_t)s * 64 + q * 4);
        float4 gd = *(const float4*)(g_sp + (size_t)d * 64 + q * 4);
        spsT[(q*4+0)*16+e] = gs.x; spsT[(q*4+1)*16+e] = gs.y;
        spsT[(q*4+2)*16+e] = gs.z; spsT[(q*4+3)*16+e] = gs.w;
        spsT[(64+q*4+0)*16+e] = gd.x; spsT[(64+q*4+1)*16+e] = gd.y;
        spsT[(64+q*4+2)*16+e] = gd.z; spsT[(64+q*4+3)*16+e] = gd.w;

        {
            float4 p0 = *(const float4*)(g_vp + (size_t)s * 192 + q * 12);
            float4 p1 = *(const float4*)(g_vp + (size_t)s * 192 + q * 12 + 4);
            float4 p2 = *(const float4*)(g_vp + (size_t)s * 192 + q * 12 + 8);
            float pv[12] = {p0.x,p0.y,p0.z,p0.w,p1.x,p1.y,p1.z,p1.w,p2.x,p2.y,p2.z,p2.w};
            #pragma unroll
            for (int r = 0; r < 12; r++) vpsT[(q*12 + r)*16 + e] = pv[r];
        }
        {
            float4 p0 = *(const float4*)(g_vp + (size_t)d * 192 + q * 12);
            float4 p1 = *(const float4*)(g_vp + (size_t)d * 192 + q * 12 + 4);
            float4 p2 = *(const float4*)(g_vp + (size_t)d * 192 + q * 12 + 8);
            float pv[12] = {p0.x,p0.y,p0.z,p0.w,p1.x,p1.y,p1.z,p1.w,p2.x,p2.y,p2.z,p2.w};
            #pragma unroll
            for (int r = 0; r < 12; r++) vpsT[(192 + q*12 + r)*16 + e] = pv[r];
        }
    } else {
        for (int idx = tid - 256; idx < 16 * ROWE; idx += 64) {
            int e = idx / ROWE, i = idx % ROWE;
            eat2[idx] = (i < EAD)
                ? __float2half_rn(edge_attr[(size_t)(e0 + e) * EAD + i])
                : __half(0.f);
        }
    }
    __syncthreads();

    // ---- Phase 2 (tensor): h1 = silu(s0@Ws1+bs1), r1 = silu(ea@Wr1+br1) ----
    {
        const unsigned a0addr = smem_b + OFF_S0*4   + (unsigned)(lane & 15) * (ROWS0*2) + (unsigned)(lane >> 4) * 16;
        const unsigned aeaddr = smem_b + OFF_EAT2*4 + (unsigned)(lane & 15) * (ROWE*2)  + (unsigned)(lane >> 4) * 16;
        for (int nt = wid; nt < 16; nt += 10) {
            float ds[4] = {0.f, 0.f, 0.f, 0.f};
            const __half* bp = g_Ws1t + (nt*8 + g) * KS0 + t*2;
            #pragma unroll
            for (int kt = 0; kt < 12; kt++) {
                uint32_t A0, A1, A2, A3;
                LDMX4(A0, A1, A2, A3, a0addr + kt*32);
                uint32_t b0 = *(const uint32_t*)(bp + kt*16);
                uint32_t b1 = *(const uint32_t*)(bp + kt*16 + 8);
                MMA16816(ds[0], ds[1], ds[2], ds[3], A0, A1, A2, A3, b0, b1);
            }
            float dr[4] = {0.f, 0.f, 0.f, 0.f};
            const __half* bq = g_Wr1t + (nt*8 + g) * 32 + t*2;
            #pragma unroll
            for (int kt = 0; kt < 2; kt++) {
                uint32_t A0, A1, A2, A3;
                LDMX4(A0, A1, A2, A3, aeaddr + kt*32);
                uint32_t b0 = *(const uint32_t*)(bq + kt*16);
                uint32_t b1 = *(const uint32_t*)(bq + kt*16 + 8);
                MMA16816(dr[0], dr[1], dr[2], dr[3], A0, A1, A2, A3, b0, b1);
            }
            float2 bbs = *(const float2*)(bs1 + nt*8 + t*2);
            float2 bbr = *(const float2*)(br1 + nt*8 + t*2);
            *(unsigned*)(h1h + g*ROWH     + nt*8 + t*2) = f2h2(siluf(ds[0]+bbs.x), siluf(ds[1]+bbs.y));
            *(unsigned*)(h1h + (g+8)*ROWH + nt*8 + t*2) = f2h2(siluf(ds[2]+bbs.x), siluf(ds[3]+bbs.y));
            *(unsigned*)(r1h + g*ROWH     + nt*8 + t*2) = f2h2(siluf(dr[0]+bbr.x), siluf(dr[1]+bbr.y));
            *(unsigned*)(r1h + (g+8)*ROWH + nt*8 + t*2) = f2h2(siluf(dr[2]+bbr.x), siluf(dr[3]+bbr.y));
        }
    }
    __syncthreads();

    // ---- Phase 3 (tensor): tp_w = (h1@Ws2+bs2)*(r1@Wr2+br2) ----
    {
        const unsigned aoffs = (unsigned)(lane & 15) * (ROWH*2) + (unsigned)(lane >> 4) * 16;
        const unsigned h1addr = smem_b + OFF_H1*4 + aoffs;
        const unsigned r1addr = smem_b + OFF_R1*4 + aoffs;
        uint32_t A[8][4];
        float dt[2][4], dr[2][4];

        #pragma unroll
        for (int pass = 0; pass < 2; pass++) {
            const int ntb = wid * 4 + pass * 2;
            #pragma unroll
            for (int kt = 0; kt < 8; kt++)
                LDMX4(A[kt][0], A[kt][1], A[kt][2], A[kt][3], h1addr + kt*32);
            #pragma unroll
            for (int q = 0; q < 2; q++) {
                dt[q][0] = dt[q][1] = dt[q][2] = dt[q][3] = 0.f;
                const __half* bp = g_Ws2t + ((ntb + q)*8 + g) * HID + t*2;
                #pragma unroll
                for (int kt = 0; kt < 8; kt++) {
                    uint32_t b0 = *(const uint32_t*)(bp + kt*16);
                    uint32_t b1 = *(const uint32_t*)(bp + kt*16 + 8);
                    MMA16816(dt[q][0], dt[q][1], dt[q][2], dt[q][3],
                             A[kt][0], A[kt][1], A[kt][2], A[kt][3], b0, b1);
                }
            }
            #pragma unroll
            for (int kt = 0; kt < 8; kt++)
                LDMX4(A[kt][0], A[kt][1], A[kt][2], A[kt][3], r1addr + kt*32);
            #pragma unroll
            for (int q = 0; q < 2; q++) {
                dr[q][0] = dr[q][1] = dr[q][2] = dr[q][3] = 0.f;
                const __half* bp = g_Wr2t + ((ntb + q)*8 + g) * HID + t*2;
                #pragma unroll
                for (int kt = 0; kt < 8; kt++) {
                    uint32_t b0 = *(const uint32_t*)(bp + kt*16);
                    uint32_t b1 = *(const uint32_t*)(bp + kt*16 + 8);
                    MMA16816(dr[q][0], dr[q][1], dr[q][2], dr[q][3],
                             A[kt][0], A[kt][1], A[kt][2], A[kt][3], b0, b1);
                }
            }
            #pragma unroll
            for (int q = 0; q < 2; q++) {
                int kv0 = (ntb + q)*8 + t*2;
                float2 bb = *(const float2*)(bs2 + kv0);
                float2 cc = *(const float2*)(br2 + kv0);
                tpwh[kv0*16 + g]         = __float2half_rn((dt[q][0]+bb.x)*(dr[q][0]+cc.x));
                tpwh[(kv0+1)*16 + g]     = __float2half_rn((dt[q][1]+bb.y)*(dr[q][1]+cc.y));
                tpwh[kv0*16 + g + 8]     = __float2half_rn((dt[q][2]+bb.x)*(dr[q][2]+cc.x));
                tpwh[(kv0+1)*16 + g + 8] = __float2half_rn((dt[q][3]+bb.y)*(dr[q][3]+cc.y));
            }
        }
    }
    __syncthreads();

    // ---- Phase 4a: out_v gated -> Vt2[(c*16+e)][u] (half, scaled 1/16) ----
    for (int idx = tid; idx < TE * TPV; idx += BT) {
        int e = idx & 15, u = idx >> 4;
        float vx, vy, vz;
        if (u < 64) {
            float coef = __half2float(tpwh[(64+u)*16+e]) * spsT[u*16+e];
            vx = coef * vpsT[(192 +       u)*16+e];
            vy = coef * vpsT[(192 + 64  + u)*16+e];
            vz = coef * vpsT[(192 + 128 + u)*16+e];
        } else if (u < 128) {
            int uu = u - 64;
            float coef = __half2float(tpwh[(128+uu)*16+e]) * spsT[(64+uu)*16+e];
            vx = coef * vpsT[(      uu)*16+e];
            vy = coef * vpsT[( 64 + uu)*16+e];
            vz = coef * vpsT[(128 + uu)*16+e];
        } else {
            int uu = u - 128;
            float w5 = __half2float(tpwh[(256+uu)*16+e]) * INV_SQRT2;
            float ax = vpsT[uu*16+e],       ay = vpsT[(64+uu)*16+e],  az = vpsT[(128+uu)*16+e];
            float bx = vpsT[(192+uu)*16+e], by = vpsT[(256+uu)*16+e], bz = vpsT[(320+uu)*16+e];
            vx = w5 * (ay*bz - az*by);
            vy = w5 * (az*bx - ax*bz);
            vz = w5 * (ax*by - ay*bx);
        }
        float nrm = sqrtf(vx*vx + vy*vy + vz*vz + 1e-12f);
        float gg = siluf(nrm * gwp[u] + gbp[u]) * VSCALE;
        Vth[(0*16+e)*ROWV + u] = __float2half_rn(vx * gg);
        Vth[(1*16+e)*ROWV + u] = __float2half_rn(vy * gg);
        Vth[(2*16+e)*ROWV + u] = __float2half_rn(vz * gg);
    }

    // ---- Phase 4b: out_s -> outsh[e][j] (half) ----
    for (int idx = tid; idx < TE * TPS; idx += BT) {
        int e = idx & 15, j = idx >> 4;
        float val;
        if (j < 64) {
            val = __half2float(tpwh[j*16+e]) * spsT[j*16+e] * spsT[(64+j)*16+e];
        } else {
            int u = j - 64;
            float dt = vpsT[u*16+e]       * vpsT[(192+u)*16+e]
                     + vpsT[(64+u)*16+e]  * vpsT[(256+u)*16+e]
                     + vpsT[(128+u)*16+e] * vpsT[(320+u)*16+e];
            val = __half2float(tpwh[(192+u)*16+e]) * dt * INV_SQRT3;
        }
        outsh[e*ROWH + j] = __float2half_rn(siluf(val));
    }
    __syncthreads();

    // ---- Phase 5 (tensor): fij_v (24 tiles) + fij_s (8 tiles) over 10 warps ----
    {
        for (int T = wid; T < 32; T += 10) {
            if (T < 24) {
                const int mt = T >> 3, nt = T & 7;   // mt = c
                const unsigned aaddr = smem_b + OFF_VT*4
                    + (unsigned)(mt*16 + (lane & 15)) * (ROWV*2) + (unsigned)(lane >> 4) * 16;
                float dd[4] = {0.f, 0.f, 0.f, 0.f};
                const __half* bp = g_Wpvt + (nt*8 + g) * TPV + t*2;
                #pragma unroll
                for (int kt = 0; kt < 12; kt++) {
                    uint32_t A0, A1, A2, A3;
                    LDMX4(A0, A1, A2, A3, aaddr + kt*32);
                    uint32_t b0 = *(const uint32_t*)(bp + kt*16);
                    uint32_t b1 = *(const uint32_t*)(bp + kt*16 + 8);
                    MMA16816(dd[0], dd[1], dd[2], dd[3], A0, A1, A2, A3, b0, b1);
                }
                const int v0 = nt*8 + t*2;
                size_t o;
                o = (size_t)(e0 + g)     * 256 + 64 + (size_t)v0*3     + mt; out[o] = fij_in[o] + dd[0]*VUNSCALE;
                o = (size_t)(e0 + g)     * 256 + 64 + (size_t)(v0+1)*3 + mt; out[o] = fij_in[o] + dd[1]*VUNSCALE;
                o = (size_t)(e0 + g + 8) * 256 + 64 + (size_t)v0*3     + mt; out[o] = fij_in[o] + dd[2]*VUNSCALE;
                o = (size_t)(e0 + g + 8) * 256 + 64 + (size_t)(v0+1)*3 + mt; out[o] = fij_in[o] + dd[3]*VUNSCALE;
            } else {
                const int nt = T - 24;
                const unsigned aaddr = smem_b + OFF_OUTS*4
                    + (unsigned)(lane & 15) * (ROWH*2) + (unsigned)(lane >> 4) * 16;
                float dd[4] = {0.f, 0.f, 0.f, 0.f};
                const __half* bp = g_Wpst + (nt*8 + g) * TPS + t*2;
                #pragma unroll
                for (int kt = 0; kt < 8; kt++) {
                    uint32_t A0, A1, A2, A3;
                    LDMX4(A0, A1, A2, A3, aaddr + kt*32);
                    uint32_t b0 = *(const uint32_t*)(bp + kt*16);
                    uint32_t b1 = *(const uint32_t*)(bp + kt*16 + 8);
                    MMA16816(dd[0], dd[1], dd[2], dd[3], A0, A1, A2, A3, b0, b1);
                }
                const int v0 = nt*8 + t*2;
                size_t o;
                o = (size_t)(e0 + g)     * 256 + v0;     out[o] = fij_in[o] + dd[0];
                o = (size_t)(e0 + g)     * 256 + v0 + 1; out[o] = fij_in[o] + dd[1];
                o = (size_t)(e0 + g + 8) * 256 + v0;     out[o] = fij_in[o] + dd[2];
                o = (size_t)(e0 + g + 8) * 256 + v0 + 1; out[o] = fij_in[o] + dd[3];
            }
        }
    }
}

// ---------------------------------------------------------------------------
extern "C" void kernel_launch(void* const* d_in, const int* in_sizes, int n_in,
                              void* d_out, int out_size)
{
    const float* x         = (const float*)d_in[0];
    const float* edge_attr = (const float*)d_in[1];
    const float* fij_in    = (const float*)d_in[2];
    const float* W_pre_s   = (const float*)d_in[3];
    const float* b_pre_s   = (const float*)d_in[4];
    const float* W_pre_v   = (const float*)d_in[5];
    const float* gw_pre    = (const float*)d_in[6];
    const float* gb_pre    = (const float*)d_in[7];
    const float* Ws1       = (const float*)d_in[8];
    const float* bs1       = (const float*)d_in[9];
    const float* Ws2       = (const float*)d_in[10];
    const float* bs2       = (const float*)d_in[11];
    const float* Wr1       = (const float*)d_in[12];
    const float* br1       = (const float*)d_in[13];
    const float* Wr2       = (const float*)d_in[14];
    const float* br2       = (const float*)d_in[15];
    const float* gw_post   = (const float*)d_in[16];
    const float* gb_post   = (const float*)d_in[17];
    const float* W_post_s  = (const float*)d_in[18];
    const float* W_post_v  = (const float*)d_in[19];
    const int*   ei        = (const int*)d_in[20];

    const int N = in_sizes[0] / 256;
    const int E = in_sizes[2] / 256;

    node_kernel<<<(N + 3) / 4, 256>>>(x, W_pre_s, b_pre_s, W_pre_v, gw_pre, gb_pre, N);
    wconv_kernel<<<(WN * HID + 255) / 256, 256>>>(Ws1, Wr1, Ws2, Wr2, W_post_v, W_post_s);

    const size_t shm = (size_t)SMEM_FLOATS * 4;   // 66688 B
    cudaFuncSetAttribute(edge_kernel, cudaFuncAttributeMaxDynamicSharedMemorySize, (int)shm);

    edge_kernel<<<E / TE, BT, shm>>>(
        x, edge_attr, fij_in,
        bs1, bs2, br1, br2,
        gw_post, gb_post,
        ei, (float*)d_out, E);
}

// round 13
// speedup vs baseline: 2.5372x; 1.5279x over previous
#include <cuda_runtime.h>
#include <cuda_bf16.h>
#include <cuda_fp16.h>
#include <cstdint>

#define NN 10000
#define NS 64
#define NV 64
#define HID 128
#define WN 320
#define KS0 192
#define EAD 20
#define TPS 128
#define TPV 192

#define TE 16
#define BT 320
#define ROWS0 200   // s0 row pitch (halves)
#define ROWH  136   // h1/r1/outs row pitch
#define ROWE  40    // eat row pitch
#define ROWV  200   // Vt2 row pitch

#define INV_SQRT3 0.5773502691896258f
#define INV_SQRT2 0.7071067811865476f
#define VSCALE    0.0625f
#define VUNSCALE  16.0f

// smem offsets (float units)
#define OFF_S0   0      // half [16][200] (1600 fu) ─┐ region A (4800 fu)
#define OFF_H1   1600   // half [16][136] (1088)     │ Vt2 half [48][200]
#define OFF_R1   2688   // half [16][136] (1088)     │ overlays after ph3
#define OFF_EAT2 3776   // half [16][40]  (320)      │
#define OFF_VT   0      //                           ┘
#define OFF_SPS  4800   // f32 [128][16] (2048)
#define OFF_VPS  6848   // f32 [384][16] (6144)
#define OFF_TPW  12992  // half [320][16] (2560)
#define OFF_OUTS 15552  // half [16][136] (1088)
#define OFF_IDX  16640  // 32 ints
#define SMEM_FLOATS 16672   // 66688 B

// packed weight table sizes (uint4 elements)
#define CNT_W1S (16*12*32)   // 6144
#define CNT_W1R (16*2*32)    // 1024
#define CNT_W2  (40*8*32)    // 10240
#define CNT_W5V (8*12*32)    // 3072
#define CNT_W5S (8*8*32)     // 2048

typedef unsigned long long u64;

__device__ float g_sp[NN * NS];
__device__ float g_vp[NN * 3 * NV];     // [n][c*64+v]
__device__ uint4 g_W1sf[CNT_W1S];       // [nt][kt][lane] {b0h,b1h,b0l,b1l}
__device__ uint4 g_W1rf[CNT_W1R];
__device__ uint4 g_W2sf[CNT_W2];
__device__ uint4 g_W2rf[CNT_W2];
__device__ uint4 g_W5vf[CNT_W5V];
__device__ uint4 g_W5sf[CNT_W5S];

__device__ __forceinline__ float siluf(float x) { return x / (1.0f + __expf(-x)); }
__device__ __forceinline__ unsigned int f2h2(float a, float b) {
    __half2 h = __floats2half2_rn(a, b);
    return *reinterpret_cast<unsigned int*>(&h);
}
#define LDMX4(r0,r1,r2,r3,addr) \
    asm volatile("ldmatrix.sync.aligned.m8n8.x4.shared.b16 {%0,%1,%2,%3}, [%4];" \
        : "=r"(r0), "=r"(r1), "=r"(r2), "=r"(r3) : "r"(addr))
#define MMA16816(d0,d1,d2,d3,a0,a1,a2,a3,b0,b1) \
    asm volatile("mma.sync.aligned.m16n8k16.row.col.f32.f16.f16.f32 " \
        "{%0,%1,%2,%3}, {%4,%5,%6,%7}, {%8,%9}, {%0,%1,%2,%3};" \
        : "+f"(d0), "+f"(d1), "+f"(d2), "+f"(d3) \
        : "r"(a0), "r"(a1), "r"(a2), "r"(a3), "r"(b0), "r"(b1))

// ---------------------------------------------------------------------------
__global__ __launch_bounds__(256) void node_kernel(
    const float* __restrict__ x,
    const float* __restrict__ Wps, const float* __restrict__ bps,
    const float* __restrict__ Wpv,
    const float* __restrict__ gw, const float* __restrict__ gb,
    int N)
{
    __shared__ float sx[4][256];
    const int ln = threadIdx.x >> 6;
    const int v  = threadIdx.x & 63;
    const int n  = blockIdx.x * 4 + ln;

    if (n < N) {
        #pragma unroll
        for (int i = v; i < 256; i += 64) sx[ln][i] = x[n * 256 + i];
    }
    __syncthreads();
    if (n >= N) return;

    const float* xs = sx[ln];
    const float* xv = sx[ln] + 64;

    float sacc = bps[v];
    #pragma unroll 4
    for (int i = 0; i < NS; i++) sacc = fmaf(xs[i], Wps[i * NS + v], sacc);

    float ax = 0.f, ay = 0.f, az = 0.f;
    #pragma unroll 4
    for (int u = 0; u < NV; u++) {
        float w = Wpv[u * NV + v];
        ax = fmaf(xv[u * 3 + 0], w, ax);
        ay = fmaf(xv[u * 3 + 1], w, ay);
        az = fmaf(xv[u * 3 + 2], w, az);
    }
    float nrm = sqrtf(ax * ax + ay * ay + az * az + 1e-12f);
    float g = siluf(nrm * gw[v] + gb[v]);

    g_sp[n * NS + v] = siluf(sacc);
    g_vp[n * 192 + 0 * 64 + v] = ax * g;
    g_vp[n * 192 + 1 * 64 + v] = ay * g;
    g_vp[n * 192 + 2 * 64 + v] = az * g;
}

// ---------------------------------------------------------------------------
// Pack weight element quads (hi+lo fp16 split) in mma-fragment order.
__device__ __forceinline__ uint4 pack_w(const float* W, int ld, int n, int k0, int Kv) {
    float w00 = (k0     < Kv) ? W[(k0)     * ld + n] : 0.f;
    float w01 = (k0 + 1 < Kv) ? W[(k0 + 1) * ld + n] : 0.f;
    float w10 = (k0 + 8 < Kv) ? W[(k0 + 8) * ld + n] : 0.f;
    float w11 = (k0 + 9 < Kv) ? W[(k0 + 9) * ld + n] : 0.f;
    __half h00 = __float2half_rn(w00), h01 = __float2half_rn(w01);
    __half h10 = __float2half_rn(w10), h11 = __float2half_rn(w11);
    __half l00 = __float2half_rn(w00 - __half2float(h00));
    __half l01 = __float2half_rn(w01 - __half2float(h01));
    __half l10 = __float2half_rn(w10 - __half2float(h10));
    __half l11 = __float2half_rn(w11 - __half2float(h11));
    uint4 r;
    __half2 p;
    p = __halves2half2(h00, h01); r.x = *(unsigned*)&p;
    p = __halves2half2(h10, h11); r.y = *(unsigned*)&p;
    p = __halves2half2(l00, l01); r.z = *(unsigned*)&p;
    p = __halves2half2(l10, l11); r.w = *(unsigned*)&p;
    return r;
}

__global__ __launch_bounds__(256) void wconv_kernel(
    const float* __restrict__ Ws1, const float* __restrict__ Wr1,
    const float* __restrict__ Ws2, const float* __restrict__ Wr2,
    const float* __restrict__ Wpv, const float* __restrict__ Wps)
{
    int i = blockIdx.x * 256 + threadIdx.x;
    int lane = i & 31, g = lane >> 2, t = lane & 3;
    if (i < CNT_W1S) {
        int kt = (i >> 5) % 12, nt = i / (12 * 32);
        g_W1sf[i] = pack_w(Ws1, HID, nt*8 + g, kt*16 + t*2, KS0);
    } else if (i < CNT_W1S + CNT_W1R) {
        int j = i - CNT_W1S;
        int kt = (j >> 5) & 1, nt = j / 64;
        g_W1rf[j] = pack_w(Wr1, HID, nt*8 + g, kt*16 + t*2, EAD);
    } else if (i < CNT_W1S + CNT_W1R + CNT_W2) {
        int j = i - (CNT_W1S + CNT_W1R);
        int kt = (j >> 5) & 7, nt = j / 256;
        g_W2sf[j] = pack_w(Ws2, WN, nt*8 + g, kt*16 + t*2, HID);
    } else if (i < CNT_W1S + CNT_W1R + 2*CNT_W2) {
        int j = i - (CNT_W1S + CNT_W1R + CNT_W2);
        int kt = (j >> 5) & 7, nt = j / 256;
        g_W2rf[j] = pack_w(Wr2, WN, nt*8 + g, kt*16 + t*2, HID);
    } else if (i < CNT_W1S + CNT_W1R + 2*CNT_W2 + CNT_W5V) {
        int j = i - (CNT_W1S + CNT_W1R + 2*CNT_W2);
        int kt = (j >> 5) % 12, nt = j / 384;
        g_W5vf[j] = pack_w(Wpv, NV, nt*8 + g, kt*16 + t*2, TPV);
    } else if (i < CNT_W1S + CNT_W1R + 2*CNT_W2 + CNT_W5V + CNT_W5S) {
        int j = i - (CNT_W1S + CNT_W1R + 2*CNT_W2 + CNT_W5V);
        int kt = (j >> 5) & 7, nt = j / 256;
        g_W5sf[j] = pack_w(Wps, NS, nt*8 + g, kt*16 + t*2, TPS);
    }
}

// ---------------------------------------------------------------------------
__global__ __launch_bounds__(BT, 3) void edge_kernel(
    const float* __restrict__ x,
    const float* __restrict__ edge_attr,
    const float* __restrict__ fij_in,
    const float* __restrict__ bs1, const float* __restrict__ bs2,
    const float* __restrict__ br1, const float* __restrict__ br2,
    const float* __restrict__ gwp, const float* __restrict__ gbp,
    const int* __restrict__ ei,
    float* __restrict__ out, int E)
{
    extern __shared__ float sm[];
    __half* s0h   = (__half*)(sm + OFF_S0);    // [16][200]
    __half* h1h   = (__half*)(sm + OFF_H1);    // [16][136]
    __half* r1h   = (__half*)(sm + OFF_R1);    // [16][136]
    __half* eat2  = (__half*)(sm + OFF_EAT2);  // [16][40]
    __half* Vth   = (__half*)(sm + OFF_VT);    // [48][200] after ph3 (scaled 1/16)
    float*  spsT  = sm + OFF_SPS;
    float*  vpsT  = sm + OFF_VPS;
    __half* tpwh  = (__half*)(sm + OFF_TPW);   // [320][16]
    __half* outsh = (__half*)(sm + OFF_OUTS);  // [16][136]
    int*    sidx  = (int*)(sm + OFF_IDX);

    const int tid = threadIdx.x;
    const int e0  = blockIdx.x * TE;
    const unsigned smem_b = (unsigned)__cvta_generic_to_shared(sm);
    const int wid = tid >> 5, lane = tid & 31;
    const int g = lane >> 2, t = lane & 3;

    if (tid < 32) {
        int e = tid & 15;
        sidx[tid] = (tid < 16) ? ei[e0 + e] : ei[E + e0 + e];
    }
    __syncthreads();

    // ---- Phase 1 (tid<256): gather x (s0 -> [e][k] fp16), g_sp, g_vp ----
    if (tid < 256) {
        const int e = tid & 15, q = tid >> 4;
        const int s = sidx[e], d = sidx[TE + e];
        const float* xs = x + (size_t)s * 256;
        const float* xd = x + (size_t)d * 256;

        float4 a = *(const float4*)(xs + q * 4);
        float4 b = *(const float4*)(xd + q * 4);
        *(uint2*)(s0h + e*ROWS0 + q*4)      = make_uint2(f2h2(a.x, a.y), f2h2(a.z, a.w));
        *(uint2*)(s0h + e*ROWS0 + 64 + q*4) = make_uint2(f2h2(b.x, b.y), f2h2(b.z, b.w));

        float4 v0 = *(const float4*)(xs + 64 + q*12);
        float4 v1 = *(const float4*)(xs + 64 + q*12 + 4);
        float4 v2 = *(const float4*)(xs + 64 + q*12 + 8);
        float4 w0 = *(const float4*)(xd + 64 + q*12);
        float4 w1 = *(const float4*)(xd + 64 + q*12 + 4);
        float4 w2 = *(const float4*)(xd + 64 + q*12 + 8);
        float d0 = v0.x*w0.x + v0.y*w0.y + v0.z*w0.z;
        float d1 = v0.w*w0.w + v1.x*w1.x + v1.y*w1.y;
        float d2 = v1.z*w1.z + v1.w*w1.w + v2.x*w2.x;
        float d3 = v2.y*w2.y + v2.z*w2.z + v2.w*w2.w;
        *(uint2*)(s0h + e*ROWS0 + 128 + q*4) = make_uint2(f2h2(d0, d1), f2h2(d2, d3));

        float4 gs = *(const float4*)(g_sp + (size_t)s * 64 + q * 4);
        float4 gd = *(const float4*)(g_sp + (size_t)d * 64 + q * 4);
        spsT[(q*4+0)*16+e] = gs.x; spsT[(q*4+1)*16+e] = gs.y;
        spsT[(q*4+2)*16+e] = gs.z; spsT[(q*4+3)*16+e] = gs.w;
        spsT[(64+q*4+0)*16+e] = gd.x; spsT[(64+q*4+1)*16+e] = gd.y;
        spsT[(64+q*4+2)*16+e] = gd.z; spsT[(64+q*4+3)*16+e] = gd.w;

        {
            float4 p0 = *(const float4*)(g_vp + (size_t)s * 192 + q * 12);
            float4 p1 = *(const float4*)(g_vp + (size_t)s * 192 + q * 12 + 4);
            float4 p2 = *(const float4*)(g_vp + (size_t)s * 192 + q * 12 + 8);
            float pv[12] = {p0.x,p0.y,p0.z,p0.w,p1.x,p1.y,p1.z,p1.w,p2.x,p2.y,p2.z,p2.w};
            #pragma unroll
            for (int r = 0; r < 12; r++) vpsT[(q*12 + r)*16 + e] = pv[r];
        }
        {
            float4 p0 = *(const float4*)(g_vp + (size_t)d * 192 + q * 12);
            float4 p1 = *(const float4*)(g_vp + (size_t)d * 192 + q * 12 + 4);
            float4 p2 = *(const float4*)(g_vp + (size_t)d * 192 + q * 12 + 8);
            float pv[12] = {p0.x,p0.y,p0.z,p0.w,p1.x,p1.y,p1.z,p1.w,p2.x,p2.y,p2.z,p2.w};
            #pragma unroll
            for (int r = 0; r < 12; r++) vpsT[(192 + q*12 + r)*16 + e] = pv[r];
        }
    } else {
        for (int idx = tid - 256; idx < 16 * ROWE; idx += 64) {
            int e = idx / ROWE, i = idx % ROWE;
            eat2[idx] = (i < EAD)
                ? __float2half_rn(edge_attr[(size_t)(e0 + e) * EAD + i])
                : __half(0.f);
        }
    }
    __syncthreads();

    // ---- Phase 2 (tensor, hi/lo): h1 = silu(s0@Ws1+bs1), r1 = silu(ea@Wr1+br1) ----
    {
        const unsigned a0addr = smem_b + OFF_S0*4   + (unsigned)(lane & 15) * (ROWS0*2) + (unsigned)(lane >> 4) * 16;
        const unsigned aeaddr = smem_b + OFF_EAT2*4 + (unsigned)(lane & 15) * (ROWE*2)  + (unsigned)(lane >> 4) * 16;
        for (int nt = wid; nt < 16; nt += 10) {
            float ds[4] = {0.f, 0.f, 0.f, 0.f};
            const uint4* bp = g_W1sf + nt*384 + lane;
            #pragma unroll
            for (int kt = 0; kt < 12; kt++) {
                uint32_t A0, A1, A2, A3;
                LDMX4(A0, A1, A2, A3, a0addr + kt*32);
                uint4 w = bp[kt*32];
                MMA16816(ds[0], ds[1], ds[2], ds[3], A0, A1, A2, A3, w.x, w.y);
                MMA16816(ds[0], ds[1], ds[2], ds[3], A0, A1, A2, A3, w.z, w.w);
            }
            float dr[4] = {0.f, 0.f, 0.f, 0.f};
            const uint4* bq = g_W1rf + nt*64 + lane;
            #pragma unroll
            for (int kt = 0; kt < 2; kt++) {
                uint32_t A0, A1, A2, A3;
                LDMX4(A0, A1, A2, A3, aeaddr + kt*32);
                uint4 w = bq[kt*32];
                MMA16816(dr[0], dr[1], dr[2], dr[3], A0, A1, A2, A3, w.x, w.y);
                MMA16816(dr[0], dr[1], dr[2], dr[3], A0, A1, A2, A3, w.z, w.w);
            }
            float2 bbs = *(const float2*)(bs1 + nt*8 + t*2);
            float2 bbr = *(const float2*)(br1 + nt*8 + t*2);
            *(unsigned*)(h1h + g*ROWH     + nt*8 + t*2) = f2h2(siluf(ds[0]+bbs.x), siluf(ds[1]+bbs.y));
            *(unsigned*)(h1h + (g+8)*ROWH + nt*8 + t*2) = f2h2(siluf(ds[2]+bbs.x), siluf(ds[3]+bbs.y));
            *(unsigned*)(r1h + g*ROWH     + nt*8 + t*2) = f2h2(siluf(dr[0]+bbr.x), siluf(dr[1]+bbr.y));
            *(unsigned*)(r1h + (g+8)*ROWH + nt*8 + t*2) = f2h2(siluf(dr[2]+bbr.x), siluf(dr[3]+bbr.y));
        }
    }
    __syncthreads();

    // ---- Phase 3 (tensor, hi/lo): tp_w = (h1@Ws2+bs2)*(r1@Wr2+br2) ----
    {
        const unsigned aoffs = (unsigned)(lane & 15) * (ROWH*2) + (unsigned)(lane >> 4) * 16;
        const unsigned h1addr = smem_b + OFF_H1*4 + aoffs;
        const unsigned r1addr = smem_b + OFF_R1*4 + aoffs;
        uint32_t A[8][4];
        float dt[2][4], dr[2][4];

        #pragma unroll
        for (int pass = 0; pass < 2; pass++) {
            const int ntb = wid * 4 + pass * 2;
            #pragma unroll
            for (int kt = 0; kt < 8; kt++)
                LDMX4(A[kt][0], A[kt][1], A[kt][2], A[kt][3], h1addr + kt*32);
            #pragma unroll
            for (int q = 0; q < 2; q++) {
                dt[q][0] = dt[q][1] = dt[q][2] = dt[q][3] = 0.f;
                const uint4* bp = g_W2sf + (ntb + q)*256 + lane;
                #pragma unroll
                for (int kt = 0; kt < 8; kt++) {
                    uint4 w = bp[kt*32];
                    MMA16816(dt[q][0], dt[q][1], dt[q][2], dt[q][3],
                             A[kt][0], A[kt][1], A[kt][2], A[kt][3], w.x, w.y);
                    MMA16816(dt[q][0], dt[q][1], dt[q][2], dt[q][3],
                             A[kt][0], A[kt][1], A[kt][2], A[kt][3], w.z, w.w);
                }
            }
            #pragma unroll
            for (int kt = 0; kt < 8; kt++)
                LDMX4(A[kt][0], A[kt][1], A[kt][2], A[kt][3], r1addr + kt*32);
            #pragma unroll
            for (int q = 0; q < 2; q++) {
                dr[q][0] = dr[q][1] = dr[q][2] = dr[q][3] = 0.f;
                const uint4* bp = g_W2rf + (ntb + q)*256 + lane;
                #pragma unroll
                for (int kt = 0; kt < 8; kt++) {
                    uint4 w = bp[kt*32];
                    MMA16816(dr[q][0], dr[q][1], dr[q][2], dr[q][3],
                             A[kt][0], A[kt][1], A[kt][2], A[kt][3], w.x, w.y);
                    MMA16816(dr[q][0], dr[q][1], dr[q][2], dr[q][3],
                             A[kt][0], A[kt][1], A[kt][2], A[kt][3], w.z, w.w);
                }
            }
            #pragma unroll
            for (int q = 0; q < 2; q++) {
                int kv0 = (ntb + q)*8 + t*2;
                float2 bb = *(const float2*)(bs2 + kv0);
                float2 cc = *(const float2*)(br2 + kv0);
                tpwh[kv0*16 + g]         = __float2half_rn((dt[q][0]+bb.x)*(dr[q][0]+cc.x));
                tpwh[(kv0+1)*16 + g]     = __float2half_rn((dt[q][1]+bb.y)*(dr[q][1]+cc.y));
                tpwh[kv0*16 + g + 8]     = __float2half_rn((dt[q][2]+bb.x)*(dr[q][2]+cc.x));
                tpwh[(kv0+1)*16 + g + 8] = __float2half_rn((dt[q][3]+bb.y)*(dr[q][3]+cc.y));
            }
        }
    }
    __syncthreads();

    // ---- Phase 4a: out_v gated -> Vt2[(c*16+e)][u] (half, scaled 1/16) ----
    for (int idx = tid; idx < TE * TPV; idx += BT) {
        int e = idx & 15, u = idx >> 4;
        float vx, vy, vz;
        if (u < 64) {
            float coef = __half2float(tpwh[(64+u)*16+e]) * spsT[u*16+e];
            vx = coef * vpsT[(192 +       u)*16+e];
            vy = coef * vpsT[(192 + 64  + u)*16+e];
            vz = coef * vpsT[(192 + 128 + u)*16+e];
        } else if (u < 128) {
            int uu = u - 64;
            float coef = __half2float(tpwh[(128+uu)*16+e]) * spsT[(64+uu)*16+e];
            vx = coef * vpsT[(      uu)*16+e];
            vy = coef * vpsT[( 64 + uu)*16+e];
            vz = coef * vpsT[(128 + uu)*16+e];
        } else {
            int uu = u - 128;
            float w5 = __half2float(tpwh[(256+uu)*16+e]) * INV_SQRT2;
            float ax = vpsT[uu*16+e],       ay = vpsT[(64+uu)*16+e],  az = vpsT[(128+uu)*16+e];
            float bx = vpsT[(192+uu)*16+e], by = vpsT[(256+uu)*16+e], bz = vpsT[(320+uu)*16+e];
            vx = w5 * (ay*bz - az*by);
            vy = w5 * (az*bx - ax*bz);
            vz = w5 * (ax*by - ay*bx);
        }
        float nrm = sqrtf(vx*vx + vy*vy + vz*vz + 1e-12f);
        float gg = siluf(nrm * gwp[u] + gbp[u]) * VSCALE;
        Vth[(0*16+e)*ROWV + u] = __float2half_rn(vx * gg);
        Vth[(1*16+e)*ROWV + u] = __float2half_rn(vy * gg);
        Vth[(2*16+e)*ROWV + u] = __float2half_rn(vz * gg);
    }

    // ---- Phase 4b: out_s -> outsh[e][j] (half) ----
    for (int idx = tid; idx < TE * TPS; idx += BT) {
        int e = idx & 15, j = idx >> 4;
        float val;
        if (j < 64) {
            val = __half2float(tpwh[j*16+e]) * spsT[j*16+e] * spsT[(64+j)*16+e];
        } else {
            int u = j - 64;
            float dt = vpsT[u*16+e]       * vpsT[(192+u)*16+e]
                     + vpsT[(64+u)*16+e]  * vpsT[(256+u)*16+e]
                     + vpsT[(128+u)*16+e] * vpsT[(320+u)*16+e];
            val = __half2float(tpwh[(192+u)*16+e]) * dt * INV_SQRT3;
        }
        outsh[e*ROWH + j] = __float2half_rn(siluf(val));
    }
    __syncthreads();

    // ---- Phase 5 (tensor, hi/lo): fij_v (24 tiles) + fij_s (8 tiles) ----
    {
        for (int T = wid; T < 32; T += 10) {
            if (T < 24) {
                const int mt = T >> 3, nt = T & 7;   // mt = c
                const unsigned aaddr = smem_b + OFF_VT*4
                    + (unsigned)(mt*16 + (lane & 15)) * (ROWV*2) + (unsigned)(lane >> 4) * 16;
                float dd[4] = {0.f, 0.f, 0.f, 0.f};
                const uint4* bp = g_W5vf + nt*384 + lane;
                #pragma unroll
                for (int kt = 0; kt < 12; kt++) {
                    uint32_t A0, A1, A2, A3;
                    LDMX4(A0, A1, A2, A3, aaddr + kt*32);
                    uint4 w = bp[kt*32];
                    MMA16816(dd[0], dd[1], dd[2], dd[3], A0, A1, A2, A3, w.x, w.y);
                    MMA16816(dd[0], dd[1], dd[2], dd[3], A0, A1, A2, A3, w.z, w.w);
                }
                const int v0 = nt*8 + t*2;
                size_t o;
                o = (size_t)(e0 + g)     * 256 + 64 + (size_t)v0*3     + mt; out[o] = fij_in[o] + dd[0]*VUNSCALE;
                o = (size_t)(e0 + g)     * 256 + 64 + (size_t)(v0+1)*3 + mt; out[o] = fij_in[o] + dd[1]*VUNSCALE;
                o = (size_t)(e0 + g + 8) * 256 + 64 + (size_t)v0*3     + mt; out[o] = fij_in[o] + dd[2]*VUNSCALE;
                o = (size_t)(e0 + g + 8) * 256 + 64 + (size_t)(v0+1)*3 + mt; out[o] = fij_in[o] + dd[3]*VUNSCALE;
            } else {
                const int nt = T - 24;
                const unsigned aaddr = smem_b + OFF_OUTS*4
                    + (unsigned)(lane & 15) * (ROWH*2) + (unsigned)(lane >> 4) * 16;
                float dd[4] = {0.f, 0.f, 0.f, 0.f};
                const uint4* bp = g_W5sf + nt*256 + lane;
                #pragma unroll
                for (int kt = 0; kt < 8; kt++) {
                    uint32_t A0, A1, A2, A3;
                    LDMX4(A0, A1, A2, A3, aaddr + kt*32);
                    uint4 w = bp[kt*32];
                    MMA16816(dd[0], dd[1], dd[2], dd[3], A0, A1, A2, A3, w.x, w.y);
                    MMA16816(dd[0], dd[1], dd[2], dd[3], A0, A1, A2, A3, w.z, w.w);
                }
                const int v0 = nt*8 + t*2;
                size_t o;
                o = (size_t)(e0 + g)     * 256 + v0;     out[o] = fij_in[o] + dd[0];
                o = (size_t)(e0 + g)     * 256 + v0 + 1; out[o] = fij_in[o] + dd[1];
                o = (size_t)(e0 + g + 8) * 256 + v0;     out[o] = fij_in[o] + dd[2];
                o = (size_t)(e0 + g + 8) * 256 + v0 + 1; out[o] = fij_in[o] + dd[3];
            }
        }
    }
}

// ---------------------------------------------------------------------------
extern "C" void kernel_launch(void* const* d_in, const int* in_sizes, int n_in,
                              void* d_out, int out_size)
{
    const float* x         = (const float*)d_in[0];
    const float* edge_attr = (const float*)d_in[1];
    const float* fij_in    = (const float*)d_in[2];
    const float* W_pre_s   = (const float*)d_in[3];
    const float* b_pre_s   = (const float*)d_in[4];
    const float* W_pre_v   = (const float*)d_in[5];
    const float* gw_pre    = (const float*)d_in[6];
    const float* gb_pre    = (const float*)d_in[7];
    const float* Ws1       = (const float*)d_in[8];
    const float* bs1       = (const float*)d_in[9];
    const float* Ws2       = (const float*)d_in[10];
    const float* bs2       = (const float*)d_in[11];
    const float* Wr1       = (const float*)d_in[12];
    const float* br1       = (const float*)d_in[13];
    const float* Wr2       = (const float*)d_in[14];
    const float* br2       = (const float*)d_in[15];
    const float* gw_post   = (const float*)d_in[16];
    const float* gb_post   = (const float*)d_in[17];
    const float* W_post_s  = (const float*)d_in[18];
    const float* W_post_v  = (const float*)d_in[19];
    const int*   ei        = (const int*)d_in[20];

    const int N = in_sizes[0] / 256;
    const int E = in_sizes[2] / 256;

    node_kernel<<<(N + 3) / 4, 256>>>(x, W_pre_s, b_pre_s, W_pre_v, gw_pre, gb_pre, N);

    const int total_w = CNT_W1S + CNT_W1R + 2*CNT_W2 + CNT_W5V + CNT_W5S;
    wconv_kernel<<<(total_w + 255) / 256, 256>>>(Ws1, Wr1, Ws2, Wr2, W_post_v, W_post_s);

    const size_t shm = (size_t)SMEM_FLOATS * 4;   // 66688 B
    cudaFuncSetAttribute(edge_kernel, cudaFuncAttributeMaxDynamicSharedMemorySize, (int)shm);

    edge_kernel<<<E / TE, BT, shm>>>(
        x, edge_attr, fij_in,
        bs1, bs2, br1, br2,
        gw_post, gb_post,
        ei, (float*)d_out, E);
}

// round 14
// speedup vs baseline: 2.7720x; 1.0925x over previous
#include <cuda_runtime.h>
#include <cuda_bf16.h>
#include <cuda_fp16.h>
#include <cstdint>

#define NN 10000
#define NS 64
#define NV 64
#define HID 128
#define WN 320
#define KS0 192
#define EAD 20
#define TPS 128
#define TPV 192

#define TE 32
#define BT 320
#define ROWS0 200   // s0 row pitch (halves)
#define ROWH  136   // h1/r1/outs row pitch
#define ROWE  40    // eat row pitch
#define ROWV  200   // Vt row pitch
#define ROWT  328   // tpw row pitch [e][kv]

#define INV_SQRT3 0.5773502691896258f
#define INV_SQRT2 0.7071067811865476f
#define VSCALE    0.0625f
#define VUNSCALE  16.0f

// smem offsets (float units)
#define OFF_S0   0      // half [32][200] (3200 fu) ─┐ region A (9600 fu)
#define OFF_H1   3200   // half [32][136] (2176)     │ Vt half [96][200]
#define OFF_R1   5376   // half [32][136] (2176)     │ overlays after ph3
#define OFF_EAT2 7552   // half [32][40]  (640)      │
#define OFF_VT   0      //                           ┘
#define OFF_TPW  9600   // half [32][328] (5248)
#define OFF_OUTS 14848  // half [32][136] (2176)
#define OFF_IDX  17024  // 64 ints
#define SMEM_FLOATS 17088   // 68352 B

// packed weight table sizes (uint4 elements), layout [nt][kt][lane]
#define CNT_W1S (16*12*32)
#define CNT_W1R (16*2*32)
#define CNT_W2  (40*8*32)
#define CNT_W5V (8*12*32)
#define CNT_W5S (8*8*32)

typedef unsigned long long u64;

__device__ float g_sp[NN * NS];
__device__ float g_vp[NN * 3 * NV];     // [n][c*64+v]
__device__ uint4 g_W1sf[CNT_W1S];
__device__ uint4 g_W1rf[CNT_W1R];
__device__ uint4 g_W2sf[CNT_W2];
__device__ uint4 g_W2rf[CNT_W2];
__device__ uint4 g_W5vf[CNT_W5V];
__device__ uint4 g_W5sf[CNT_W5S];

__device__ __forceinline__ float siluf(float x) { return x / (1.0f + __expf(-x)); }
__device__ __forceinline__ unsigned int f2h2(float a, float b) {
    __half2 h = __floats2half2_rn(a, b);
    return *reinterpret_cast<unsigned int*>(&h);
}
#define LDMX4(r0,r1,r2,r3,addr) \
    asm volatile("ldmatrix.sync.aligned.m8n8.x4.shared.b16 {%0,%1,%2,%3}, [%4];" \
        : "=r"(r0), "=r"(r1), "=r"(r2), "=r"(r3) : "r"(addr))
#define MMA16816(d0,d1,d2,d3,a0,a1,a2,a3,b0,b1) \
    asm volatile("mma.sync.aligned.m16n8k16.row.col.f32.f16.f16.f32 " \
        "{%0,%1,%2,%3}, {%4,%5,%6,%7}, {%8,%9}, {%0,%1,%2,%3};" \
        : "+f"(d0), "+f"(d1), "+f"(d2), "+f"(d3) \
        : "r"(a0), "r"(a1), "r"(a2), "r"(a3), "r"(b0), "r"(b1))

// ---------------------------------------------------------------------------
__global__ __launch_bounds__(256) void node_kernel(
    const float* __restrict__ x,
    const float* __restrict__ Wps, const float* __restrict__ bps,
    const float* __restrict__ Wpv,
    const float* __restrict__ gw, const float* __restrict__ gb,
    int N)
{
    __shared__ float sx[4][256];
    const int ln = threadIdx.x >> 6;
    const int v  = threadIdx.x & 63;
    const int n  = blockIdx.x * 4 + ln;

    if (n < N) {
        #pragma unroll
        for (int i = v; i < 256; i += 64) sx[ln][i] = x[n * 256 + i];
    }
    __syncthreads();
    if (n >= N) return;

    const float* xs = sx[ln];
    const float* xv = sx[ln] + 64;

    float sacc = bps[v];
    #pragma unroll 4
    for (int i = 0; i < NS; i++) sacc = fmaf(xs[i], Wps[i * NS + v], sacc);

    float ax = 0.f, ay = 0.f, az = 0.f;
    #pragma unroll 4
    for (int u = 0; u < NV; u++) {
        float w = Wpv[u * NV + v];
        ax = fmaf(xv[u * 3 + 0], w, ax);
        ay = fmaf(xv[u * 3 + 1], w, ay);
        az = fmaf(xv[u * 3 + 2], w, az);
    }
    float nrm = sqrtf(ax * ax + ay * ay + az * az + 1e-12f);
    float g = siluf(nrm * gw[v] + gb[v]);

    g_sp[n * NS + v] = siluf(sacc);
    g_vp[n * 192 + 0 * 64 + v] = ax * g;
    g_vp[n * 192 + 1 * 64 + v] = ay * g;
    g_vp[n * 192 + 2 * 64 + v] = az * g;
}

// ---------------------------------------------------------------------------
__device__ __forceinline__ uint4 pack_w(const float* W, int ld, int n, int k0, int Kv) {
    float w00 = (k0     < Kv) ? W[(k0)     * ld + n] : 0.f;
    float w01 = (k0 + 1 < Kv) ? W[(k0 + 1) * ld + n] : 0.f;
    float w10 = (k0 + 8 < Kv) ? W[(k0 + 8) * ld + n] : 0.f;
    float w11 = (k0 + 9 < Kv) ? W[(k0 + 9) * ld + n] : 0.f;
    __half h00 = __float2half_rn(w00), h01 = __float2half_rn(w01);
    __half h10 = __float2half_rn(w10), h11 = __float2half_rn(w11);
    __half l00 = __float2half_rn(w00 - __half2float(h00));
    __half l01 = __float2half_rn(w01 - __half2float(h01));
    __half l10 = __float2half_rn(w10 - __half2float(h10));
    __half l11 = __float2half_rn(w11 - __half2float(h11));
    uint4 r;
    __half2 p;
    p = __halves2half2(h00, h01); r.x = *(unsigned*)&p;
    p = __halves2half2(h10, h11); r.y = *(unsigned*)&p;
    p = __halves2half2(l00, l01); r.z = *(unsigned*)&p;
    p = __halves2half2(l10, l11); r.w = *(unsigned*)&p;
    return r;
}

__global__ __launch_bounds__(256) void wconv_kernel(
    const float* __restrict__ Ws1, const float* __restrict__ Wr1,
    const float* __restrict__ Ws2, const float* __restrict__ Wr2,
    const float* __restrict__ Wpv, const float* __restrict__ Wps)
{
    int i = blockIdx.x * 256 + threadIdx.x;
    int lane = i & 31, g = lane >> 2, t = lane & 3;
    if (i < CNT_W1S) {
        int kt = (i >> 5) % 12, nt = i / (12 * 32);
        g_W1sf[i] = pack_w(Ws1, HID, nt*8 + g, kt*16 + t*2, KS0);
    } else if (i < CNT_W1S + CNT_W1R) {
        int j = i - CNT_W1S;
        int kt = (j >> 5) & 1, nt = j / 64;
        g_W1rf[j] = pack_w(Wr1, HID, nt*8 + g, kt*16 + t*2, EAD);
    } else if (i < CNT_W1S + CNT_W1R + CNT_W2) {
        int j = i - (CNT_W1S + CNT_W1R);
        int kt = (j >> 5) & 7, nt = j / 256;
        g_W2sf[j] = pack_w(Ws2, WN, nt*8 + g, kt*16 + t*2, HID);
    } else if (i < CNT_W1S + CNT_W1R + 2*CNT_W2) {
        int j = i - (CNT_W1S + CNT_W1R + CNT_W2);
        int kt = (j >> 5) & 7, nt = j / 256;
        g_W2rf[j] = pack_w(Wr2, WN, nt*8 + g, kt*16 + t*2, HID);
    } else if (i < CNT_W1S + CNT_W1R + 2*CNT_W2 + CNT_W5V) {
        int j = i - (CNT_W1S + CNT_W1R + 2*CNT_W2);
        int kt = (j >> 5) % 12, nt = j / 384;
        g_W5vf[j] = pack_w(Wpv, NV, nt*8 + g, kt*16 + t*2, TPV);
    } else if (i < CNT_W1S + CNT_W1R + 2*CNT_W2 + CNT_W5V + CNT_W5S) {
        int j = i - (CNT_W1S + CNT_W1R + 2*CNT_W2 + CNT_W5V);
        int kt = (j >> 5) & 7, nt = j / 256;
        g_W5sf[j] = pack_w(Wps, NS, nt*8 + g, kt*16 + t*2, TPS);
    }
}

// ---------------------------------------------------------------------------
__global__ __launch_bounds__(BT, 3) void edge_kernel(
    const float* __restrict__ x,
    const float* __restrict__ edge_attr,
    const float* __restrict__ fij_in,
    const float* __restrict__ bs1, const float* __restrict__ bs2,
    const float* __restrict__ br1, const float* __restrict__ br2,
    const float* __restrict__ gwp, const float* __restrict__ gbp,
    const int* __restrict__ ei,
    float* __restrict__ out, int E)
{
    extern __shared__ float sm[];
    __half* s0h   = (__half*)(sm + OFF_S0);    // [32][200]
    __half* h1h   = (__half*)(sm + OFF_H1);    // [32][136]
    __half* r1h   = (__half*)(sm + OFF_R1);    // [32][136]
    __half* eat2  = (__half*)(sm + OFF_EAT2);  // [32][40]
    __half* Vth   = (__half*)(sm + OFF_VT);    // [96][200] after ph3 (scaled 1/16)
    __half* tpwh  = (__half*)(sm + OFF_TPW);   // [32][328]
    __half* outsh = (__half*)(sm + OFF_OUTS);  // [32][136]
    int*    sidx  = (int*)(sm + OFF_IDX);      // [64]

    const int tid = threadIdx.x;
    const int e0  = blockIdx.x * TE;
    const unsigned smem_b = (unsigned)__cvta_generic_to_shared(sm);
    const int wid = tid >> 5, lane = tid & 31;
    const int g = lane >> 2, t = lane & 3;

    if (tid < 64) {
        int e = tid & 31;
        sidx[tid] = (tid < 32) ? ei[e0 + e] : ei[E + e0 + e];
    }
    __syncthreads();

    // ---- Phase 1: gather x -> s0h[e][k] fp16 (32 edges); eat ----
    for (int idx = tid; idx < 512; idx += BT) {
        const int e = idx & 31, q = idx >> 5;   // q 0..15
        const int s = sidx[e], d = sidx[32 + e];
        const float* xs = x + (size_t)s * 256;
        const float* xd = x + (size_t)d * 256;

        float4 a = *(const float4*)(xs + q * 4);
        float4 b = *(const float4*)(xd + q * 4);
        *(uint2*)(s0h + e*ROWS0 + q*4)      = make_uint2(f2h2(a.x, a.y), f2h2(a.z, a.w));
        *(uint2*)(s0h + e*ROWS0 + 64 + q*4) = make_uint2(f2h2(b.x, b.y), f2h2(b.z, b.w));

        float4 v0 = *(const float4*)(xs + 64 + q*12);
        float4 v1 = *(const float4*)(xs + 64 + q*12 + 4);
        float4 v2 = *(const float4*)(xs + 64 + q*12 + 8);
        float4 w0 = *(const float4*)(xd + 64 + q*12);
        float4 w1 = *(const float4*)(xd + 64 + q*12 + 4);
        float4 w2 = *(const float4*)(xd + 64 + q*12 + 8);
        float d0 = v0.x*w0.x + v0.y*w0.y + v0.z*w0.z;
        float d1 = v0.w*w0.w + v1.x*w1.x + v1.y*w1.y;
        float d2 = v1.z*w1.z + v1.w*w1.w + v2.x*w2.x;
        float d3 = v2.y*w2.y + v2.z*w2.z + v2.w*w2.w;
        *(uint2*)(s0h + e*ROWS0 + 128 + q*4) = make_uint2(f2h2(d0, d1), f2h2(d2, d3));
    }
    for (int idx = tid; idx < 32 * ROWE; idx += BT) {
        int e = idx / ROWE, i = idx % ROWE;
        eat2[idx] = (i < EAD)
            ? __float2half_rn(edge_attr[(size_t)(e0 + e) * EAD + i])
            : __half(0.f);
    }
    __syncthreads();

    // ---- Phase 2 (tensor): h1/r1 for 32 edges; B shared across 2 m-tiles ----
    {
        const unsigned a0b = smem_b + OFF_S0*4   + (unsigned)(lane & 15) * (ROWS0*2) + (unsigned)(lane >> 4) * 16;
        const unsigned aeb = smem_b + OFF_EAT2*4 + (unsigned)(lane & 15) * (ROWE*2)  + (unsigned)(lane >> 4) * 16;
        for (int nt = wid; nt < 16; nt += 10) {
            float ds[2][4] = {{0,0,0,0},{0,0,0,0}};
            const uint4* bp = g_W1sf + nt*384 + lane;
            #pragma unroll
            for (int ktb = 0; ktb < 3; ktb++) {
                uint4 w[4];
                #pragma unroll
                for (int j = 0; j < 4; j++) w[j] = bp[(ktb*4 + j)*32];
                #pragma unroll
                for (int m = 0; m < 2; m++) {
                    const unsigned ab = a0b + (unsigned)(m*16) * (ROWS0*2);
                    #pragma unroll
                    for (int j = 0; j < 4; j++) {
                        uint32_t A0, A1, A2, A3;
                        LDMX4(A0, A1, A2, A3, ab + (ktb*4 + j)*32);
                        MMA16816(ds[m][0], ds[m][1], ds[m][2], ds[m][3], A0, A1, A2, A3, w[j].x, w[j].y);
                        MMA16816(ds[m][0], ds[m][1], ds[m][2], ds[m][3], A0, A1, A2, A3, w[j].z, w[j].w);
                    }
                }
            }
            float dr[2][4] = {{0,0,0,0},{0,0,0,0}};
            const uint4* bq = g_W1rf + nt*64 + lane;
            {
                uint4 w0 = bq[0], w1 = bq[32];
                #pragma unroll
                for (int m = 0; m < 2; m++) {
                    const unsigned ab = aeb + (unsigned)(m*16) * (ROWE*2);
                    uint32_t A0, A1, A2, A3;
                    LDMX4(A0, A1, A2, A3, ab);
                    MMA16816(dr[m][0], dr[m][1], dr[m][2], dr[m][3], A0, A1, A2, A3, w0.x, w0.y);
                    MMA16816(dr[m][0], dr[m][1], dr[m][2], dr[m][3], A0, A1, A2, A3, w0.z, w0.w);
                    LDMX4(A0, A1, A2, A3, ab + 32);
                    MMA16816(dr[m][0], dr[m][1], dr[m][2], dr[m][3], A0, A1, A2, A3, w1.x, w1.y);
                    MMA16816(dr[m][0], dr[m][1], dr[m][2], dr[m][3], A0, A1, A2, A3, w1.z, w1.w);
                }
            }
            float2 bbs = *(const float2*)(bs1 + nt*8 + t*2);
            float2 bbr = *(const float2*)(br1 + nt*8 + t*2);
            #pragma unroll
            for (int m = 0; m < 2; m++) {
                int eL = m*16 + g, eH = eL + 8;
                *(unsigned*)(h1h + eL*ROWH + nt*8 + t*2) = f2h2(siluf(ds[m][0]+bbs.x), siluf(ds[m][1]+bbs.y));
                *(unsigned*)(h1h + eH*ROWH + nt*8 + t*2) = f2h2(siluf(ds[m][2]+bbs.x), siluf(ds[m][3]+bbs.y));
                *(unsigned*)(r1h + eL*ROWH + nt*8 + t*2) = f2h2(siluf(dr[m][0]+bbr.x), siluf(dr[m][1]+bbr.y));
                *(unsigned*)(r1h + eH*ROWH + nt*8 + t*2) = f2h2(siluf(dr[m][2]+bbr.x), siluf(dr[m][3]+bbr.y));
            }
        }
    }
    __syncthreads();

    // ---- Phase 3 (tensor): tp_w; 40 nt over 10 warps; B shared across 2 m ----
    {
        const unsigned h1b = smem_b + OFF_H1*4 + (unsigned)(lane & 15) * (ROWH*2) + (unsigned)(lane >> 4) * 16;
        const unsigned r1b = smem_b + OFF_R1*4 + (unsigned)(lane & 15) * (ROWH*2) + (unsigned)(lane >> 4) * 16;
        #pragma unroll
        for (int p = 0; p < 4; p++) {
            const int nt = wid*4 + p;
            float at[2][4] = {{0,0,0,0},{0,0,0,0}};
            float ar[2][4] = {{0,0,0,0},{0,0,0,0}};
            const uint4* bsp = g_W2sf + nt*256 + lane;
            const uint4* brp = g_W2rf + nt*256 + lane;
            #pragma unroll
            for (int ktb = 0; ktb < 2; ktb++) {
                uint4 w[4];
                #pragma unroll
                for (int j = 0; j < 4; j++) w[j] = bsp[(ktb*4 + j)*32];
                #pragma unroll
                for (int m = 0; m < 2; m++) {
                    const unsigned ab = h1b + (unsigned)(m*16) * (ROWH*2);
                    #pragma unroll
                    for (int j = 0; j < 4; j++) {
                        uint32_t A0, A1, A2, A3;
                        LDMX4(A0, A1, A2, A3, ab + (ktb*4 + j)*32);
                        MMA16816(at[m][0], at[m][1], at[m][2], at[m][3], A0, A1, A2, A3, w[j].x, w[j].y);
                        MMA16816(at[m][0], at[m][1], at[m][2], at[m][3], A0, A1, A2, A3, w[j].z, w[j].w);
                    }
                }
            }
            #pragma unroll
            for (int ktb = 0; ktb < 2; ktb++) {
                uint4 w[4];
                #pragma unroll
                for (int j = 0; j < 4; j++) w[j] = brp[(ktb*4 + j)*32];
                #pragma unroll
                for (int m = 0; m < 2; m++) {
                    const unsigned ab = r1b + (unsigned)(m*16) * (ROWH*2);
                    #pragma unroll
                    for (int j = 0; j < 4; j++) {
                        uint32_t A0, A1, A2, A3;
                        LDMX4(A0, A1, A2, A3, ab + (ktb*4 + j)*32);
                        MMA16816(ar[m][0], ar[m][1], ar[m][2], ar[m][3], A0, A1, A2, A3, w[j].x, w[j].y);
                        MMA16816(ar[m][0], ar[m][1], ar[m][2], ar[m][3], A0, A1, A2, A3, w[j].z, w[j].w);
                    }
                }
            }
            const int kv0 = nt*8 + t*2;
            float2 bb = *(const float2*)(bs2 + kv0);
            float2 cc = *(const float2*)(br2 + kv0);
            #pragma unroll
            for (int m = 0; m < 2; m++) {
                int eL = m*16 + g, eH = eL + 8;
                *(unsigned*)(tpwh + eL*ROWT + kv0) =
                    f2h2((at[m][0]+bb.x)*(ar[m][0]+cc.x), (at[m][1]+bb.y)*(ar[m][1]+cc.y));
                *(unsigned*)(tpwh + eH*ROWT + kv0) =
                    f2h2((at[m][2]+bb.x)*(ar[m][2]+cc.x), (at[m][3]+bb.y)*(ar[m][3]+cc.y));
            }
        }
    }
    __syncthreads();

    // ---- Phase 4a: out_v gated -> Vth[(c*32+e)][u]; g_sp/g_vp from L2 ----
    for (int idx = tid; idx < TE * TPV; idx += BT) {
        const int e = idx / TPV, u = idx - e * TPV;
        const int s = sidx[e], d = sidx[32 + e];
        float vx, vy, vz;
        if (u < 64) {
            float coef = __half2float(tpwh[e*ROWT + 64 + u]) * g_sp[(size_t)s*64 + u];
            const float* vp = g_vp + (size_t)d * 192;
            vx = coef * vp[u]; vy = coef * vp[64 + u]; vz = coef * vp[128 + u];
        } else if (u < 128) {
            int uu = u - 64;
            float coef = __half2float(tpwh[e*ROWT + 128 + uu]) * g_sp[(size_t)d*64 + uu];
            const float* vp = g_vp + (size_t)s * 192;
            vx = coef * vp[uu]; vy = coef * vp[64 + uu]; vz = coef * vp[128 + uu];
        } else {
            int uu = u - 128;
            float w5 = __half2float(tpwh[e*ROWT + 256 + uu]) * INV_SQRT2;
            const float* va = g_vp + (size_t)s * 192;
            const float* vb = g_vp + (size_t)d * 192;
            float ax = va[uu], ay = va[64 + uu], az = va[128 + uu];
            float bx = vb[uu], by = vb[64 + uu], bz = vb[128 + uu];
            vx = w5 * (ay*bz - az*by);
            vy = w5 * (az*bx - ax*bz);
            vz = w5 * (ax*by - ay*bx);
        }
        float nrm = sqrtf(vx*vx + vy*vy + vz*vz + 1e-12f);
        float gg = siluf(nrm * gwp[u] + gbp[u]) * VSCALE;
        Vth[(0*32 + e)*ROWV + u] = __float2half_rn(vx * gg);
        Vth[(1*32 + e)*ROWV + u] = __float2half_rn(vy * gg);
        Vth[(2*32 + e)*ROWV + u] = __float2half_rn(vz * gg);
    }

    // ---- Phase 4b: out_s -> outsh[e][j] ----
    for (int idx = tid; idx < TE * TPS; idx += BT) {
        const int e = idx >> 7, j = idx & 127;
        const int s = sidx[e], d = sidx[32 + e];
        float val;
        if (j < 64) {
            val = __half2float(tpwh[e*ROWT + j]) * g_sp[(size_t)s*64 + j] * g_sp[(size_t)d*64 + j];
        } else {
            int u = j - 64;
            const float* va = g_vp + (size_t)s * 192;
            const float* vb = g_vp + (size_t)d * 192;
            float dt = va[u]*vb[u] + va[64+u]*vb[64+u] + va[128+u]*vb[128+u];
            val = __half2float(tpwh[e*ROWT + 192 + u]) * dt * INV_SQRT3;
        }
        outsh[e*ROWH + j] = __float2half_rn(siluf(val));
    }
    __syncthreads();

    // ---- Phase 5 (tensor): warps 0-7 -> fij_v (nt=wid, 6 m); 8-9 -> fij_s ----
    if (wid < 8) {
        const int nt = wid;
        const uint4* bp = g_W5vf + nt*384 + lane;
        #pragma unroll
        for (int ch = 0; ch < 2; ch++) {
            float acc[3][4] = {{0,0,0,0},{0,0,0,0},{0,0,0,0}};
            #pragma unroll
            for (int ktb = 0; ktb < 3; ktb++) {
                uint4 w[4];
                #pragma unroll
                for (int j = 0; j < 4; j++) w[j] = bp[(ktb*4 + j)*32];
                #pragma unroll
                for (int mm = 0; mm < 3; mm++) {
                    const int m = ch*3 + mm;
                    const unsigned ab = smem_b + OFF_VT*4
                        + (unsigned)(m*16 + (lane & 15)) * (ROWV*2) + (unsigned)(lane >> 4) * 16;
                    #pragma unroll
                    for (int j = 0; j < 4; j++) {
                        uint32_t A0, A1, A2, A3;
                        LDMX4(A0, A1, A2, A3, ab + (ktb*4 + j)*32);
                        MMA16816(acc[mm][0], acc[mm][1], acc[mm][2], acc[mm][3], A0, A1, A2, A3, w[j].x, w[j].y);
                        MMA16816(acc[mm][0], acc[mm][1], acc[mm][2], acc[mm][3], A0, A1, A2, A3, w[j].z, w[j].w);
                    }
                }
            }
            const int v0 = nt*8 + t*2;
            #pragma unroll
            for (int mm = 0; mm < 3; mm++) {
                const int m = ch*3 + mm;
                const int c  = m >> 1;
                const int eb = (m & 1) * 16;
                size_t o;
                o = (size_t)(e0 + eb + g)     * 256 + 64 + (size_t)v0*3     + c; out[o] = fij_in[o] + acc[mm][0]*VUNSCALE;
                o = (size_t)(e0 + eb + g)     * 256 + 64 + (size_t)(v0+1)*3 + c; out[o] = fij_in[o] + acc[mm][1]*VUNSCALE;
                o = (size_t)(e0 + eb + g + 8) * 256 + 64 + (size_t)v0*3     + c; out[o] = fij_in[o] + acc[mm][2]*VUNSCALE;
                o = (size_t)(e0 + eb + g + 8) * 256 + 64 + (size_t)(v0+1)*3 + c; out[o] = fij_in[o] + acc[mm][3]*VUNSCALE;
            }
        }
    } else {
        #pragma unroll
        for (int p = 0; p < 4; p++) {
            const int nt = (wid - 8)*4 + p;
            const uint4* bp = g_W5sf + nt*256 + lane;
            float acc[2][4] = {{0,0,0,0},{0,0,0,0}};
            #pragma unroll
            for (int ktb = 0; ktb < 2; ktb++) {
                uint4 w[4];
                #pragma unroll
                for (int j = 0; j < 4; j++) w[j] = bp[(ktb*4 + j)*32];
                #pragma unroll
                for (int m = 0; m < 2; m++) {
                    const unsigned ab = smem_b + OFF_OUTS*4
                        + (unsigned)(m*16 + (lane & 15)) * (ROWH*2) + (unsigned)(lane >> 4) * 16;
                    #pragma unroll
                    for (int j = 0; j < 4; j++) {
                        uint32_t A0, A1, A2, A3;
                        LDMX4(A0, A1, A2, A3, ab + (ktb*4 + j)*32);
                        MMA16816(acc[m][0], acc[m][1], acc[m][2], acc[m][3], A0, A1, A2, A3, w[j].x, w[j].y);
                        MMA16816(acc[m][0], acc[m][1], acc[m][2], acc[m][3], A0, A1, A2, A3, w[j].z, w[j].w);
                    }
                }
            }
            const int v0 = nt*8 + t*2;
            #pragma unroll
            for (int m = 0; m < 2; m++) {
                const int eb = m*16;
                size_t o;
                o = (size_t)(e0 + eb + g)     * 256 + v0;     out[o] = fij_in[o] + acc[m][0];
                o = (size_t)(e0 + eb + g)     * 256 + v0 + 1; out[o] = fij_in[o] + acc[m][1];
                o = (size_t)(e0 + eb + g + 8) * 256 + v0;     out[o] = fij_in[o] + acc[m][2];
                o = (size_t)(e0 + eb + g + 8) * 256 + v0 + 1; out[o] = fij_in[o] + acc[m][3];
            }
        }
    }
}

// ---------------------------------------------------------------------------
extern "C" void kernel_launch(void* const* d_in, const int* in_sizes, int n_in,
                              void* d_out, int out_size)
{
    const float* x         = (const float*)d_in[0];
    const float* edge_attr = (const float*)d_in[1];
    const float* fij_in    = (const float*)d_in[2];
    const float* W_pre_s   = (const float*)d_in[3];
    const float* b_pre_s   = (const float*)d_in[4];
    const float* W_pre_v   = (const float*)d_in[5];
    const float* gw_pre    = (const float*)d_in[6];
    const float* gb_pre    = (const float*)d_in[7];
    const float* Ws1       = (const float*)d_in[8];
    const float* bs1       = (const float*)d_in[9];
    const float* Ws2       = (const float*)d_in[10];
    const float* bs2       = (const float*)d_in[11];
    const float* Wr1       = (const float*)d_in[12];
    const float* br1       = (const float*)d_in[13];
    const float* Wr2       = (const float*)d_in[14];
    const float* br2       = (const float*)d_in[15];
    const float* gw_post   = (const float*)d_in[16];
    const float* gb_post   = (const float*)d_in[17];
    const float* W_post_s  = (const float*)d_in[18];
    const float* W_post_v  = (const float*)d_in[19];
    const int*   ei        = (const int*)d_in[20];

    const int N = in_sizes[0] / 256;
    const int E = in_sizes[2] / 256;

    node_kernel<<<(N + 3) / 4, 256>>>(x, W_pre_s, b_pre_s, W_pre_v, gw_pre, gb_pre, N);

    const int total_w = CNT_W1S + CNT_W1R + 2*CNT_W2 + CNT_W5V + CNT_W5S;
    wconv_kernel<<<(total_w + 255) / 256, 256>>>(Ws1, Wr1, Ws2, Wr2, W_post_v, W_post_s);

    const size_t shm = (size_t)SMEM_FLOATS * 4;   // 68352 B
    cudaFuncSetAttribute(edge_kernel, cudaFuncAttributeMaxDynamicSharedMemorySize, (int)shm);

    edge_kernel<<<E / TE, BT, shm>>>(
        x, edge_attr, fij_in,
        bs1, bs2, br1, br2,
        gw_post, gb_post,
        ei, (float*)d_out, E);
}

// round 15
// speedup vs baseline: 3.0215x; 1.0900x over previous
#include <cuda_runtime.h>
#include <cuda_bf16.h>
#include <cuda_fp16.h>
#include <cstdint>

#define NN 10000
#define NS 64
#define NV 64
#define HID 128
#define WN 320
#define KS0 192
#define EAD 20
#define TPS 128
#define TPV 192

#define TE 32
#define BT 320
#define ROWS0 200   // s0 row pitch (halves)
#define ROWH  136   // h1/r1/outs row pitch
#define ROWE  40    // eat row pitch
#define ROWV  200   // Vt row pitch
#define ROWT  328   // tpw row pitch [e][kv]

#define INV_SQRT3 0.5773502691896258f
#define INV_SQRT2 0.7071067811865476f
#define VSCALE    0.0625f
#define VUNSCALE  16.0f

// smem offsets (float units)
#define OFF_S0   0      // half [32][200] (3200 fu) ─┐ region A (9600 fu)
#define OFF_H1   3200   // half [32][136] (2176)     │ Vt half [96][200]
#define OFF_R1   5376   // half [32][136] (2176)     │ overlays after ph3
#define OFF_EAT2 7552   // half [32][40]  (640)      │
#define OFF_VT   0      //                           ┘
#define OFF_TPW  9600   // half [32][328] (5248)
#define OFF_OUTS 14848  // half [32][136] (2176)
#define OFF_IDX  17024  // 64 ints
#define SMEM_FLOATS 17088   // 68352 B

// packed weight table sizes (uint4 elements), layout [nt][kt][lane]
#define CNT_W1S (16*12*32)
#define CNT_W1R (16*2*32)
#define CNT_W2  (40*8*32)
#define CNT_W5V (8*12*32)
#define CNT_W5S (8*8*32)

typedef unsigned long long u64;

__device__ float g_sp[NN * NS];
__device__ float g_vp[NN * 3 * NV];     // [n][c*64+v]
__device__ uint4 g_W1sf[CNT_W1S];
__device__ uint4 g_W1rf[CNT_W1R];
__device__ uint4 g_W2sf[CNT_W2];
__device__ uint4 g_W2rf[CNT_W2];
__device__ uint4 g_W5vf[CNT_W5V];
__device__ uint4 g_W5sf[CNT_W5S];

// fast silu: x * sigmoid(x), exp2 bit-trick + Newton reciprocal (FMA/ALU only)
__device__ __forceinline__ float siluf(float x) {
    float z = 1.4426950408889634f * x;
    z = fminf(fmaxf(z, -30.f), 30.f);
    float fl = floorf(z);
    float f  = z - fl;
    float p =            1.8775767e-3f;
    p = fmaf(p, f, 8.9893397e-3f);
    p = fmaf(p, f, 5.5826318e-2f);
    p = fmaf(p, f, 2.4015361e-1f);
    p = fmaf(p, f, 6.9315308e-1f);
    p = fmaf(p, f, 1.0000000f);
    float two_z = __int_as_float(__float_as_int(p) + ((int)fl << 23));
    float d = 1.0f + two_z;
    float r = __int_as_float(0x7EF127EAu - __float_as_int(d));
    r = r * fmaf(-d, r, 2.0f);
    r = r * fmaf(-d, r, 2.0f);
    return x * two_z * r;
}
__device__ __forceinline__ unsigned int f2h2(float a, float b) {
    __half2 h = __floats2half2_rn(a, b);
    return *reinterpret_cast<unsigned int*>(&h);
}
#define LDMX4(r0,r1,r2,r3,addr) \
    asm volatile("ldmatrix.sync.aligned.m8n8.x4.shared.b16 {%0,%1,%2,%3}, [%4];" \
        : "=r"(r0), "=r"(r1), "=r"(r2), "=r"(r3) : "r"(addr))
#define MMA16816(d0,d1,d2,d3,a0,a1,a2,a3,b0,b1) \
    asm volatile("mma.sync.aligned.m16n8k16.row.col.f32.f16.f16.f32 " \
        "{%0,%1,%2,%3}, {%4,%5,%6,%7}, {%8,%9}, {%0,%1,%2,%3};" \
        : "+f"(d0), "+f"(d1), "+f"(d2), "+f"(d3) \
        : "r"(a0), "r"(a1), "r"(a2), "r"(a3), "r"(b0), "r"(b1))

// ---------------------------------------------------------------------------
__global__ __launch_bounds__(256) void node_kernel(
    const float* __restrict__ x,
    const float* __restrict__ Wps, const float* __restrict__ bps,
    const float* __restrict__ Wpv,
    const float* __restrict__ gw, const float* __restrict__ gb,
    int N)
{
    __shared__ float sx[4][256];
    const int ln = threadIdx.x >> 6;
    const int v  = threadIdx.x & 63;
    const int n  = blockIdx.x * 4 + ln;

    if (n < N) {
        #pragma unroll
        for (int i = v; i < 256; i += 64) sx[ln][i] = x[n * 256 + i];
    }
    __syncthreads();
    if (n >= N) return;

    const float* xs = sx[ln];
    const float* xv = sx[ln] + 64;

    float sacc = bps[v];
    #pragma unroll 4
    for (int i = 0; i < NS; i++) sacc = fmaf(xs[i], Wps[i * NS + v], sacc);

    float ax = 0.f, ay = 0.f, az = 0.f;
    #pragma unroll 4
    for (int u = 0; u < NV; u++) {
        float w = Wpv[u * NV + v];
        ax = fmaf(xv[u * 3 + 0], w, ax);
        ay = fmaf(xv[u * 3 + 1], w, ay);
        az = fmaf(xv[u * 3 + 2], w, az);
    }
    float nrm = sqrtf(ax * ax + ay * ay + az * az + 1e-12f);
    float g = siluf(nrm * gw[v] + gb[v]);

    g_sp[n * NS + v] = siluf(sacc);
    g_vp[n * 192 + 0 * 64 + v] = ax * g;
    g_vp[n * 192 + 1 * 64 + v] = ay * g;
    g_vp[n * 192 + 2 * 64 + v] = az * g;
}

// ---------------------------------------------------------------------------
__device__ __forceinline__ uint4 pack_w(const float* W, int ld, int n, int k0, int Kv) {
    float w00 = (k0     < Kv) ? W[(k0)     * ld + n] : 0.f;
    float w01 = (k0 + 1 < Kv) ? W[(k0 + 1) * ld + n] : 0.f;
    float w10 = (k0 + 8 < Kv) ? W[(k0 + 8) * ld + n] : 0.f;
    float w11 = (k0 + 9 < Kv) ? W[(k0 + 9) * ld + n] : 0.f;
    __half h00 = __float2half_rn(w00), h01 = __float2half_rn(w01);
    __half h10 = __float2half_rn(w10), h11 = __float2half_rn(w11);
    __half l00 = __float2half_rn(w00 - __half2float(h00));
    __half l01 = __float2half_rn(w01 - __half2float(h01));
    __half l10 = __float2half_rn(w10 - __half2float(h10));
    __half l11 = __float2half_rn(w11 - __half2float(h11));
    uint4 r;
    __half2 p;
    p = __halves2half2(h00, h01); r.x = *(unsigned*)&p;
    p = __halves2half2(h10, h11); r.y = *(unsigned*)&p;
    p = __halves2half2(l00, l01); r.z = *(unsigned*)&p;
    p = __halves2half2(l10, l11); r.w = *(unsigned*)&p;
    return r;
}

__global__ __launch_bounds__(256) void wconv_kernel(
    const float* __restrict__ Ws1, const float* __restrict__ Wr1,
    const float* __restrict__ Ws2, const float* __restrict__ Wr2,
    const float* __restrict__ Wpv, const float* __restrict__ Wps)
{
    int i = blockIdx.x * 256 + threadIdx.x;
    int lane = i & 31, g = lane >> 2, t = lane & 3;
    if (i < CNT_W1S) {
        int kt = (i >> 5) % 12, nt = i / (12 * 32);
        g_W1sf[i] = pack_w(Ws1, HID, nt*8 + g, kt*16 + t*2, KS0);
    } else if (i < CNT_W1S + CNT_W1R) {
        int j = i - CNT_W1S;
        int kt = (j >> 5) & 1, nt = j / 64;
        g_W1rf[j] = pack_w(Wr1, HID, nt*8 + g, kt*16 + t*2, EAD);
    } else if (i < CNT_W1S + CNT_W1R + CNT_W2) {
        int j = i - (CNT_W1S + CNT_W1R);
        int kt = (j >> 5) & 7, nt = j / 256;
        g_W2sf[j] = pack_w(Ws2, WN, nt*8 + g, kt*16 + t*2, HID);
    } else if (i < CNT_W1S + CNT_W1R + 2*CNT_W2) {
        int j = i - (CNT_W1S + CNT_W1R + CNT_W2);
        int kt = (j >> 5) & 7, nt = j / 256;
        g_W2rf[j] = pack_w(Wr2, WN, nt*8 + g, kt*16 + t*2, HID);
    } else if (i < CNT_W1S + CNT_W1R + 2*CNT_W2 + CNT_W5V) {
        int j = i - (CNT_W1S + CNT_W1R + 2*CNT_W2);
        int kt = (j >> 5) % 12, nt = j / 384;
        g_W5vf[j] = pack_w(Wpv, NV, nt*8 + g, kt*16 + t*2, TPV);
    } else if (i < CNT_W1S + CNT_W1R + 2*CNT_W2 + CNT_W5V + CNT_W5S) {
        int j = i - (CNT_W1S + CNT_W1R + 2*CNT_W2 + CNT_W5V);
        int kt = (j >> 5) & 7, nt = j / 256;
        g_W5sf[j] = pack_w(Wps, NS, nt*8 + g, kt*16 + t*2, TPS);
    }
}

// ---------------------------------------------------------------------------
__global__ __launch_bounds__(BT, 3) void edge_kernel(
    const float* __restrict__ x,
    const float* __restrict__ edge_attr,
    const float* __restrict__ fij_in,
    const float* __restrict__ bs1, const float* __restrict__ bs2,
    const float* __restrict__ br1, const float* __restrict__ br2,
    const float* __restrict__ gwp, const float* __restrict__ gbp,
    const int* __restrict__ ei,
    float* __restrict__ out, int E)
{
    extern __shared__ float sm[];
    __half* s0h   = (__half*)(sm + OFF_S0);    // [32][200]
    __half* h1h   = (__half*)(sm + OFF_H1);    // [32][136]
    __half* r1h   = (__half*)(sm + OFF_R1);    // [32][136]
    __half* eat2  = (__half*)(sm + OFF_EAT2);  // [32][40]
    __half* Vth   = (__half*)(sm + OFF_VT);    // [96][200] after ph3 (scaled 1/16)
    __half* tpwh  = (__half*)(sm + OFF_TPW);   // [32][328]
    __half* outsh = (__half*)(sm + OFF_OUTS);  // [32][136]
    int*    sidx  = (int*)(sm + OFF_IDX);      // [64]

    const int tid = threadIdx.x;
    const int e0  = blockIdx.x * TE;
    const unsigned smem_b = (unsigned)__cvta_generic_to_shared(sm);
    const int wid = tid >> 5, lane = tid & 31;
    const int g = lane >> 2, t = lane & 3;

    if (tid < 64) {
        int e = tid & 31;
        sidx[tid] = (tid < 32) ? ei[e0 + e] : ei[E + e0 + e];
    }
    __syncthreads();

    // ---- Phase 1: gather x -> s0h[e][k] fp16 (32 edges); eat ----
    for (int idx = tid; idx < 512; idx += BT) {
        const int e = idx & 31, q = idx >> 5;   // q 0..15
        const int s = sidx[e], d = sidx[32 + e];
        const float* xs = x + (size_t)s * 256;
        const float* xd = x + (size_t)d * 256;

        float4 a = *(const float4*)(xs + q * 4);
        float4 b = *(const float4*)(xd + q * 4);
        *(uint2*)(s0h + e*ROWS0 + q*4)      = make_uint2(f2h2(a.x, a.y), f2h2(a.z, a.w));
        *(uint2*)(s0h + e*ROWS0 + 64 + q*4) = make_uint2(f2h2(b.x, b.y), f2h2(b.z, b.w));

        float4 v0 = *(const float4*)(xs + 64 + q*12);
        float4 v1 = *(const float4*)(xs + 64 + q*12 + 4);
        float4 v2 = *(const float4*)(xs + 64 + q*12 + 8);
        float4 w0 = *(const float4*)(xd + 64 + q*12);
        float4 w1 = *(const float4*)(xd + 64 + q*12 + 4);
        float4 w2 = *(const float4*)(xd + 64 + q*12 + 8);
        float d0 = v0.x*w0.x + v0.y*w0.y + v0.z*w0.z;
        float d1 = v0.w*w0.w + v1.x*w1.x + v1.y*w1.y;
        float d2 = v1.z*w1.z + v1.w*w1.w + v2.x*w2.x;
        float d3 = v2.y*w2.y + v2.z*w2.z + v2.w*w2.w;
        *(uint2*)(s0h + e*ROWS0 + 128 + q*4) = make_uint2(f2h2(d0, d1), f2h2(d2, d3));
    }
    for (int idx = tid; idx < 32 * ROWE; idx += BT) {
        int e = idx / ROWE, i = idx % ROWE;
        eat2[idx] = (i < EAD)
            ? __float2half_rn(edge_attr[(size_t)(e0 + e) * EAD + i])
            : __half(0.f);
    }
    __syncthreads();

    // ---- Phase 2 (tensor): h1/r1 for 32 edges; B shared across 2 m-tiles ----
    {
        const unsigned a0b = smem_b + OFF_S0*4   + (unsigned)(lane & 15) * (ROWS0*2) + (unsigned)(lane >> 4) * 16;
        const unsigned aeb = smem_b + OFF_EAT2*4 + (unsigned)(lane & 15) * (ROWE*2)  + (unsigned)(lane >> 4) * 16;
        for (int nt = wid; nt < 16; nt += 10) {
            float ds[2][4] = {{0,0,0,0},{0,0,0,0}};
            const uint4* bp = g_W1sf + nt*384 + lane;
            #pragma unroll
            for (int ktb = 0; ktb < 3; ktb++) {
                uint4 w[4];
                #pragma unroll
                for (int j = 0; j < 4; j++) w[j] = bp[(ktb*4 + j)*32];
                #pragma unroll
                for (int m = 0; m < 2; m++) {
                    const unsigned ab = a0b + (unsigned)(m*16) * (ROWS0*2);
                    #pragma unroll
                    for (int j = 0; j < 4; j++) {
                        uint32_t A0, A1, A2, A3;
                        LDMX4(A0, A1, A2, A3, ab + (ktb*4 + j)*32);
                        MMA16816(ds[m][0], ds[m][1], ds[m][2], ds[m][3], A0, A1, A2, A3, w[j].x, w[j].y);
                        MMA16816(ds[m][0], ds[m][1], ds[m][2], ds[m][3], A0, A1, A2, A3, w[j].z, w[j].w);
                    }
                }
            }
            float dr[2][4] = {{0,0,0,0},{0,0,0,0}};
            const uint4* bq = g_W1rf + nt*64 + lane;
            {
                uint4 w0 = bq[0], w1 = bq[32];
                #pragma unroll
                for (int m = 0; m < 2; m++) {
                    const unsigned ab = aeb + (unsigned)(m*16) * (ROWE*2);
                    uint32_t A0, A1, A2, A3;
                    LDMX4(A0, A1, A2, A3, ab);
                    MMA16816(dr[m][0], dr[m][1], dr[m][2], dr[m][3], A0, A1, A2, A3, w0.x, w0.y);
                    MMA16816(dr[m][0], dr[m][1], dr[m][2], dr[m][3], A0, A1, A2, A3, w0.z, w0.w);
                    LDMX4(A0, A1, A2, A3, ab + 32);
                    MMA16816(dr[m][0], dr[m][1], dr[m][2], dr[m][3], A0, A1, A2, A3, w1.x, w1.y);
                    MMA16816(dr[m][0], dr[m][1], dr[m][2], dr[m][3], A0, A1, A2, A3, w1.z, w1.w);
                }
            }
            float2 bbs = *(const float2*)(bs1 + nt*8 + t*2);
            float2 bbr = *(const float2*)(br1 + nt*8 + t*2);
            #pragma unroll
            for (int m = 0; m < 2; m++) {
                int eL = m*16 + g, eH = eL + 8;
                *(unsigned*)(h1h + eL*ROWH + nt*8 + t*2) = f2h2(siluf(ds[m][0]+bbs.x), siluf(ds[m][1]+bbs.y));
                *(unsigned*)(h1h + eH*ROWH + nt*8 + t*2) = f2h2(siluf(ds[m][2]+bbs.x), siluf(ds[m][3]+bbs.y));
                *(unsigned*)(r1h + eL*ROWH + nt*8 + t*2) = f2h2(siluf(dr[m][0]+bbr.x), siluf(dr[m][1]+bbr.y));
                *(unsigned*)(r1h + eH*ROWH + nt*8 + t*2) = f2h2(siluf(dr[m][2]+bbr.x), siluf(dr[m][3]+bbr.y));
            }
        }
    }
    __syncthreads();

    // ---- Phase 3 (tensor): tp_w; 40 nt over 10 warps; B shared across 2 m ----
    {
        const unsigned h1b = smem_b + OFF_H1*4 + (unsigned)(lane & 15) * (ROWH*2) + (unsigned)(lane >> 4) * 16;
        const unsigned r1b = smem_b + OFF_R1*4 + (unsigned)(lane & 15) * (ROWH*2) + (unsigned)(lane >> 4) * 16;
        #pragma unroll
        for (int p = 0; p < 4; p++) {
            const int nt = wid*4 + p;
            float at[2][4] = {{0,0,0,0},{0,0,0,0}};
            float ar[2][4] = {{0,0,0,0},{0,0,0,0}};
            const uint4* bsp = g_W2sf + nt*256 + lane;
            const uint4* brp = g_W2rf + nt*256 + lane;
            #pragma unroll
            for (int ktb = 0; ktb < 2; ktb++) {
                uint4 w[4];
                #pragma unroll
                for (int j = 0; j < 4; j++) w[j] = bsp[(ktb*4 + j)*32];
                #pragma unroll
                for (int m = 0; m < 2; m++) {
                    const unsigned ab = h1b + (unsigned)(m*16) * (ROWH*2);
                    #pragma unroll
                    for (int j = 0; j < 4; j++) {
                        uint32_t A0, A1, A2, A3;
                        LDMX4(A0, A1, A2, A3, ab + (ktb*4 + j)*32);
                        MMA16816(at[m][0], at[m][1], at[m][2], at[m][3], A0, A1, A2, A3, w[j].x, w[j].y);
                        MMA16816(at[m][0], at[m][1], at[m][2], at[m][3], A0, A1, A2, A3, w[j].z, w[j].w);
                    }
                }
            }
            #pragma unroll
            for (int ktb = 0; ktb < 2; ktb++) {
                uint4 w[4];
                #pragma unroll
                for (int j = 0; j < 4; j++) w[j] = brp[(ktb*4 + j)*32];
                #pragma unroll
                for (int m = 0; m < 2; m++) {
                    const unsigned ab = r1b + (unsigned)(m*16) * (ROWH*2);
                    #pragma unroll
                    for (int j = 0; j < 4; j++) {
                        uint32_t A0, A1, A2, A3;
                        LDMX4(A0, A1, A2, A3, ab + (ktb*4 + j)*32);
                        MMA16816(ar[m][0], ar[m][1], ar[m][2], ar[m][3], A0, A1, A2, A3, w[j].x, w[j].y);
                        MMA16816(ar[m][0], ar[m][1], ar[m][2], ar[m][3], A0, A1, A2, A3, w[j].z, w[j].w);
                    }
                }
            }
            const int kv0 = nt*8 + t*2;
            float2 bb = *(const float2*)(bs2 + kv0);
            float2 cc = *(const float2*)(br2 + kv0);
            #pragma unroll
            for (int m = 0; m < 2; m++) {
                int eL = m*16 + g, eH = eL + 8;
                *(unsigned*)(tpwh + eL*ROWT + kv0) =
                    f2h2((at[m][0]+bb.x)*(ar[m][0]+cc.x), (at[m][1]+bb.y)*(ar[m][1]+cc.y));
                *(unsigned*)(tpwh + eH*ROWT + kv0) =
                    f2h2((at[m][2]+bb.x)*(ar[m][2]+cc.x), (at[m][3]+bb.y)*(ar[m][3]+cc.y));
            }
        }
    }
    __syncthreads();

    // ---- Phase 4a: out_v gated -> Vth[(c*32+e)][u]; g_sp/g_vp from L2 ----
    for (int idx = tid; idx < TE * TPV; idx += BT) {
        const int e = idx / TPV, u = idx - e * TPV;
        const int s = sidx[e], d = sidx[32 + e];
        float vx, vy, vz;
        if (u < 64) {
            float coef = __half2float(tpwh[e*ROWT + 64 + u]) * g_sp[(size_t)s*64 + u];
            const float* vp = g_vp + (size_t)d * 192;
            vx = coef * vp[u]; vy = coef * vp[64 + u]; vz = coef * vp[128 + u];
        } else if (u < 128) {
            int uu = u - 64;
            float coef = __half2float(tpwh[e*ROWT + 128 + uu]) * g_sp[(size_t)d*64 + uu];
            const float* vp = g_vp + (size_t)s * 192;
            vx = coef * vp[uu]; vy = coef * vp[64 + uu]; vz = coef * vp[128 + uu];
        } else {
            int uu = u - 128;
            float w5 = __half2float(tpwh[e*ROWT + 256 + uu]) * INV_SQRT2;
            const float* va = g_vp + (size_t)s * 192;
            const float* vb = g_vp + (size_t)d * 192;
            float ax = va[uu], ay = va[64 + uu], az = va[128 + uu];
            float bx = vb[uu], by = vb[64 + uu], bz = vb[128 + uu];
            vx = w5 * (ay*bz - az*by);
            vy = w5 * (az*bx - ax*bz);
            vz = w5 * (ax*by - ay*bx);
        }
        float nrm = sqrtf(vx*vx + vy*vy + vz*vz + 1e-12f);
        float gg = siluf(nrm * gwp[u] + gbp[u]) * VSCALE;
        Vth[(0*32 + e)*ROWV + u] = __float2half_rn(vx * gg);
        Vth[(1*32 + e)*ROWV + u] = __float2half_rn(vy * gg);
        Vth[(2*32 + e)*ROWV + u] = __float2half_rn(vz * gg);
    }

    // ---- Phase 4b: out_s -> outsh[e][j] ----
    for (int idx = tid; idx < TE * TPS; idx += BT) {
        const int e = idx >> 7, j = idx & 127;
        const int s = sidx[e], d = sidx[32 + e];
        float val;
        if (j < 64) {
            val = __half2float(tpwh[e*ROWT + j]) * g_sp[(size_t)s*64 + j] * g_sp[(size_t)d*64 + j];
        } else {
            int u = j - 64;
            const float* va = g_vp + (size_t)s * 192;
            const float* vb = g_vp + (size_t)d * 192;
            float dt = va[u]*vb[u] + va[64+u]*vb[64+u] + va[128+u]*vb[128+u];
            val = __half2float(tpwh[e*ROWT + 192 + u]) * dt * INV_SQRT3;
        }
        outsh[e*ROWH + j] = __float2half_rn(siluf(val));
    }
    __syncthreads();

    // ---- Phase 5 (tensor): warps 0-7 -> fij_v (coalesced 24B chunks); 8-9 -> fij_s ----
    if (wid < 8) {
        const int nt = wid;
        const uint4* bp = g_W5vf + nt*384 + lane;
        #pragma unroll
        for (int ch = 0; ch < 2; ch++) {            // ch = edge half
            float acc[3][4] = {{0,0,0,0},{0,0,0,0},{0,0,0,0}};   // [c][frag]
            #pragma unroll
            for (int ktb = 0; ktb < 3; ktb++) {
                uint4 w[4];
                #pragma unroll
                for (int j = 0; j < 4; j++) w[j] = bp[(ktb*4 + j)*32];
                #pragma unroll
                for (int mm = 0; mm < 3; mm++) {    // mm = c
                    const int m = 2*mm + ch;        // Vth m-tile (rows c*32 + ch*16 ..)
                    const unsigned ab = smem_b + OFF_VT*4
                        + (unsigned)(m*16 + (lane & 15)) * (ROWV*2) + (unsigned)(lane >> 4) * 16;
                    #pragma unroll
                    for (int j = 0; j < 4; j++) {
                        uint32_t A0, A1, A2, A3;
                        LDMX4(A0, A1, A2, A3, ab + (ktb*4 + j)*32);
                        MMA16816(acc[mm][0], acc[mm][1], acc[mm][2], acc[mm][3], A0, A1, A2, A3, w[j].x, w[j].y);
                        MMA16816(acc[mm][0], acc[mm][1], acc[mm][2], acc[mm][3], A0, A1, A2, A3, w[j].z, w[j].w);
                    }
                }
            }
            const int v0 = nt*8 + t*2;
            #pragma unroll
            for (int h = 0; h < 2; h++) {
                const int e = ch*16 + g + h*8;
                const float* fi = fij_in + (size_t)(e0 + e) * 256 + 64 + v0*3;
                float*       op = out    + (size_t)(e0 + e) * 256 + 64 + v0*3;
                float2 f01 = *(const float2*)(fi);
                float2 f23 = *(const float2*)(fi + 2);
                float2 f45 = *(const float2*)(fi + 4);
                float2 o01, o23, o45;
                o01.x = f01.x + acc[0][2*h]   * VUNSCALE;   // v0,  c0
                o01.y = f01.y + acc[1][2*h]   * VUNSCALE;   // v0,  c1
                o23.x = f23.x + acc[2][2*h]   * VUNSCALE;   // v0,  c2
                o23.y = f23.y + acc[0][2*h+1] * VUNSCALE;   // v0+1,c0
                o45.x = f45.x + acc[1][2*h+1] * VUNSCALE;   // v0+1,c1
                o45.y = f45.y + acc[2][2*h+1] * VUNSCALE;   // v0+1,c2
                *(float2*)(op)     = o01;
                *(float2*)(op + 2) = o23;
                *(float2*)(op + 4) = o45;
            }
        }
    } else {
        #pragma unroll
        for (int p = 0; p < 4; p++) {
            const int nt = (wid - 8)*4 + p;
            const uint4* bp = g_W5sf + nt*256 + lane;
            float acc[2][4] = {{0,0,0,0},{0,0,0,0}};
            #pragma unroll
            for (int ktb = 0; ktb < 2; ktb++) {
                uint4 w[4];
                #pragma unroll
                for (int j = 0; j < 4; j++) w[j] = bp[(ktb*4 + j)*32];
                #pragma unroll
                for (int m = 0; m < 2; m++) {
                    const unsigned ab = smem_b + OFF_OUTS*4
                        + (unsigned)(m*16 + (lane & 15)) * (ROWH*2) + (unsigned)(lane >> 4) * 16;
                    #pragma unroll
                    for (int j = 0; j < 4; j++) {
                        uint32_t A0, A1, A2, A3;
                        LDMX4(A0, A1, A2, A3, ab + (ktb*4 + j)*32);
                        MMA16816(acc[m][0], acc[m][1], acc[m][2], acc[m][3], A0, A1, A2, A3, w[j].x, w[j].y);
                        MMA16816(acc[m][0], acc[m][1], acc[m][2], acc[m][3], A0, A1, A2, A3, w[j].z, w[j].w);
                    }
                }
            }
            const int v0 = nt*8 + t*2;
            #pragma unroll
            for (int m = 0; m < 2; m++) {
                const int eb = m*16;
                size_t o;
                o = (size_t)(e0 + eb + g)     * 256 + v0;     out[o] = fij_in[o] + acc[m][0];
                o = (size_t)(e0 + eb + g)     * 256 + v0 + 1; out[o] = fij_in[o] + acc[m][1];
                o = (size_t)(e0 + eb + g + 8) * 256 + v0;     out[o] = fij_in[o] + acc[m][2];
                o = (size_t)(e0 + eb + g + 8) * 256 + v0 + 1; out[o] = fij_in[o] + acc[m][3];
            }
        }
    }
}

// ---------------------------------------------------------------------------
extern "C" void kernel_launch(void* const* d_in, const int* in_sizes, int n_in,
                              void* d_out, int out_size)
{
    const float* x         = (const float*)d_in[0];
    const float* edge_attr = (const float*)d_in[1];
    const float* fij_in    = (const float*)d_in[2];
    const float* W_pre_s   = (const float*)d_in[3];
    const float* b_pre_s   = (const float*)d_in[4];
    const float* W_pre_v   = (const float*)d_in[5];
    const float* gw_pre    = (const float*)d_in[6];
    const float* gb_pre    = (const float*)d_in[7];
    const float* Ws1       = (const float*)d_in[8];
    const float* bs1       = (const float*)d_in[9];
    const float* Ws2       = (const float*)d_in[10];
    const float* bs2       = (const float*)d_in[11];
    const float* Wr1       = (const float*)d_in[12];
    const float* br1       = (const float*)d_in[13];
    const float* Wr2       = (const float*)d_in[14];
    const float* br2       = (const float*)d_in[15];
    const float* gw_post   = (const float*)d_in[16];
    const float* gb_post   = (const float*)d_in[17];
    const float* W_post_s  = (const float*)d_in[18];
    const float* W_post_v  = (const float*)d_in[19];
    const int*   ei        = (const int*)d_in[20];

    const int N = in_sizes[0] / 256;
    const int E = in_sizes[2] / 256;

    node_kernel<<<(N + 3) / 4, 256>>>(x, W_pre_s, b_pre_s, W_pre_v, gw_pre, gb_pre, N);

    const int total_w = CNT_W1S + CNT_W1R + 2*CNT_W2 + CNT_W5V + CNT_W5S;
    wconv_kernel<<<(total_w + 255) / 256, 256>>>(Ws1, Wr1, Ws2, Wr2, W_post_v, W_post_s);

    const size_t shm = (size_t)SMEM_FLOATS * 4;   // 68352 B
    cudaFuncSetAttribute(edge_kernel, cudaFuncAttributeMaxDynamicSharedMemorySize, (int)shm);

    edge_kernel<<<E / TE, BT, shm>>>(
        x, edge_attr, fij_in,
        bs1, bs2, br1, br2,
        gw_post, gb_post,
        ei, (float*)d_out, E);
}

// round 17
// speedup vs baseline: 3.5369x; 1.1706x over previous
#include <cuda_runtime.h>
#include <cuda_bf16.h>
#include <cuda_fp16.h>
#include <cstdint>

#define NN 10000
#define NS 64
#define NV 64
#define HID 128
#define WN 320
#define KS0 192
#define EAD 20
#define TPS 128
#define TPV 192

#define TE 32
#define BT 320
#define ROWS0 200   // s0 row pitch (halves)
#define ROWH  136   // h1/r1/outs row pitch
#define ROWE  40    // eat row pitch
#define ROWV  200   // Vt row pitch
#define ROWT  328   // tpw row pitch [e][kv]

#define INV_SQRT3 0.5773502691896258f
#define INV_SQRT2 0.7071067811865476f
#define VSCALE    0.0625f
#define VUNSCALE  16.0f

// smem offsets (float units)
#define OFF_S0   0      // half [32][200] (3200 fu) ─┐ region A (9600 fu)
#define OFF_H1   3200   // half [32][136] (2176)     │ Vt half [96][200]
#define OFF_R1   5376   // half [32][136] (2176)     │ overlays after ph3
#define OFF_EAT2 7552   // half [32][40]  (640)      │
#define OFF_VT   0      //                           ┘
#define OFF_TPW  9600   // half [32][328] (5248)
#define OFF_OUTS 14848  // half [32][136] (2176)
#define OFF_IDX  17024  // 64 ints
#define SMEM_FLOATS 17088   // 68352 B

// packed weight table sizes (uint4 elements), layout [nt][kt][lane]
#define CNT_W1S (16*12*32)
#define CNT_W1R (16*2*32)
#define CNT_W2  (40*8*32)
#define CNT_W5V (8*12*32)
#define CNT_W5S (8*8*32)

typedef unsigned long long u64;

__device__ float g_sp[NN * NS];
__device__ float g_vp[NN * 3 * NV];     // [n][c*64+v]
__device__ uint4 g_W1sf[CNT_W1S];
__device__ uint4 g_W1rf[CNT_W1R];
__device__ uint4 g_W2sf[CNT_W2];
__device__ uint4 g_W2rf[CNT_W2];
__device__ uint4 g_W5vf[CNT_W5V];
__device__ uint4 g_W5sf[CNT_W5S];

__device__ __forceinline__ float siluf(float x) { return x / (1.0f + __expf(-x)); }
__device__ __forceinline__ unsigned int f2h2(float a, float b) {
    __half2 h = __floats2half2_rn(a, b);
    return *reinterpret_cast<unsigned int*>(&h);
}
#define LDMX4(r0,r1,r2,r3,addr) \
    asm volatile("ldmatrix.sync.aligned.m8n8.x4.shared.b16 {%0,%1,%2,%3}, [%4];" \
        : "=r"(r0), "=r"(r1), "=r"(r2), "=r"(r3) : "r"(addr))
#define MMA16816(d0,d1,d2,d3,a0,a1,a2,a3,b0,b1) \
    asm volatile("mma.sync.aligned.m16n8k16.row.col.f32.f16.f16.f32 " \
        "{%0,%1,%2,%3}, {%4,%5,%6,%7}, {%8,%9}, {%0,%1,%2,%3};" \
        : "+f"(d0), "+f"(d1), "+f"(d2), "+f"(d3) \
        : "r"(a0), "r"(a1), "r"(a2), "r"(a3), "r"(b0), "r"(b1))

// ---------------------------------------------------------------------------
__global__ __launch_bounds__(256) void node_kernel(
    const float* __restrict__ x,
    const float* __restrict__ Wps, const float* __restrict__ bps,
    const float* __restrict__ Wpv,
    const float* __restrict__ gw, const float* __restrict__ gb,
    int N)
{
    __shared__ float sx[4][256];
    const int ln = threadIdx.x >> 6;
    const int v  = threadIdx.x & 63;
    const int n  = blockIdx.x * 4 + ln;

    if (n < N) {
        #pragma unroll
        for (int i = v; i < 256; i += 64) sx[ln][i] = x[n * 256 + i];
    }
    __syncthreads();
    if (n >= N) return;

    const float* xs = sx[ln];
    const float* xv = sx[ln] + 64;

    float sacc = bps[v];
    #pragma unroll 4
    for (int i = 0; i < NS; i++) sacc = fmaf(xs[i], Wps[i * NS + v], sacc);

    float ax = 0.f, ay = 0.f, az = 0.f;
    #pragma unroll 4
    for (int u = 0; u < NV; u++) {
        float w = Wpv[u * NV + v];
        ax = fmaf(xv[u * 3 + 0], w, ax);
        ay = fmaf(xv[u * 3 + 1], w, ay);
        az = fmaf(xv[u * 3 + 2], w, az);
    }
    float nrm = sqrtf(ax * ax + ay * ay + az * az + 1e-12f);
    float g = siluf(nrm * gw[v] + gb[v]);

    g_sp[n * NS + v] = siluf(sacc);
    g_vp[n * 192 + 0 * 64 + v] = ax * g;
    g_vp[n * 192 + 1 * 64 + v] = ay * g;
    g_vp[n * 192 + 2 * 64 + v] = az * g;
}

// ---------------------------------------------------------------------------
__device__ __forceinline__ uint4 pack_w(const float* W, int ld, int n, int k0, int Kv) {
    float w00 = (k0     < Kv) ? W[(k0)     * ld + n] : 0.f;
    float w01 = (k0 + 1 < Kv) ? W[(k0 + 1) * ld + n] : 0.f;
    float w10 = (k0 + 8 < Kv) ? W[(k0 + 8) * ld + n] : 0.f;
    float w11 = (k0 + 9 < Kv) ? W[(k0 + 9) * ld + n] : 0.f;
    __half h00 = __float2half_rn(w00), h01 = __float2half_rn(w01);
    __half h10 = __float2half_rn(w10), h11 = __float2half_rn(w11);
    __half l00 = __float2half_rn(w00 - __half2float(h00));
    __half l01 = __float2half_rn(w01 - __half2float(h01));
    __half l10 = __float2half_rn(w10 - __half2float(h10));
    __half l11 = __float2half_rn(w11 - __half2float(h11));
    uint4 r;
    __half2 p;
    p = __halves2half2(h00, h01); r.x = *(unsigned*)&p;
    p = __halves2half2(h10, h11); r.y = *(unsigned*)&p;
    p = __halves2half2(l00, l01); r.z = *(unsigned*)&p;
    p = __halves2half2(l10, l11); r.w = *(unsigned*)&p;
    return r;
}

__global__ __launch_bounds__(256) void wconv_kernel(
    const float* __restrict__ Ws1, const float* __restrict__ Wr1,
    const float* __restrict__ Ws2, const float* __restrict__ Wr2,
    const float* __restrict__ Wpv, const float* __restrict__ Wps)
{
    int i = blockIdx.x * 256 + threadIdx.x;
    int lane = i & 31, g = lane >> 2, t = lane & 3;
    if (i < CNT_W1S) {
        int kt = (i >> 5) % 12, nt = i / (12 * 32);
        g_W1sf[i] = pack_w(Ws1, HID, nt*8 + g, kt*16 + t*2, KS0);
    } else if (i < CNT_W1S + CNT_W1R) {
        int j = i - CNT_W1S;
        int kt = (j >> 5) & 1, nt = j / 64;
        g_W1rf[j] = pack_w(Wr1, HID, nt*8 + g, kt*16 + t*2, EAD);
    } else if (i < CNT_W1S + CNT_W1R + CNT_W2) {
        int j = i - (CNT_W1S + CNT_W1R);
        int kt = (j >> 5) & 7, nt = j / 256;
        g_W2sf[j] = pack_w(Ws2, WN, nt*8 + g, kt*16 + t*2, HID);
    } else if (i < CNT_W1S + CNT_W1R + 2*CNT_W2) {
        int j = i - (CNT_W1S + CNT_W1R + CNT_W2);
        int kt = (j >> 5) & 7, nt = j / 256;
        g_W2rf[j] = pack_w(Wr2, WN, nt*8 + g, kt*16 + t*2, HID);
    } else if (i < CNT_W1S + CNT_W1R + 2*CNT_W2 + CNT_W5V) {
        int j = i - (CNT_W1S + CNT_W1R + 2*CNT_W2);
        int kt = (j >> 5) % 12, nt = j / 384;
        g_W5vf[j] = pack_w(Wpv, NV, nt*8 + g, kt*16 + t*2, TPV);
    } else if (i < CNT_W1S + CNT_W1R + 2*CNT_W2 + CNT_W5V + CNT_W5S) {
        int j = i - (CNT_W1S + CNT_W1R + 2*CNT_W2 + CNT_W5V);
        int kt = (j >> 5) & 7, nt = j / 256;
        g_W5sf[j] = pack_w(Wps, NS, nt*8 + g, kt*16 + t*2, TPS);
    }
}

// ---------------------------------------------------------------------------
__global__ __launch_bounds__(BT, 3) void edge_kernel(
    const float* __restrict__ x,
    const float* __restrict__ edge_attr,
    const float* __restrict__ fij_in,
    const float* __restrict__ bs1, const float* __restrict__ bs2,
    const float* __restrict__ br1, const float* __restrict__ br2,
    const float* __restrict__ gwp, const float* __restrict__ gbp,
    const int* __restrict__ ei,
    float* __restrict__ out, int E)
{
    extern __shared__ float sm[];
    __half* s0h   = (__half*)(sm + OFF_S0);    // [32][200]
    __half* h1h   = (__half*)(sm + OFF_H1);    // [32][136]
    __half* r1h   = (__half*)(sm + OFF_R1);    // [32][136]
    __half* eat2  = (__half*)(sm + OFF_EAT2);  // [32][40]
    __half* Vth   = (__half*)(sm + OFF_VT);    // [96][200] after ph3 (scaled 1/16)
    __half* tpwh  = (__half*)(sm + OFF_TPW);   // [32][328]
    __half* outsh = (__half*)(sm + OFF_OUTS);  // [32][136]
    int*    sidx  = (int*)(sm + OFF_IDX);      // [64]

    const int tid = threadIdx.x;
    const int e0  = blockIdx.x * TE;
    const unsigned smem_b = (unsigned)__cvta_generic_to_shared(sm);
    const int wid = tid >> 5, lane = tid & 31;
    const int g = lane >> 2, t = lane & 3;

    if (tid < 64) {
        int e = tid & 31;
        sidx[tid] = (tid < 32) ? ei[e0 + e] : ei[E + e0 + e];
    }
    __syncthreads();

    // ---- Phase 1: gather x -> s0h[e][k] fp16 (32 edges); eat ----
    for (int idx = tid; idx < 512; idx += BT) {
        const int e = idx & 31, q = idx >> 5;   // q 0..15
        const int s = sidx[e], d = sidx[32 + e];
        const float* xs = x + (size_t)s * 256;
        const float* xd = x + (size_t)d * 256;

        float4 a = *(const float4*)(xs + q * 4);
        float4 b = *(const float4*)(xd + q * 4);
        *(uint2*)(s0h + e*ROWS0 + q*4)      = make_uint2(f2h2(a.x, a.y), f2h2(a.z, a.w));
        *(uint2*)(s0h + e*ROWS0 + 64 + q*4) = make_uint2(f2h2(b.x, b.y), f2h2(b.z, b.w));

        float4 v0 = *(const float4*)(xs + 64 + q*12);
        float4 v1 = *(const float4*)(xs + 64 + q*12 + 4);
        float4 v2 = *(const float4*)(xs + 64 + q*12 + 8);
        float4 w0 = *(const float4*)(xd + 64 + q*12);
        float4 w1 = *(const float4*)(xd + 64 + q*12 + 4);
        float4 w2 = *(const float4*)(xd + 64 + q*12 + 8);
        float d0 = v0.x*w0.x + v0.y*w0.y + v0.z*w0.z;
        float d1 = v0.w*w0.w + v1.x*w1.x + v1.y*w1.y;
        float d2 = v1.z*w1.z + v1.w*w1.w + v2.x*w2.x;
        float d3 = v2.y*w2.y + v2.z*w2.z + v2.w*w2.w;
        *(uint2*)(s0h + e*ROWS0 + 128 + q*4) = make_uint2(f2h2(d0, d1), f2h2(d2, d3));
    }
    for (int idx = tid; idx < 32 * ROWE; idx += BT) {
        int e = idx / ROWE, i = idx % ROWE;
        eat2[idx] = (i < EAD)
            ? __float2half_rn(edge_attr[(size_t)(e0 + e) * EAD + i])
            : __half(0.f);
    }
    __syncthreads();

    // ---- Phase 2 (tensor): h1/r1 for 32 edges; B shared across 2 m-tiles ----
    {
        const unsigned a0b = smem_b + OFF_S0*4   + (unsigned)(lane & 15) * (ROWS0*2) + (unsigned)(lane >> 4) * 16;
        const unsigned aeb = smem_b + OFF_EAT2*4 + (unsigned)(lane & 15) * (ROWE*2)  + (unsigned)(lane >> 4) * 16;
        for (int nt = wid; nt < 16; nt += 10) {
            float ds[2][4] = {{0,0,0,0},{0,0,0,0}};
            const uint4* bp = g_W1sf + nt*384 + lane;
            #pragma unroll
            for (int ktb = 0; ktb < 3; ktb++) {
                uint4 w[4];
                #pragma unroll
                for (int j = 0; j < 4; j++) w[j] = bp[(ktb*4 + j)*32];
                #pragma unroll
                for (int m = 0; m < 2; m++) {
                    const unsigned ab = a0b + (unsigned)(m*16) * (ROWS0*2);
                    #pragma unroll
                    for (int j = 0; j < 4; j++) {
                        uint32_t A0, A1, A2, A3;
                        LDMX4(A0, A1, A2, A3, ab + (ktb*4 + j)*32);
                        MMA16816(ds[m][0], ds[m][1], ds[m][2], ds[m][3], A0, A1, A2, A3, w[j].x, w[j].y);
                        MMA16816(ds[m][0], ds[m][1], ds[m][2], ds[m][3], A0, A1, A2, A3, w[j].z, w[j].w);
                    }
                }
            }
            float dr[2][4] = {{0,0,0,0},{0,0,0,0}};
            const uint4* bq = g_W1rf + nt*64 + lane;
            {
                uint4 w0 = bq[0], w1 = bq[32];
                #pragma unroll
                for (int m = 0; m < 2; m++) {
                    const unsigned ab = aeb + (unsigned)(m*16) * (ROWE*2);
                    uint32_t A0, A1, A2, A3;
                    LDMX4(A0, A1, A2, A3, ab);
                    MMA16816(dr[m][0], dr[m][1], dr[m][2], dr[m][3], A0, A1, A2, A3, w0.x, w0.y);
                    MMA16816(dr[m][0], dr[m][1], dr[m][2], dr[m][3], A0, A1, A2, A3, w0.z, w0.w);
                    LDMX4(A0, A1, A2, A3, ab + 32);
                    MMA16816(dr[m][0], dr[m][1], dr[m][2], dr[m][3], A0, A1, A2, A3, w1.x, w1.y);
                    MMA16816(dr[m][0], dr[m][1], dr[m][2], dr[m][3], A0, A1, A2, A3, w1.z, w1.w);
                }
            }
            float2 bbs = *(const float2*)(bs1 + nt*8 + t*2);
            float2 bbr = *(const float2*)(br1 + nt*8 + t*2);
            #pragma unroll
            for (int m = 0; m < 2; m++) {
                int eL = m*16 + g, eH = eL + 8;
                *(unsigned*)(h1h + eL*ROWH + nt*8 + t*2) = f2h2(siluf(ds[m][0]+bbs.x), siluf(ds[m][1]+bbs.y));
                *(unsigned*)(h1h + eH*ROWH + nt*8 + t*2) = f2h2(siluf(ds[m][2]+bbs.x), siluf(ds[m][3]+bbs.y));
                *(unsigned*)(r1h + eL*ROWH + nt*8 + t*2) = f2h2(siluf(dr[m][0]+bbr.x), siluf(dr[m][1]+bbr.y));
                *(unsigned*)(r1h + eH*ROWH + nt*8 + t*2) = f2h2(siluf(dr[m][2]+bbr.x), siluf(dr[m][3]+bbr.y));
            }
        }
    }
    __syncthreads();

    // ---- Phase 3 (tensor): tp_w; 40 nt over 10 warps; B shared across 2 m ----
    {
        const unsigned h1b = smem_b + OFF_H1*4 + (unsigned)(lane & 15) * (ROWH*2) + (unsigned)(lane >> 4) * 16;
        const unsigned r1b = smem_b + OFF_R1*4 + (unsigned)(lane & 15) * (ROWH*2) + (unsigned)(lane >> 4) * 16;
        #pragma unroll
        for (int p = 0; p < 4; p++) {
            const int nt = wid*4 + p;
            float at[2][4] = {{0,0,0,0},{0,0,0,0}};
            float ar[2][4] = {{0,0,0,0},{0,0,0,0}};
            const uint4* bsp = g_W2sf + nt*256 + lane;
            const uint4* brp = g_W2rf + nt*256 + lane;
            #pragma unroll
            for (int ktb = 0; ktb < 2; ktb++) {
                uint4 w[4];
                #pragma unroll
                for (int j = 0; j < 4; j++) w[j] = bsp[(ktb*4 + j)*32];
                #pragma unroll
                for (int m = 0; m < 2; m++) {
                    const unsigned ab = h1b + (unsigned)(m*16) * (ROWH*2);
                    #pragma unroll
                    for (int j = 0; j < 4; j++) {
                        uint32_t A0, A1, A2, A3;
                        LDMX4(A0, A1, A2, A3, ab + (ktb*4 + j)*32);
                        MMA16816(at[m][0], at[m][1], at[m][2], at[m][3], A0, A1, A2, A3, w[j].x, w[j].y);
                        MMA16816(at[m][0], at[m][1], at[m][2], at[m][3], A0, A1, A2, A3, w[j].z, w[j].w);
                    }
                }
            }
            #pragma unroll
            for (int ktb = 0; ktb < 2; ktb++) {
                uint4 w[4];
                #pragma unroll
                for (int j = 0; j < 4; j++) w[j] = brp[(ktb*4 + j)*32];
                #pragma unroll
                for (int m = 0; m < 2; m++) {
                    const unsigned ab = r1b + (unsigned)(m*16) * (ROWH*2);
                    #pragma unroll
                    for (int j = 0; j < 4; j++) {
                        uint32_t A0, A1, A2, A3;
                        LDMX4(A0, A1, A2, A3, ab + (ktb*4 + j)*32);
                        MMA16816(ar[m][0], ar[m][1], ar[m][2], ar[m][3], A0, A1, A2, A3, w[j].x, w[j].y);
                        MMA16816(ar[m][0], ar[m][1], ar[m][2], ar[m][3], A0, A1, A2, A3, w[j].z, w[j].w);
                    }
                }
            }
            const int kv0 = nt*8 + t*2;
            float2 bb = *(const float2*)(bs2 + kv0);
            float2 cc = *(const float2*)(br2 + kv0);
            #pragma unroll
            for (int m = 0; m < 2; m++) {
                int eL = m*16 + g, eH = eL + 8;
                *(unsigned*)(tpwh + eL*ROWT + kv0) =
                    f2h2((at[m][0]+bb.x)*(ar[m][0]+cc.x), (at[m][1]+bb.y)*(ar[m][1]+cc.y));
                *(unsigned*)(tpwh + eH*ROWT + kv0) =
                    f2h2((at[m][2]+bb.x)*(ar[m][2]+cc.x), (at[m][3]+bb.y)*(ar[m][3]+cc.y));
            }
        }
    }
    __syncthreads();

    // ---- Phase 4 (merged): per (e, uu) produce out_s[uu], out_s[64+uu],
    //      and out_v slices u = uu / 64+uu / 128+uu, with one load set ----
    for (int idx = tid; idx < TE * 64; idx += BT) {
        const int e = idx >> 6, uu = idx & 63;
        const int s = sidx[e], d = sidx[32 + e];
        const float* va = g_vp + (size_t)s * 192;
        const float* vb = g_vp + (size_t)d * 192;
        const float sps = g_sp[(size_t)s * 64 + uu];
        const float spd = g_sp[(size_t)d * 64 + uu];
        const float ax = va[uu], ay = va[64 + uu], az = va[128 + uu];
        const float bx = vb[uu], by = vb[64 + uu], bz = vb[128 + uu];
        const __half* tr = tpwh + e * ROWT;
        const float w1 = __half2float(tr[uu]);
        const float w2 = __half2float(tr[64  + uu]);
        const float w3 = __half2float(tr[128 + uu]);
        const float w4 = __half2float(tr[192 + uu]);
        const float w5 = __half2float(tr[256 + uu]) * INV_SQRT2;

        // out_s
        outsh[e*ROWH + uu] = __float2half_rn(siluf(w1 * sps * spd));
        float dotv = ax*bx + ay*by + az*bz;
        outsh[e*ROWH + 64 + uu] = __float2half_rn(siluf(w4 * dotv * INV_SQRT3));

        // out_v u = uu : w2 * si * vj
        {
            float coef = w2 * sps;
            float vx = coef*bx, vy = coef*by, vz = coef*bz;
            float nrm = sqrtf(vx*vx + vy*vy + vz*vz + 1e-12f);
            float gg = siluf(nrm * gwp[uu] + gbp[uu]) * VSCALE;
            Vth[(0*32 + e)*ROWV + uu] = __float2half_rn(vx * gg);
            Vth[(1*32 + e)*ROWV + uu] = __float2half_rn(vy * gg);
            Vth[(2*32 + e)*ROWV + uu] = __float2half_rn(vz * gg);
        }
        // out_v u = 64+uu : w3 * sj * vi
        {
            float coef = w3 * spd;
            float vx = coef*ax, vy = coef*ay, vz = coef*az;
            float nrm = sqrtf(vx*vx + vy*vy + vz*vz + 1e-12f);
            float gg = siluf(nrm * gwp[64 + uu] + gbp[64 + uu]) * VSCALE;
            Vth[(0*32 + e)*ROWV + 64 + uu] = __float2half_rn(vx * gg);
            Vth[(1*32 + e)*ROWV + 64 + uu] = __float2half_rn(vy * gg);
            Vth[(2*32 + e)*ROWV + 64 + uu] = __float2half_rn(vz * gg);
        }
        // out_v u = 128+uu : w5 * cross(vi, vj)
        {
            float vx = w5 * (ay*bz - az*by);
            float vy = w5 * (az*bx - ax*bz);
            float vz = w5 * (ax*by - ay*bx);
            float nrm = sqrtf(vx*vx + vy*vy + vz*vz + 1e-12f);
            float gg = siluf(nrm * gwp[128 + uu] + gbp[128 + uu]) * VSCALE;
            Vth[(0*32 + e)*ROWV + 128 + uu] = __float2half_rn(vx * gg);
            Vth[(1*32 + e)*ROWV + 128 + uu] = __float2half_rn(vy * gg);
            Vth[(2*32 + e)*ROWV + 128 + uu] = __float2half_rn(vz * gg);
        }
    }
    __syncthreads();

    // ---- Phase 5 (tensor): warps 0-7 -> fij_v (coalesced 24B chunks); 8-9 -> fij_s ----
    if (wid < 8) {
        const int nt = wid;
        const uint4* bp = g_W5vf + nt*384 + lane;
        #pragma unroll
        for (int ch = 0; ch < 2; ch++) {            // ch = edge half
            float acc[3][4] = {{0,0,0,0},{0,0,0,0},{0,0,0,0}};   // [c][frag]
            #pragma unroll
            for (int ktb = 0; ktb < 3; ktb++) {
                uint4 w[4];
                #pragma unroll
                for (int j = 0; j < 4; j++) w[j] = bp[(ktb*4 + j)*32];
                #pragma unroll
                for (int mm = 0; mm < 3; mm++) {    // mm = c
                    const int m = 2*mm + ch;
                    const unsigned ab = smem_b + OFF_VT*4
                        + (unsigned)(m*16 + (lane & 15)) * (ROWV*2) + (unsigned)(lane >> 4) * 16;
                    #pragma unroll
                    for (int j = 0; j < 4; j++) {
                        uint32_t A0, A1, A2, A3;
                        LDMX4(A0, A1, A2, A3, ab + (ktb*4 + j)*32);
                        MMA16816(acc[mm][0], acc[mm][1], acc[mm][2], acc[mm][3], A0, A1, A2, A3, w[j].x, w[j].y);
                        MMA16816(acc[mm][0], acc[mm][1], acc[mm][2], acc[mm][3], A0, A1, A2, A3, w[j].z, w[j].w);
                    }
                }
            }
            const int v0 = nt*8 + t*2;
            #pragma unroll
            for (int h = 0; h < 2; h++) {
                const int e = ch*16 + g + h*8;
                const float* fi = fij_in + (size_t)(e0 + e) * 256 + 64 + v0*3;
                float*       op = out    + (size_t)(e0 + e) * 256 + 64 + v0*3;
                float2 f01 = *(const float2*)(fi);
                float2 f23 = *(const float2*)(fi + 2);
                float2 f45 = *(const float2*)(fi + 4);
                float2 o01, o23, o45;
                o01.x = f01.x + acc[0][2*h]   * VUNSCALE;
                o01.y = f01.y + acc[1][2*h]   * VUNSCALE;
                o23.x = f23.x + acc[2][2*h]   * VUNSCALE;
                o23.y = f23.y + acc[0][2*h+1] * VUNSCALE;
                o45.x = f45.x + acc[1][2*h+1] * VUNSCALE;
                o45.y = f45.y + acc[2][2*h+1] * VUNSCALE;
                *(float2*)(op)     = o01;
                *(float2*)(op + 2) = o23;
                *(float2*)(op + 4) = o45;
            }
        }
    } else {
        #pragma unroll
        for (int p = 0; p < 4; p++) {
            const int nt = (wid - 8)*4 + p;
            const uint4* bp = g_W5sf + nt*256 + lane;
            float acc[2][4] = {{0,0,0,0},{0,0,0,0}};
            #pragma unroll
            for (int ktb = 0; ktb < 2; ktb++) {
                uint4 w[4];
                #pragma unroll
                for (int j = 0; j < 4; j++) w[j] = bp[(ktb*4 + j)*32];
                #pragma unroll
                for (int m = 0; m < 2; m++) {
                    const unsigned ab = smem_b + OFF_OUTS*4
                        + (unsigned)(m*16 + (lane & 15)) * (ROWH*2) + (unsigned)(lane >> 4) * 16;
                    #pragma unroll
                    for (int j = 0; j < 4; j++) {
                        uint32_t A0, A1, A2, A3;
                        LDMX4(A0, A1, A2, A3, ab + (ktb*4 + j)*32);
                        MMA16816(acc[m][0], acc[m][1], acc[m][2], acc[m][3], A0, A1, A2, A3, w[j].x, w[j].y);
                        MMA16816(acc[m][0], acc[m][1], acc[m][2], acc[m][3], A0, A1, A2, A3, w[j].z, w[j].w);
                    }
                }
            }
            const int v0 = nt*8 + t*2;
            #pragma unroll
            for (int m = 0; m < 2; m++) {
                const int eb = m*16;
                size_t o;
                o = (size_t)(e0 + eb + g)     * 256 + v0;     out[o] = fij_in[o] + acc[m][0];
                o = (size_t)(e0 + eb + g)     * 256 + v0 + 1; out[o] = fij_in[o] + acc[m][1];
                o = (size_t)(e0 + eb + g + 8) * 256 + v0;     out[o] = fij_in[o] + acc[m][2];
                o = (size_t)(e0 + eb + g + 8) * 256 + v0 + 1; out[o] = fij_in[o] + acc[m][3];
            }
        }
    }
}

// ---------------------------------------------------------------------------
extern "C" void kernel_launch(void* const* d_in, const int* in_sizes, int n_in,
                              void* d_out, int out_size)
{
    const float* x         = (const float*)d_in[0];
    const float* edge_attr = (const float*)d_in[1];
    const float* fij_in    = (const float*)d_in[2];
    const float* W_pre_s   = (const float*)d_in[3];
    const float* b_pre_s   = (const float*)d_in[4];
    const float* W_pre_v   = (const float*)d_in[5];
    const float* gw_pre    = (const float*)d_in[6];
    const float* gb_pre    = (const float*)d_in[7];
    const float* Ws1       = (const float*)d_in[8];
    const float* bs1       = (const float*)d_in[9];
    const float* Ws2       = (const float*)d_in[10];
    const float* bs2       = (const float*)d_in[11];
    const float* Wr1       = (const float*)d_in[12];
    const float* br1       = (const float*)d_in[13];
    const float* Wr2       = (const float*)d_in[14];
    const float* br2       = (const float*)d_in[15];
    const float* gw_post   = (const float*)d_in[16];
    const float* gb_post   = (const float*)d_in[17];
    const float* W_post_s  = (const float*)d_in[18];
    const float* W_post_v  = (const float*)d_in[19];
    const int*   ei        = (const int*)d_in[20];

    const int N = in_sizes[0] / 256;
    const int E = in_sizes[2] / 256;

    node_kernel<<<(N + 3) / 4, 256>>>(x, W_pre_s, b_pre_s, W_pre_v, gw_pre, gb_pre, N);

    const int total_w = CNT_W1S + CNT_W1R + 2*CNT_W2 + CNT_W5V + CNT_W5S;
    wconv_kernel<<<(total_w + 255) / 256, 256>>>(Ws1, Wr1, Ws2, Wr2, W_post_v, W_post_s);

    const size_t shm = (size_t)SMEM_FLOATS * 4;   // 68352 B
    cudaFuncSetAttribute(edge_kernel, cudaFuncAttributeMaxDynamicSharedMemorySize, (int)shm);

    edge_kernel<<<E / TE, BT, shm>>>(
        x, edge_attr, fij_in,
        bs1, bs2, br1, br2,
        gw_post, gb_post,
        ei, (float*)d_out, E);
}